// round 6
// baseline (speedup 1.0000x reference)
#include <cuda_runtime.h>
#include <cuda_fp16.h>
#include <cstdint>

// Problem constants
#define NB   16          // batch
#define TT   255         // teacher length (T-1)
#define UU   1024        // GRU units
#define VV   32000       // vocab
#define EE   256         // emb dim
#define LATD 512         // latent dim
#define MROWS (NB*TT)    // 4080
#define MPAD 4096
#define N3   (3*UU)      // 3072

#define GRU_BLOCKS 128
#define HSTR 20                              // padded batch stride in h_sh (floats)
#define GRU_SMEM (1024*HSTR*4 + NB*32*4)     // 81920 + 2048

// ---------------- device scratch (no allocs allowed) ----------------
__device__ float g_hT[2][1024*NB];                    // transposed hidden state [unit][batch], ping-pong
__device__ float g_xproj[(size_t)MROWS*N3];           // x @ gru_kernel + b0
__device__ __align__(128) __half g_Ah[(size_t)MPAD*UU];   // fp16 GRU outputs (rows>=4080 stay 0)
__device__ __align__(128) __half g_Wh[(size_t)VV*UU];     // fp16 out_W^T  [V][U]
__device__ __align__(128) __half g_embh[(size_t)VV*EE];   // fp16 emb
__device__ __align__(128) __half g_gkT[(size_t)N3*EE];    // fp16 gru_kernel^T [3072][256]
__device__ int   g_arow[MROWS];
__device__ unsigned char g_flag[MROWS];
__device__ unsigned g_done[GRU_BLOCKS];               // flag barrier slots (monotonic)

// ---------------- PTX helpers ----------------
__device__ __forceinline__ uint32_t smem_to_u32(const void* p){
    uint32_t a;
    asm("{ .reg .u64 t; cvta.to.shared.u64 t, %1; cvt.u32.u64 %0, t; }" : "=r"(a) : "l"(p));
    return a;
}
__device__ __forceinline__ void cp16(uint32_t s, const void* g){
    asm volatile("cp.async.cg.shared.global [%0], [%1], 16;" :: "r"(s), "l"(g));
}
__device__ __forceinline__ void cp_commit(){ asm volatile("cp.async.commit_group;" ::: "memory"); }
template<int N> __device__ __forceinline__ void cp_wait(){
    asm volatile("cp.async.wait_group %0;" :: "n"(N) : "memory");
}
__device__ __forceinline__ void ldsm4(uint32_t* r, uint32_t addr){
    asm volatile("ldmatrix.sync.aligned.m8n8.x4.shared.b16 {%0,%1,%2,%3}, [%4];"
        : "=r"(r[0]),"=r"(r[1]),"=r"(r[2]),"=r"(r[3]) : "r"(addr));
}
__device__ __forceinline__ void mma16816(float* c, const uint32_t* a, const uint32_t* b){
    asm volatile("mma.sync.aligned.m16n8k16.row.col.f32.f16.f16.f32 "
        "{%0,%1,%2,%3}, {%4,%5,%6,%7}, {%8,%9}, {%0,%1,%2,%3};"
        : "+f"(c[0]), "+f"(c[1]), "+f"(c[2]), "+f"(c[3])
        : "r"(a[0]), "r"(a[1]), "r"(a[2]), "r"(a[3]), "r"(b[0]), "r"(b[1]));
}

// ---------------- f32x2 helpers ----------------
__device__ __forceinline__ unsigned long long packdup(float a){
    unsigned long long r;
    asm("mov.b64 %0, {%1, %1};" : "=l"(r) : "f"(a));
    return r;
}
__device__ __forceinline__ void ffma2(float2& c, unsigned long long a2, float2 b){
    unsigned long long b2, c2;
    b2 = *reinterpret_cast<unsigned long long*>(&b);
    c2 = *reinterpret_cast<unsigned long long*>(&c);
    asm("fma.rn.f32x2 %0, %1, %2, %3;" : "=l"(c2) : "l"(a2), "l"(b2), "l"(c2));
    c = *reinterpret_cast<float2*>(&c2);
}

// flag-array grid barrier: per-CTA release store to own slot, acquire poll on all.
// target is monotonic across graph replays via base read at kernel start.
__device__ __forceinline__ void gru_barrier(int bl, unsigned target){
    __syncthreads();
    if (threadIdx.x == 0){
        asm volatile("st.release.gpu.u32 [%0], %1;" :: "l"(g_done + bl), "r"(target) : "memory");
    }
    if (threadIdx.x < GRU_BLOCKS){
        const unsigned* p = g_done + threadIdx.x;
        unsigned v;
        do {
            asm volatile("ld.acquire.gpu.u32 %0, [%1];" : "=r"(v) : "l"(p) : "memory");
        } while ((int)(v - target) < 0);
    }
    __syncthreads();
}

// ---------------- kernel 1: h0 = latent @ dense_W + dense_b (writes transposed) ----------------
__global__ void h0_kernel(const float* __restrict__ lat,
                          const float* __restrict__ W,
                          const float* __restrict__ bb){
    int o = blockIdx.x*blockDim.x + threadIdx.x;
    if (o >= NB*UU) return;
    int b = o >> 10, u = o & (UU-1);
    float acc = bb[u];
    const float* lrow = lat + b*LATD;
    #pragma unroll 8
    for (int k=0;k<LATD;k++) acc = fmaf(lrow[k], W[(size_t)k*UU + u], acc);
    g_hT[0][u*NB + b] = acc;
}

// ---------------- kernel 2: token gather index + prefix-OR flag ----------------
__global__ void prep_kernel(const int* __restrict__ tok){
    int tid = threadIdx.x;
    if (tid < NB){
        unsigned char f = 0;
        for (int t=0;t<TT;t++){
            f |= (tok[tid*256 + t] != 0) ? 1 : 0;
            g_flag[tid*TT + t] = f;
        }
    }
    for (int m=tid; m<MROWS; m+=blockDim.x){
        int v = tok[(m/TT)*256 + (m%TT)];
        if (v < 0) v = 0;
        if (v >= VV) v = VV-1;
        g_arow[m] = v;
    }
}

// ---------------- kernel 2b: transpose out_W [U][V] -> fp16 g_Wh [V][U] ----------------
__global__ void convW_kernel(const float* __restrict__ W){
    __shared__ float tile[32][33];
    int n0 = blockIdx.x*32, k0 = blockIdx.y*32;
    int tx = threadIdx.x, ty = threadIdx.y;   // 32 x 8
    #pragma unroll
    for (int i=ty; i<32; i+=8)
        tile[i][tx] = W[(size_t)(k0+i)*VV + n0+tx];
    __syncthreads();
    #pragma unroll
    for (int i=ty; i<32; i+=8){
        int n = n0 + i, k = k0 + tx;
        g_Wh[(size_t)n*UU + k] = __float2half(tile[tx][i]);
    }
}

// ---------------- kernel 2c: emb fp32 -> fp16 ----------------
__global__ void convEmb_kernel(const float* __restrict__ E){
    int i = blockIdx.x*blockDim.x + threadIdx.x;       // one float4 -> 4 halves
    if (i >= VV*EE/4) return;
    float4 v = ((const float4*)E)[i];
    __half2* dst = (__half2*)g_embh;
    dst[i*2+0] = __floats2half2_rn(v.x, v.y);
    dst[i*2+1] = __floats2half2_rn(v.z, v.w);
}

// ---------------- kernel 2d: transpose gru_kernel [E][N3] -> fp16 g_gkT [N3][E] ----------------
__global__ void convGkT_kernel(const float* __restrict__ G){
    __shared__ float tile[32][33];
    int n0 = blockIdx.x*32, k0 = blockIdx.y*32;
    int tx = threadIdx.x, ty = threadIdx.y;   // 32 x 8
    #pragma unroll
    for (int i=ty; i<32; i+=8)
        tile[i][tx] = G[(size_t)(k0+i)*N3 + n0+tx];
    __syncthreads();
    #pragma unroll
    for (int i=ty; i<32; i+=8){
        int n = n0 + i, k = k0 + tx;
        g_gkT[(size_t)n*EE + k] = __float2half(tile[tx][i]);
    }
}

// ---------------- shared HMMA tile constants ----------------
#define HG_STRIDE 72
#define HG_BUFB   (128*HG_STRIDE*2)       // 18432 bytes per buffer
#define HG_SMEM   (6*HG_BUFB)             // A0..A2, B0..B2 = 110592

// ---------------- kernel 3: fp16 HMMA xproj GEMM (gathered A) ----------------
// g_xproj[m][n] = emb[tok[m]] @ gru_kernel[:,n] + gru_bias[0][n];  M=4080(pad 4096), N=3072, K=256
__global__ __launch_bounds__(256,2) void xp_hmma(const float* __restrict__ bias0,
                                                 float* __restrict__ C){
    extern __shared__ __align__(128) char sm[];
    const uint32_t sb = smem_to_u32(sm);
    const int tid = threadIdx.x, lane = tid & 31, wid = tid >> 5;
    const int m0 = blockIdx.x * 128;
    const int n0 = blockIdx.y * 128;
    const int wm = wid >> 2, wn = wid & 3;     // 2 x 4 warps

    // per-thread gathered A row pointers (4 (row,seg) slots)
    const __half* aptr[4];
    int asegs[4];
    #pragma unroll
    for (int i=0;i<4;i++){
        int idx = tid + i*256;
        int row = idx >> 3; asegs[i] = idx & 7;
        int grow = m0 + row;
        int tokv = (grow < MROWS) ? g_arow[grow] : 0;
        aptr[i] = g_embh + (size_t)tokv*EE;
    }
    auto loadA = [&](int kc, int st){
        uint32_t base = sb + st*HG_BUFB;
        #pragma unroll
        for (int i=0;i<4;i++){
            int idx = tid + i*256;
            int row = idx >> 3;
            cp16(base + (uint32_t)(row*HG_STRIDE + asegs[i]*8)*2,
                 aptr[i] + kc*64 + asegs[i]*8);
        }
    };
    auto loadB = [&](int kc, int st){
        const __half* gB = g_gkT + (size_t)n0*EE + kc*64;
        uint32_t base = sb + (3+st)*HG_BUFB;
        #pragma unroll
        for (int i=0;i<4;i++){
            int idx = tid + i*256;
            int row = idx >> 3, seg = idx & 7;
            cp16(base + (uint32_t)(row*HG_STRIDE + seg*8)*2,
                 gB + (size_t)row*EE + seg*8);
        }
    };

    float acc[4][4][4];
    #pragma unroll
    for (int i=0;i<4;i++)
        #pragma unroll
        for (int j=0;j<4;j++)
            #pragma unroll
            for (int p=0;p<4;p++) acc[i][j][p] = 0.f;

    const int lane15 = lane & 15, laneHi = lane >> 4;
    const uint32_t aOff = (uint32_t)((wm*64 + lane15)*HG_STRIDE + laneHi*8)*2;
    const int nr  = (lane & 7) + ((lane >> 4) << 3);
    const int kc8 = ((lane >> 3) & 1) * 8;
    const uint32_t bOff = (uint32_t)((wn*32 + nr)*HG_STRIDE + kc8)*2;

    loadA(0,0); loadB(0,0); cp_commit();
    loadA(1,1); loadB(1,1); cp_commit();

    for (int kc=0; kc<4; kc++){
        int st = kc % 3;
        if (kc < 3) cp_wait<1>(); else cp_wait<0>();
        __syncthreads();
        if (kc + 2 < 4){
            loadA(kc+2, (kc+2)%3);
            loadB(kc+2, (kc+2)%3);
            cp_commit();
        }
        const uint32_t aBase = sb + st*HG_BUFB + aOff;
        const uint32_t bBase = sb + (3+st)*HG_BUFB + bOff;
        #pragma unroll
        for (int k16=0; k16<4; k16++){
            uint32_t af[4][4], bf[2][4];
            #pragma unroll
            for (int mi=0; mi<4; mi++)
                ldsm4(af[mi], aBase + (uint32_t)(mi*16*HG_STRIDE + k16*16)*2);
            #pragma unroll
            for (int ni=0; ni<2; ni++)
                ldsm4(bf[ni], bBase + (uint32_t)(ni*16*HG_STRIDE + k16*16)*2);
            #pragma unroll
            for (int mi=0; mi<4; mi++)
                #pragma unroll
                for (int nt=0; nt<4; nt++)
                    mma16816(acc[mi][nt], af[mi], &bf[nt>>1][(nt&1)*2]);
        }
        if (kc < 3) __syncthreads();
    }

    const int g = lane >> 2, q = lane & 3;
    float2 bias2[4];
    #pragma unroll
    for (int nt=0; nt<4; nt++){
        int col = n0 + wn*32 + nt*8 + q*2;
        bias2[nt] = *(const float2*)(bias0 + col);
    }
    #pragma unroll
    for (int mi=0; mi<4; mi++){
        int r0 = m0 + wm*64 + mi*16 + g;
        int r1 = r0 + 8;
        #pragma unroll
        for (int nt=0; nt<4; nt++){
            int col = n0 + wn*32 + nt*8 + q*2;
            if (r0 < MROWS){
                float2 v = make_float2(acc[mi][nt][0] + bias2[nt].x,
                                       acc[mi][nt][1] + bias2[nt].y);
                *(float2*)(C + (size_t)r0*N3 + col) = v;
            }
            if (r1 < MROWS){
                float2 v = make_float2(acc[mi][nt][2] + bias2[nt].x,
                                       acc[mi][nt][3] + bias2[nt].y);
                *(float2*)(C + (size_t)r1*N3 + col) = v;
            }
        }
    }
}

// ---------------- kernel 4: persistent GRU (flag barrier) ----------------
__global__ __launch_bounds__(256,1) void gru_kernel(
    const float* __restrict__ rk,
    const float* __restrict__ gbias,
    const int* __restrict__ tok)
{
    extern __shared__ float sh[];
    float* hT    = sh;                 // [1024][HSTR]
    float* rp_sh = sh + 1024*HSTR;     // [b][32] (24 used)
    const int tid = threadIdx.x, lane = tid & 31, wrp = tid >> 5, bl = blockIdx.x;

    // monotonic barrier base (own slot; written only by this CTA)
    unsigned bar_base = *(volatile unsigned*)(g_done + bl);

    // persistent recurrent weights: warp wrp owns local cols {3w,3w+1,3w+2} of 24
    float w0[32], w1[32], w2[32];
    {
        int c0 = wrp*3, c1 = c0+1, c2 = c0+2;
        int g0 = (c0>>3)*UU + bl*8 + (c0&7);
        int g1 = (c1>>3)*UU + bl*8 + (c1&7);
        int g2 = (c2>>3)*UU + bl*8 + (c2&7);
        #pragma unroll
        for (int i=0;i<32;i++){
            int k = i*32 + lane;
            w0[i] = rk[(size_t)k*N3 + g0];
            w1[i] = rk[(size_t)k*N3 + g1];
            w2[i] = rk[(size_t)k*N3 + g2];
        }
    }

    int eb=0, eu=0, ecol=0;
    float bz=0.f, br=0.f, bh=0.f;
    if (tid < 128){
        eb = tid >> 3; eu = tid & 7; ecol = bl*8 + eu;
        bz = gbias[N3 + ecol];
        br = gbias[N3 + UU + ecol];
        bh = gbias[N3 + 2*UU + ecol];
    }

    for (int t=0; t<TT; t++){
        const int rbuf = t & 1, wbuf = rbuf ^ 1;

        // prefetch epilogue inputs (hide L2 latency)
        float xz=0.f, xr=0.f, xh=0.f; bool msk=false, fl=false;
        if (tid < 128){
            int r = eb*TT + t;
            const float* xp = g_xproj + (size_t)r*N3;
            xz = xp[ecol]; xr = xp[UU+ecol]; xh = xp[2*UU+ecol];
            msk = (tok[eb*256 + t] != 0);
            fl  = (g_flag[r] != 0);
        }

        // broadcast transposed h into padded SMEM
        {
            const float4* src = (const float4*)&g_hT[rbuf][0];
            #pragma unroll 4
            for (int i=tid; i<1024*NB/4; i+=256){
                float4 v = src[i];
                int u = i >> 2, g = i & 3;
                *(float4*)&hT[u*HSTR + g*4] = v;
            }
        }
        __syncthreads();

        // rp = h @ rkernel: packed over batch pairs
        float2 acc0[8], acc1[8], acc2[8];
        #pragma unroll
        for (int bp=0;bp<8;bp++){ acc0[bp]=make_float2(0.f,0.f); acc1[bp]=make_float2(0.f,0.f); acc2[bp]=make_float2(0.f,0.f); }

        #pragma unroll
        for (int i=0;i<32;i++){
            int k = i*32 + lane;
            const float4* hk = (const float4*)&hT[k*HSTR];
            float4 ha = hk[0], hb4 = hk[1], hc = hk[2], hd = hk[3];
            float2 hp[8] = {{ha.x,ha.y},{ha.z,ha.w},{hb4.x,hb4.y},{hb4.z,hb4.w},
                            {hc.x,hc.y},{hc.z,hc.w},{hd.x,hd.y},{hd.z,hd.w}};
            unsigned long long p0 = packdup(w0[i]), p1 = packdup(w1[i]), p2 = packdup(w2[i]);
            #pragma unroll
            for (int bp=0;bp<8;bp++){
                ffma2(acc0[bp], p0, hp[bp]);
                ffma2(acc1[bp], p1, hp[bp]);
                ffma2(acc2[bp], p2, hp[bp]);
            }
        }

        // lane reduction + store (24 packed values)
        {
            int c0 = wrp*3;
            #pragma unroll
            for (int bp=0;bp<8;bp++){
                float2 v0 = acc0[bp], v1 = acc1[bp], v2 = acc2[bp];
                #pragma unroll
                for (int o=16;o>0;o>>=1){
                    v0.x += __shfl_xor_sync(0xffffffffu, v0.x, o);
                    v0.y += __shfl_xor_sync(0xffffffffu, v0.y, o);
                    v1.x += __shfl_xor_sync(0xffffffffu, v1.x, o);
                    v1.y += __shfl_xor_sync(0xffffffffu, v1.y, o);
                    v2.x += __shfl_xor_sync(0xffffffffu, v2.x, o);
                    v2.y += __shfl_xor_sync(0xffffffffu, v2.y, o);
                }
                if (lane == 0){
                    int b0 = bp*2, b1 = bp*2+1;
                    rp_sh[b0*32 + c0 + 0] = v0.x;  rp_sh[b1*32 + c0 + 0] = v0.y;
                    rp_sh[b0*32 + c0 + 1] = v1.x;  rp_sh[b1*32 + c0 + 1] = v1.y;
                    rp_sh[b0*32 + c0 + 2] = v2.x;  rp_sh[b1*32 + c0 + 2] = v2.y;
                }
            }
        }
        __syncthreads();

        // gate math + state update (one thread per (b, unit))
        if (tid < 128){
            float rz = rp_sh[eb*32 + eu]      + bz;
            float rr = rp_sh[eb*32 + 8 + eu]  + br;
            float rh = rp_sh[eb*32 + 16 + eu] + bh;
            float z  = 1.f/(1.f + __expf(-(xz+rz)));
            float rg = 1.f/(1.f + __expf(-(xr+rr)));
            float hh = tanhf(xh + rg*rh);
            float hold = hT[ecol*HSTR + eb];
            float hn = z*hold + (1.f - z)*hh;
            float hnew = msk ? hn : hold;
            g_hT[wbuf][ecol*NB + eb] = hnew;
            float yv = fl ? hnew : 0.f;
            g_Ah[(size_t)(eb*TT + t)*UU + ecol] = __float2half(yv);
        }
        gru_barrier(bl, bar_base + t + 1);
    }
}

// ---------------- kernel 5: fp16 HMMA output GEMM ----------------
__global__ __launch_bounds__(256,2) void out_hmma(const float* __restrict__ ob,
                                                  float* __restrict__ C){
    extern __shared__ __align__(128) char sm[];
    const uint32_t sb = smem_to_u32(sm);
    const int tid = threadIdx.x, lane = tid & 31, wid = tid >> 5;
    const int m0 = blockIdx.x * 128;
    const int n0 = blockIdx.y * 128;
    const int wm = wid >> 2, wn = wid & 3;     // 2 x 4 warps

    auto loadA = [&](int kc, int st){
        const __half* gA = g_Ah + (size_t)m0*UU + kc*64;
        uint32_t base = sb + st*HG_BUFB;
        #pragma unroll
        for (int i=0;i<4;i++){
            int idx = tid + i*256;             // 0..1023
            int row = idx >> 3, seg = idx & 7; // 128 rows x 8 segs of 8 halves
            cp16(base + (uint32_t)(row*HG_STRIDE + seg*8)*2,
                 gA + (size_t)row*UU + seg*8);
        }
    };
    auto loadB = [&](int kc, int st){
        const __half* gB = g_Wh + (size_t)n0*UU + kc*64;
        uint32_t base = sb + (3+st)*HG_BUFB;
        #pragma unroll
        for (int i=0;i<4;i++){
            int idx = tid + i*256;
            int row = idx >> 3, seg = idx & 7;
            cp16(base + (uint32_t)(row*HG_STRIDE + seg*8)*2,
                 gB + (size_t)row*UU + seg*8);
        }
    };

    float acc[4][4][4];
    #pragma unroll
    for (int i=0;i<4;i++)
        #pragma unroll
        for (int j=0;j<4;j++)
            #pragma unroll
            for (int p=0;p<4;p++) acc[i][j][p] = 0.f;

    const int lane15 = lane & 15, laneHi = lane >> 4;
    const uint32_t aOff = (uint32_t)((wm*64 + lane15)*HG_STRIDE + laneHi*8)*2;
    const int nr  = (lane & 7) + ((lane >> 4) << 3);
    const int kc8 = ((lane >> 3) & 1) * 8;
    const uint32_t bOff = (uint32_t)((wn*32 + nr)*HG_STRIDE + kc8)*2;

    loadA(0,0); loadB(0,0); cp_commit();
    loadA(1,1); loadB(1,1); cp_commit();

    for (int kc=0; kc<16; kc++){
        int st = kc % 3;
        if (kc < 15) cp_wait<1>(); else cp_wait<0>();
        __syncthreads();
        if (kc + 2 < 16){
            loadA(kc+2, (kc+2)%3);
            loadB(kc+2, (kc+2)%3);
            cp_commit();
        }

        const uint32_t aBase = sb + st*HG_BUFB + aOff;
        const uint32_t bBase = sb + (3+st)*HG_BUFB + bOff;
        #pragma unroll
        for (int k16=0; k16<4; k16++){
            uint32_t af[4][4], bf[2][4];
            #pragma unroll
            for (int mi=0; mi<4; mi++)
                ldsm4(af[mi], aBase + (uint32_t)(mi*16*HG_STRIDE + k16*16)*2);
            #pragma unroll
            for (int ni=0; ni<2; ni++)
                ldsm4(bf[ni], bBase + (uint32_t)(ni*16*HG_STRIDE + k16*16)*2);
            #pragma unroll
            for (int mi=0; mi<4; mi++)
                #pragma unroll
                for (int nt=0; nt<4; nt++)
                    mma16816(acc[mi][nt], af[mi], &bf[nt>>1][(nt&1)*2]);
        }
    }

    // epilogue: bias + store (guard rows >= MROWS)
    const int g = lane >> 2, q = lane & 3;
    float2 bias2[4];
    #pragma unroll
    for (int nt=0; nt<4; nt++){
        int col = n0 + wn*32 + nt*8 + q*2;
        bias2[nt] = *(const float2*)(ob + col);
    }
    #pragma unroll
    for (int mi=0; mi<4; mi++){
        int r0 = m0 + wm*64 + mi*16 + g;
        int r1 = r0 + 8;
        #pragma unroll
        for (int nt=0; nt<4; nt++){
            int col = n0 + wn*32 + nt*8 + q*2;
            if (r0 < MROWS){
                float2 v = make_float2(acc[mi][nt][0] + bias2[nt].x,
                                       acc[mi][nt][1] + bias2[nt].y);
                *(float2*)(C + (size_t)r0*VV + col) = v;
            }
            if (r1 < MROWS){
                float2 v = make_float2(acc[mi][nt][2] + bias2[nt].x,
                                       acc[mi][nt][3] + bias2[nt].y);
                *(float2*)(C + (size_t)r1*VV + col) = v;
            }
        }
    }
}

// ---------------- launch ----------------
extern "C" void kernel_launch(void* const* d_in, const int* in_sizes, int n_in,
                              void* d_out, int out_size)
{
    const float* latent = (const float*)d_in[0];
    const int*   tok    = (const int*)d_in[1];
    const float* emb    = (const float*)d_in[2];
    const float* dW     = (const float*)d_in[3];
    const float* db     = (const float*)d_in[4];
    const float* gk     = (const float*)d_in[5];
    const float* grk    = (const float*)d_in[6];
    const float* gb     = (const float*)d_in[7];
    const float* oW     = (const float*)d_in[8];
    const float* ob     = (const float*)d_in[9];
    float* out = (float*)d_out;

    (void)in_sizes; (void)n_in; (void)out_size;

    cudaFuncSetAttribute(gru_kernel, cudaFuncAttributeMaxDynamicSharedMemorySize, GRU_SMEM);
    cudaFuncSetAttribute(out_hmma, cudaFuncAttributeMaxDynamicSharedMemorySize, HG_SMEM);
    cudaFuncSetAttribute(xp_hmma, cudaFuncAttributeMaxDynamicSharedMemorySize, HG_SMEM);

    void *xproj_p = nullptr;
    cudaGetSymbolAddress(&xproj_p, g_xproj);

    h0_kernel<<<(NB*UU + 255)/256, 256>>>(latent, dW, db);
    prep_kernel<<<1, 256>>>(tok);
    convEmb_kernel<<<(VV*EE/4 + 255)/256, 256>>>(emb);
    convGkT_kernel<<<dim3(N3/32, EE/32), dim3(32,8)>>>(gk);
    convW_kernel<<<dim3(VV/32, UU/32), dim3(32,8)>>>(oW);

    // xproj = emb[tok] @ gru_kernel + gru_bias[0]   (HMMA)
    xp_hmma<<<dim3(MPAD/128, N3/128), 256, HG_SMEM>>>(gb, (float*)xproj_p);

    gru_kernel<<<GRU_BLOCKS, 256, GRU_SMEM>>>(grk, gb, tok);

    // m tiles fastest (blockIdx.x) so co-resident CTAs share the same B panel in L2
    out_hmma<<<dim3(MPAD/128, VV/128), 256, HG_SMEM>>>(ob, out);
}

// round 7
// speedup vs baseline: 1.4025x; 1.4025x over previous
#include <cuda_runtime.h>
#include <cuda_fp16.h>
#include <cstdint>

// Problem constants
#define NB   16          // batch
#define TT   255         // teacher length (T-1)
#define UU   1024        // GRU units
#define VV   32000       // vocab
#define EE   256         // emb dim
#define LATD 512         // latent dim
#define MROWS (NB*TT)    // 4080
#define MPAD 4096
#define N3   (3*UU)      // 3072

#define GRU_BLOCKS 128
#define HSTR 20                              // padded batch stride in h_sh (floats)
#define GRU_SMEM (1024*HSTR*4 + NB*32*4)     // 81920 + 2048

// ---------------- device scratch (no allocs allowed) ----------------
__device__ float g_hT[2][1024*NB];                    // transposed hidden state [unit][batch], ping-pong
__device__ float g_xproj[(size_t)MROWS*N3];           // x @ gru_kernel + b0
__device__ __align__(128) __half g_Ah[(size_t)MPAD*UU];   // fp16 GRU outputs (rows>=4080 stay 0)
__device__ __align__(128) __half g_Wh[(size_t)VV*UU];     // fp16 out_W^T  [V][U]
__device__ __align__(128) __half g_embh[(size_t)VV*EE];   // fp16 emb
__device__ __align__(128) __half g_gkT[(size_t)N3*EE];    // fp16 gru_kernel^T [3072][256]
__device__ int   g_arow[MROWS];
__device__ unsigned char g_flag[MROWS];
__device__ unsigned int g_bar_cnt = 0;
__device__ unsigned int g_bar_gen = 0;

// ---------------- PTX helpers ----------------
__device__ __forceinline__ uint32_t smem_to_u32(const void* p){
    uint32_t a;
    asm("{ .reg .u64 t; cvta.to.shared.u64 t, %1; cvt.u32.u64 %0, t; }" : "=r"(a) : "l"(p));
    return a;
}
__device__ __forceinline__ void cp16(uint32_t s, const void* g){
    asm volatile("cp.async.cg.shared.global [%0], [%1], 16;" :: "r"(s), "l"(g));
}
__device__ __forceinline__ void cp_commit(){ asm volatile("cp.async.commit_group;" ::: "memory"); }
template<int N> __device__ __forceinline__ void cp_wait(){
    asm volatile("cp.async.wait_group %0;" :: "n"(N) : "memory");
}
__device__ __forceinline__ void ldsm4(uint32_t* r, uint32_t addr){
    asm volatile("ldmatrix.sync.aligned.m8n8.x4.shared.b16 {%0,%1,%2,%3}, [%4];"
        : "=r"(r[0]),"=r"(r[1]),"=r"(r[2]),"=r"(r[3]) : "r"(addr));
}
__device__ __forceinline__ void mma16816(float* c, const uint32_t* a, const uint32_t* b){
    asm volatile("mma.sync.aligned.m16n8k16.row.col.f32.f16.f16.f32 "
        "{%0,%1,%2,%3}, {%4,%5,%6,%7}, {%8,%9}, {%0,%1,%2,%3};"
        : "+f"(c[0]), "+f"(c[1]), "+f"(c[2]), "+f"(c[3])
        : "r"(a[0]), "r"(a[1]), "r"(a[2]), "r"(a[3]), "r"(b[0]), "r"(b[1]));
}

// ---------------- f32x2 helpers ----------------
__device__ __forceinline__ unsigned long long packdup(float a){
    unsigned long long r;
    asm("mov.b64 %0, {%1, %1};" : "=l"(r) : "f"(a));
    return r;
}
__device__ __forceinline__ void ffma2(float2& c, unsigned long long a2, float2 b){
    unsigned long long b2, c2;
    b2 = *reinterpret_cast<unsigned long long*>(&b);
    c2 = *reinterpret_cast<unsigned long long*>(&c);
    asm("fma.rn.f32x2 %0, %1, %2, %3;" : "=l"(c2) : "l"(a2), "l"(b2), "l"(c2));
    c = *reinterpret_cast<float2*>(&c2);
}

// R5-proven grid barrier: acq_rel atomics on (cnt, gen), thread-0 spin
__device__ __forceinline__ void grid_barrier(){
    __syncthreads();
    if (threadIdx.x == 0){
        unsigned gen, old;
        asm volatile("ld.acquire.gpu.u32 %0, [%1];" : "=r"(gen) : "l"(&g_bar_gen));
        asm volatile("atom.acq_rel.gpu.add.u32 %0, [%1], 1;" : "=r"(old) : "l"(&g_bar_cnt));
        if (old == gridDim.x - 1){
            *(volatile unsigned*)&g_bar_cnt = 0;
            asm volatile("red.release.gpu.add.u32 [%0], 1;" :: "l"(&g_bar_gen));
        } else {
            unsigned g2;
            do {
                asm volatile("ld.acquire.gpu.u32 %0, [%1];" : "=r"(g2) : "l"(&g_bar_gen));
            } while (g2 == gen);
        }
    }
    __syncthreads();
}

// ---------------- kernel 1: h0 = latent @ dense_W + dense_b (writes transposed) ----------------
__global__ void h0_kernel(const float* __restrict__ lat,
                          const float* __restrict__ W,
                          const float* __restrict__ bb){
    int o = blockIdx.x*blockDim.x + threadIdx.x;
    if (o >= NB*UU) return;
    int b = o >> 10, u = o & (UU-1);
    float acc = bb[u];
    const float* lrow = lat + b*LATD;
    #pragma unroll 8
    for (int k=0;k<LATD;k++) acc = fmaf(lrow[k], W[(size_t)k*UU + u], acc);
    g_hT[0][u*NB + b] = acc;
}

// ---------------- kernel 2: token gather index + prefix-OR flag ----------------
__global__ void prep_kernel(const int* __restrict__ tok){
    int tid = threadIdx.x;
    if (tid < NB){
        unsigned char f = 0;
        for (int t=0;t<TT;t++){
            f |= (tok[tid*256 + t] != 0) ? 1 : 0;
            g_flag[tid*TT + t] = f;
        }
    }
    for (int m=tid; m<MROWS; m+=blockDim.x){
        int v = tok[(m/TT)*256 + (m%TT)];
        if (v < 0) v = 0;
        if (v >= VV) v = VV-1;
        g_arow[m] = v;
    }
}

// ---------------- kernel 2b: transpose out_W [U][V] -> fp16 g_Wh [V][U] ----------------
__global__ void convW_kernel(const float* __restrict__ W){
    __shared__ float tile[32][33];
    int n0 = blockIdx.x*32, k0 = blockIdx.y*32;
    int tx = threadIdx.x, ty = threadIdx.y;   // 32 x 8
    #pragma unroll
    for (int i=ty; i<32; i+=8)
        tile[i][tx] = W[(size_t)(k0+i)*VV + n0+tx];
    __syncthreads();
    #pragma unroll
    for (int i=ty; i<32; i+=8){
        int n = n0 + i, k = k0 + tx;
        g_Wh[(size_t)n*UU + k] = __float2half(tile[tx][i]);
    }
}

// ---------------- kernel 2c: emb fp32 -> fp16 ----------------
__global__ void convEmb_kernel(const float* __restrict__ E){
    int i = blockIdx.x*blockDim.x + threadIdx.x;       // one float4 -> 4 halves
    if (i >= VV*EE/4) return;
    float4 v = ((const float4*)E)[i];
    __half2* dst = (__half2*)g_embh;
    dst[i*2+0] = __floats2half2_rn(v.x, v.y);
    dst[i*2+1] = __floats2half2_rn(v.z, v.w);
}

// ---------------- kernel 2d: transpose gru_kernel [E][N3] -> fp16 g_gkT [N3][E] ----------------
__global__ void convGkT_kernel(const float* __restrict__ G){
    __shared__ float tile[32][33];
    int n0 = blockIdx.x*32, k0 = blockIdx.y*32;
    int tx = threadIdx.x, ty = threadIdx.y;   // 32 x 8
    #pragma unroll
    for (int i=ty; i<32; i+=8)
        tile[i][tx] = G[(size_t)(k0+i)*N3 + n0+tx];
    __syncthreads();
    #pragma unroll
    for (int i=ty; i<32; i+=8){
        int n = n0 + i, k = k0 + tx;
        g_gkT[(size_t)n*EE + k] = __float2half(tile[tx][i]);
    }
}

// ---------------- shared HMMA tile constants ----------------
#define HG_STRIDE 72
#define HG_BUFB   (128*HG_STRIDE*2)       // 18432 bytes per buffer
#define HG_SMEM   (6*HG_BUFB)             // A0..A2, B0..B2 = 110592

// ---------------- kernel 3: fp16 HMMA xproj GEMM (gathered A) ----------------
// g_xproj[m][n] = emb[tok[m]] @ gru_kernel[:,n] + gru_bias[0][n];  M=4080(pad 4096), N=3072, K=256
__global__ __launch_bounds__(256,2) void xp_hmma(const float* __restrict__ bias0,
                                                 float* __restrict__ C){
    extern __shared__ __align__(128) char sm[];
    const uint32_t sb = smem_to_u32(sm);
    const int tid = threadIdx.x, lane = tid & 31, wid = tid >> 5;
    const int m0 = blockIdx.x * 128;
    const int n0 = blockIdx.y * 128;
    const int wm = wid >> 2, wn = wid & 3;     // 2 x 4 warps

    // per-thread gathered A row pointers (4 (row,seg) slots)
    const __half* aptr[4];
    int asegs[4];
    #pragma unroll
    for (int i=0;i<4;i++){
        int idx = tid + i*256;
        int row = idx >> 3; asegs[i] = idx & 7;
        int grow = m0 + row;
        int tokv = (grow < MROWS) ? g_arow[grow] : 0;
        aptr[i] = g_embh + (size_t)tokv*EE;
    }
    auto loadA = [&](int kc, int st){
        uint32_t base = sb + st*HG_BUFB;
        #pragma unroll
        for (int i=0;i<4;i++){
            int idx = tid + i*256;
            int row = idx >> 3;
            cp16(base + (uint32_t)(row*HG_STRIDE + asegs[i]*8)*2,
                 aptr[i] + kc*64 + asegs[i]*8);
        }
    };
    auto loadB = [&](int kc, int st){
        const __half* gB = g_gkT + (size_t)n0*EE + kc*64;
        uint32_t base = sb + (3+st)*HG_BUFB;
        #pragma unroll
        for (int i=0;i<4;i++){
            int idx = tid + i*256;
            int row = idx >> 3, seg = idx & 7;
            cp16(base + (uint32_t)(row*HG_STRIDE + seg*8)*2,
                 gB + (size_t)row*EE + seg*8);
        }
    };

    float acc[4][4][4];
    #pragma unroll
    for (int i=0;i<4;i++)
        #pragma unroll
        for (int j=0;j<4;j++)
            #pragma unroll
            for (int p=0;p<4;p++) acc[i][j][p] = 0.f;

    const int lane15 = lane & 15, laneHi = lane >> 4;
    const uint32_t aOff = (uint32_t)((wm*64 + lane15)*HG_STRIDE + laneHi*8)*2;
    const int nr  = (lane & 7) + ((lane >> 4) << 3);
    const int kc8 = ((lane >> 3) & 1) * 8;
    const uint32_t bOff = (uint32_t)((wn*32 + nr)*HG_STRIDE + kc8)*2;

    loadA(0,0); loadB(0,0); cp_commit();
    loadA(1,1); loadB(1,1); cp_commit();

    for (int kc=0; kc<4; kc++){
        int st = kc % 3;
        if (kc < 3) cp_wait<1>(); else cp_wait<0>();
        __syncthreads();
        if (kc + 2 < 4){
            loadA(kc+2, (kc+2)%3);
            loadB(kc+2, (kc+2)%3);
            cp_commit();
        }
        const uint32_t aBase = sb + st*HG_BUFB + aOff;
        const uint32_t bBase = sb + (3+st)*HG_BUFB + bOff;
        #pragma unroll
        for (int k16=0; k16<4; k16++){
            uint32_t af[4][4], bf[2][4];
            #pragma unroll
            for (int mi=0; mi<4; mi++)
                ldsm4(af[mi], aBase + (uint32_t)(mi*16*HG_STRIDE + k16*16)*2);
            #pragma unroll
            for (int ni=0; ni<2; ni++)
                ldsm4(bf[ni], bBase + (uint32_t)(ni*16*HG_STRIDE + k16*16)*2);
            #pragma unroll
            for (int mi=0; mi<4; mi++)
                #pragma unroll
                for (int nt=0; nt<4; nt++)
                    mma16816(acc[mi][nt], af[mi], &bf[nt>>1][(nt&1)*2]);
        }
        if (kc < 3) __syncthreads();
    }

    const int g = lane >> 2, q = lane & 3;
    float2 bias2[4];
    #pragma unroll
    for (int nt=0; nt<4; nt++){
        int col = n0 + wn*32 + nt*8 + q*2;
        bias2[nt] = *(const float2*)(bias0 + col);
    }
    #pragma unroll
    for (int mi=0; mi<4; mi++){
        int r0 = m0 + wm*64 + mi*16 + g;
        int r1 = r0 + 8;
        #pragma unroll
        for (int nt=0; nt<4; nt++){
            int col = n0 + wn*32 + nt*8 + q*2;
            if (r0 < MROWS){
                float2 v = make_float2(acc[mi][nt][0] + bias2[nt].x,
                                       acc[mi][nt][1] + bias2[nt].y);
                *(float2*)(C + (size_t)r0*N3 + col) = v;
            }
            if (r1 < MROWS){
                float2 v = make_float2(acc[mi][nt][2] + bias2[nt].x,
                                       acc[mi][nt][3] + bias2[nt].y);
                *(float2*)(C + (size_t)r1*N3 + col) = v;
            }
        }
    }
}

// ---------------- kernel 4: persistent GRU (R5 atomic barrier) ----------------
__global__ __launch_bounds__(256,1) void gru_kernel(
    const float* __restrict__ rk,
    const float* __restrict__ gbias,
    const int* __restrict__ tok)
{
    extern __shared__ float sh[];
    float* hT    = sh;                 // [1024][HSTR]
    float* rp_sh = sh + 1024*HSTR;     // [b][32] (24 used)
    const int tid = threadIdx.x, lane = tid & 31, wrp = tid >> 5, bl = blockIdx.x;

    // persistent recurrent weights: warp wrp owns local cols {3w,3w+1,3w+2} of 24
    float w0[32], w1[32], w2[32];
    {
        int c0 = wrp*3, c1 = c0+1, c2 = c0+2;
        int g0 = (c0>>3)*UU + bl*8 + (c0&7);
        int g1 = (c1>>3)*UU + bl*8 + (c1&7);
        int g2 = (c2>>3)*UU + bl*8 + (c2&7);
        #pragma unroll
        for (int i=0;i<32;i++){
            int k = i*32 + lane;
            w0[i] = rk[(size_t)k*N3 + g0];
            w1[i] = rk[(size_t)k*N3 + g1];
            w2[i] = rk[(size_t)k*N3 + g2];
        }
    }

    int eb=0, eu=0, ecol=0;
    float bz=0.f, br=0.f, bh=0.f;
    if (tid < 128){
        eb = tid >> 3; eu = tid & 7; ecol = bl*8 + eu;
        bz = gbias[N3 + ecol];
        br = gbias[N3 + UU + ecol];
        bh = gbias[N3 + 2*UU + ecol];
    }

    for (int t=0; t<TT; t++){
        const int rbuf = t & 1, wbuf = rbuf ^ 1;

        // prefetch epilogue inputs (hide L2 latency)
        float xz=0.f, xr=0.f, xh=0.f; bool msk=false, fl=false;
        if (tid < 128){
            int r = eb*TT + t;
            const float* xp = g_xproj + (size_t)r*N3;
            xz = xp[ecol]; xr = xp[UU+ecol]; xh = xp[2*UU+ecol];
            msk = (tok[eb*256 + t] != 0);
            fl  = (g_flag[r] != 0);
        }

        // broadcast transposed h into padded SMEM
        {
            const float4* src = (const float4*)&g_hT[rbuf][0];
            #pragma unroll 4
            for (int i=tid; i<1024*NB/4; i+=256){
                float4 v = src[i];
                int u = i >> 2, g = i & 3;
                *(float4*)&hT[u*HSTR + g*4] = v;
            }
        }
        __syncthreads();

        // rp = h @ rkernel: packed over batch pairs
        float2 acc0[8], acc1[8], acc2[8];
        #pragma unroll
        for (int bp=0;bp<8;bp++){ acc0[bp]=make_float2(0.f,0.f); acc1[bp]=make_float2(0.f,0.f); acc2[bp]=make_float2(0.f,0.f); }

        #pragma unroll
        for (int i=0;i<32;i++){
            int k = i*32 + lane;
            const float4* hk = (const float4*)&hT[k*HSTR];
            float4 ha = hk[0], hb4 = hk[1], hc = hk[2], hd = hk[3];
            float2 hp[8] = {{ha.x,ha.y},{ha.z,ha.w},{hb4.x,hb4.y},{hb4.z,hb4.w},
                            {hc.x,hc.y},{hc.z,hc.w},{hd.x,hd.y},{hd.z,hd.w}};
            unsigned long long p0 = packdup(w0[i]), p1 = packdup(w1[i]), p2 = packdup(w2[i]);
            #pragma unroll
            for (int bp=0;bp<8;bp++){
                ffma2(acc0[bp], p0, hp[bp]);
                ffma2(acc1[bp], p1, hp[bp]);
                ffma2(acc2[bp], p2, hp[bp]);
            }
        }

        // lane reduction + store (24 packed values)
        {
            int c0 = wrp*3;
            #pragma unroll
            for (int bp=0;bp<8;bp++){
                float2 v0 = acc0[bp], v1 = acc1[bp], v2 = acc2[bp];
                #pragma unroll
                for (int o=16;o>0;o>>=1){
                    v0.x += __shfl_xor_sync(0xffffffffu, v0.x, o);
                    v0.y += __shfl_xor_sync(0xffffffffu, v0.y, o);
                    v1.x += __shfl_xor_sync(0xffffffffu, v1.x, o);
                    v1.y += __shfl_xor_sync(0xffffffffu, v1.y, o);
                    v2.x += __shfl_xor_sync(0xffffffffu, v2.x, o);
                    v2.y += __shfl_xor_sync(0xffffffffu, v2.y, o);
                }
                if (lane == 0){
                    int b0 = bp*2, b1 = bp*2+1;
                    rp_sh[b0*32 + c0 + 0] = v0.x;  rp_sh[b1*32 + c0 + 0] = v0.y;
                    rp_sh[b0*32 + c0 + 1] = v1.x;  rp_sh[b1*32 + c0 + 1] = v1.y;
                    rp_sh[b0*32 + c0 + 2] = v2.x;  rp_sh[b1*32 + c0 + 2] = v2.y;
                }
            }
        }
        __syncthreads();

        // gate math + state update (one thread per (b, unit))
        if (tid < 128){
            float rz = rp_sh[eb*32 + eu]      + bz;
            float rr = rp_sh[eb*32 + 8 + eu]  + br;
            float rh = rp_sh[eb*32 + 16 + eu] + bh;
            float z  = 1.f/(1.f + __expf(-(xz+rz)));
            float rg = 1.f/(1.f + __expf(-(xr+rr)));
            float hh = tanhf(xh + rg*rh);
            float hold = hT[ecol*HSTR + eb];
            float hn = z*hold + (1.f - z)*hh;
            float hnew = msk ? hn : hold;
            g_hT[wbuf][ecol*NB + eb] = hnew;
            float yv = fl ? hnew : 0.f;
            g_Ah[(size_t)(eb*TT + t)*UU + ecol] = __float2half(yv);
        }
        grid_barrier();
    }
}

// ---------------- kernel 5: fp16 HMMA output GEMM ----------------
__global__ __launch_bounds__(256,2) void out_hmma(const float* __restrict__ ob,
                                                  float* __restrict__ C){
    extern __shared__ __align__(128) char sm[];
    const uint32_t sb = smem_to_u32(sm);
    const int tid = threadIdx.x, lane = tid & 31, wid = tid >> 5;
    const int m0 = blockIdx.x * 128;
    const int n0 = blockIdx.y * 128;
    const int wm = wid >> 2, wn = wid & 3;     // 2 x 4 warps

    auto loadA = [&](int kc, int st){
        const __half* gA = g_Ah + (size_t)m0*UU + kc*64;
        uint32_t base = sb + st*HG_BUFB;
        #pragma unroll
        for (int i=0;i<4;i++){
            int idx = tid + i*256;             // 0..1023
            int row = idx >> 3, seg = idx & 7; // 128 rows x 8 segs of 8 halves
            cp16(base + (uint32_t)(row*HG_STRIDE + seg*8)*2,
                 gA + (size_t)row*UU + seg*8);
        }
    };
    auto loadB = [&](int kc, int st){
        const __half* gB = g_Wh + (size_t)n0*UU + kc*64;
        uint32_t base = sb + (3+st)*HG_BUFB;
        #pragma unroll
        for (int i=0;i<4;i++){
            int idx = tid + i*256;
            int row = idx >> 3, seg = idx & 7;
            cp16(base + (uint32_t)(row*HG_STRIDE + seg*8)*2,
                 gB + (size_t)row*UU + seg*8);
        }
    };

    float acc[4][4][4];
    #pragma unroll
    for (int i=0;i<4;i++)
        #pragma unroll
        for (int j=0;j<4;j++)
            #pragma unroll
            for (int p=0;p<4;p++) acc[i][j][p] = 0.f;

    const int lane15 = lane & 15, laneHi = lane >> 4;
    const uint32_t aOff = (uint32_t)((wm*64 + lane15)*HG_STRIDE + laneHi*8)*2;
    const int nr  = (lane & 7) + ((lane >> 4) << 3);
    const int kc8 = ((lane >> 3) & 1) * 8;
    const uint32_t bOff = (uint32_t)((wn*32 + nr)*HG_STRIDE + kc8)*2;

    loadA(0,0); loadB(0,0); cp_commit();
    loadA(1,1); loadB(1,1); cp_commit();

    for (int kc=0; kc<16; kc++){
        int st = kc % 3;
        if (kc < 15) cp_wait<1>(); else cp_wait<0>();
        __syncthreads();
        if (kc + 2 < 16){
            loadA(kc+2, (kc+2)%3);
            loadB(kc+2, (kc+2)%3);
            cp_commit();
        }

        const uint32_t aBase = sb + st*HG_BUFB + aOff;
        const uint32_t bBase = sb + (3+st)*HG_BUFB + bOff;
        #pragma unroll
        for (int k16=0; k16<4; k16++){
            uint32_t af[4][4], bf[2][4];
            #pragma unroll
            for (int mi=0; mi<4; mi++)
                ldsm4(af[mi], aBase + (uint32_t)(mi*16*HG_STRIDE + k16*16)*2);
            #pragma unroll
            for (int ni=0; ni<2; ni++)
                ldsm4(bf[ni], bBase + (uint32_t)(ni*16*HG_STRIDE + k16*16)*2);
            #pragma unroll
            for (int mi=0; mi<4; mi++)
                #pragma unroll
                for (int nt=0; nt<4; nt++)
                    mma16816(acc[mi][nt], af[mi], &bf[nt>>1][(nt&1)*2]);
        }
    }

    // epilogue: bias + store (guard rows >= MROWS)
    const int g = lane >> 2, q = lane & 3;
    float2 bias2[4];
    #pragma unroll
    for (int nt=0; nt<4; nt++){
        int col = n0 + wn*32 + nt*8 + q*2;
        bias2[nt] = *(const float2*)(ob + col);
    }
    #pragma unroll
    for (int mi=0; mi<4; mi++){
        int r0 = m0 + wm*64 + mi*16 + g;
        int r1 = r0 + 8;
        #pragma unroll
        for (int nt=0; nt<4; nt++){
            int col = n0 + wn*32 + nt*8 + q*2;
            if (r0 < MROWS){
                float2 v = make_float2(acc[mi][nt][0] + bias2[nt].x,
                                       acc[mi][nt][1] + bias2[nt].y);
                *(float2*)(C + (size_t)r0*VV + col) = v;
            }
            if (r1 < MROWS){
                float2 v = make_float2(acc[mi][nt][2] + bias2[nt].x,
                                       acc[mi][nt][3] + bias2[nt].y);
                *(float2*)(C + (size_t)r1*VV + col) = v;
            }
        }
    }
}

// ---------------- launch ----------------
extern "C" void kernel_launch(void* const* d_in, const int* in_sizes, int n_in,
                              void* d_out, int out_size)
{
    const float* latent = (const float*)d_in[0];
    const int*   tok    = (const int*)d_in[1];
    const float* emb    = (const float*)d_in[2];
    const float* dW     = (const float*)d_in[3];
    const float* db     = (const float*)d_in[4];
    const float* gk     = (const float*)d_in[5];
    const float* grk    = (const float*)d_in[6];
    const float* gb     = (const float*)d_in[7];
    const float* oW     = (const float*)d_in[8];
    const float* ob     = (const float*)d_in[9];
    float* out = (float*)d_out;

    (void)in_sizes; (void)n_in; (void)out_size;

    cudaFuncSetAttribute(gru_kernel, cudaFuncAttributeMaxDynamicSharedMemorySize, GRU_SMEM);
    cudaFuncSetAttribute(out_hmma, cudaFuncAttributeMaxDynamicSharedMemorySize, HG_SMEM);
    cudaFuncSetAttribute(xp_hmma, cudaFuncAttributeMaxDynamicSharedMemorySize, HG_SMEM);

    void *xproj_p = nullptr;
    cudaGetSymbolAddress(&xproj_p, g_xproj);

    h0_kernel<<<(NB*UU + 255)/256, 256>>>(latent, dW, db);
    prep_kernel<<<1, 256>>>(tok);
    convEmb_kernel<<<(VV*EE/4 + 255)/256, 256>>>(emb);
    convGkT_kernel<<<dim3(N3/32, EE/32), dim3(32,8)>>>(gk);
    convW_kernel<<<dim3(VV/32, UU/32), dim3(32,8)>>>(oW);

    // xproj = emb[tok] @ gru_kernel + gru_bias[0]   (HMMA)
    xp_hmma<<<dim3(MPAD/128, N3/128), 256, HG_SMEM>>>(gb, (float*)xproj_p);

    gru_kernel<<<GRU_BLOCKS, 256, GRU_SMEM>>>(grk, gb, tok);

    // m tiles fastest (blockIdx.x) so co-resident CTAs share the same B panel in L2
    out_hmma<<<dim3(MPAD/128, VV/128), 256, HG_SMEM>>>(ob, out);
}

// round 8
// speedup vs baseline: 1.8628x; 1.3282x over previous
#include <cuda_runtime.h>
#include <cuda_fp16.h>
#include <cstdint>

// Problem constants
#define NB   16          // batch
#define TT   255         // teacher length (T-1)
#define UU   1024        // GRU units
#define VV   32000       // vocab
#define EE   256         // emb dim
#define LATD 512         // latent dim
#define MROWS (NB*TT)    // 4080
#define MPAD 4096
#define N3   (3*UU)      // 3072

#define GRU_BLOCKS 128
#define AST 1032                             // padded k-stride of A tiles (halves)
#define GRU_SMEM (2*16*AST*2 + 8*16*28*4)    // Ahi+Alo (66048) + scratch (14336) = 80384

// ---------------- device scratch (no allocs allowed) ----------------
__device__ float g_hB[2][NB*UU];                      // hidden state [batch][unit], ping-pong
__device__ float g_xproj[(size_t)MROWS*N3];           // x @ gru_kernel + b0
__device__ __align__(128) __half g_Ah[(size_t)MPAD*UU];   // fp16 GRU outputs (rows>=4080 stay 0)
__device__ __align__(128) __half g_Wh[(size_t)VV*UU];     // fp16 out_W^T  [V][U]
__device__ __align__(128) __half g_embh[(size_t)VV*EE];   // fp16 emb
__device__ __align__(128) __half g_gkT[(size_t)N3*EE];    // fp16 gru_kernel^T [3072][256]
__device__ __align__(128) __half g_rkTh[(size_t)N3*UU];   // fp16 gru_rkernel^T [3072][1024]
__device__ int   g_arow[MROWS];
__device__ unsigned char g_flag[MROWS];
__device__ unsigned int g_bar_cnt = 0;
__device__ unsigned int g_bar_gen = 0;

// ---------------- PTX helpers ----------------
__device__ __forceinline__ uint32_t smem_to_u32(const void* p){
    uint32_t a;
    asm("{ .reg .u64 t; cvta.to.shared.u64 t, %1; cvt.u32.u64 %0, t; }" : "=r"(a) : "l"(p));
    return a;
}
__device__ __forceinline__ void cp16(uint32_t s, const void* g){
    asm volatile("cp.async.cg.shared.global [%0], [%1], 16;" :: "r"(s), "l"(g));
}
__device__ __forceinline__ void cp_commit(){ asm volatile("cp.async.commit_group;" ::: "memory"); }
template<int N> __device__ __forceinline__ void cp_wait(){
    asm volatile("cp.async.wait_group %0;" :: "n"(N) : "memory");
}
__device__ __forceinline__ void ldsm4(uint32_t* r, uint32_t addr){
    asm volatile("ldmatrix.sync.aligned.m8n8.x4.shared.b16 {%0,%1,%2,%3}, [%4];"
        : "=r"(r[0]),"=r"(r[1]),"=r"(r[2]),"=r"(r[3]) : "r"(addr));
}
__device__ __forceinline__ void mma16816(float* c, const uint32_t* a, const uint32_t* b){
    asm volatile("mma.sync.aligned.m16n8k16.row.col.f32.f16.f16.f32 "
        "{%0,%1,%2,%3}, {%4,%5,%6,%7}, {%8,%9}, {%0,%1,%2,%3};"
        : "+f"(c[0]), "+f"(c[1]), "+f"(c[2]), "+f"(c[3])
        : "r"(a[0]), "r"(a[1]), "r"(a[2]), "r"(a[3]), "r"(b[0]), "r"(b[1]));
}

// R5-proven grid barrier: acq_rel atomics on (cnt, gen), thread-0 spin
__device__ __forceinline__ void grid_barrier(){
    __syncthreads();
    if (threadIdx.x == 0){
        unsigned gen, old;
        asm volatile("ld.acquire.gpu.u32 %0, [%1];" : "=r"(gen) : "l"(&g_bar_gen));
        asm volatile("atom.acq_rel.gpu.add.u32 %0, [%1], 1;" : "=r"(old) : "l"(&g_bar_cnt));
        if (old == gridDim.x - 1){
            *(volatile unsigned*)&g_bar_cnt = 0;
            asm volatile("red.release.gpu.add.u32 [%0], 1;" :: "l"(&g_bar_gen));
        } else {
            unsigned g2;
            do {
                asm volatile("ld.acquire.gpu.u32 %0, [%1];" : "=r"(g2) : "l"(&g_bar_gen));
            } while (g2 == gen);
        }
    }
    __syncthreads();
}

// ---------------- kernel 1: h0 = latent @ dense_W + dense_b ([batch][unit]) ----------------
__global__ void h0_kernel(const float* __restrict__ lat,
                          const float* __restrict__ W,
                          const float* __restrict__ bb){
    int o = blockIdx.x*blockDim.x + threadIdx.x;
    if (o >= NB*UU) return;
    int b = o >> 10, u = o & (UU-1);
    float acc = bb[u];
    const float* lrow = lat + b*LATD;
    #pragma unroll 8
    for (int k=0;k<LATD;k++) acc = fmaf(lrow[k], W[(size_t)k*UU + u], acc);
    g_hB[0][b*UU + u] = acc;
}

// ---------------- kernel 2: token gather index + prefix-OR flag ----------------
__global__ void prep_kernel(const int* __restrict__ tok){
    int tid = threadIdx.x;
    if (tid < NB){
        unsigned char f = 0;
        for (int t=0;t<TT;t++){
            f |= (tok[tid*256 + t] != 0) ? 1 : 0;
            g_flag[tid*TT + t] = f;
        }
    }
    for (int m=tid; m<MROWS; m+=blockDim.x){
        int v = tok[(m/TT)*256 + (m%TT)];
        if (v < 0) v = 0;
        if (v >= VV) v = VV-1;
        g_arow[m] = v;
    }
}

// ---------------- kernel 2b: transpose out_W [U][V] -> fp16 g_Wh [V][U] ----------------
__global__ void convW_kernel(const float* __restrict__ W){
    __shared__ float tile[32][33];
    int n0 = blockIdx.x*32, k0 = blockIdx.y*32;
    int tx = threadIdx.x, ty = threadIdx.y;   // 32 x 8
    #pragma unroll
    for (int i=ty; i<32; i+=8)
        tile[i][tx] = W[(size_t)(k0+i)*VV + n0+tx];
    __syncthreads();
    #pragma unroll
    for (int i=ty; i<32; i+=8){
        int n = n0 + i, k = k0 + tx;
        g_Wh[(size_t)n*UU + k] = __float2half(tile[tx][i]);
    }
}

// ---------------- kernel 2c: emb fp32 -> fp16 ----------------
__global__ void convEmb_kernel(const float* __restrict__ E){
    int i = blockIdx.x*blockDim.x + threadIdx.x;
    if (i >= VV*EE/4) return;
    float4 v = ((const float4*)E)[i];
    __half2* dst = (__half2*)g_embh;
    dst[i*2+0] = __floats2half2_rn(v.x, v.y);
    dst[i*2+1] = __floats2half2_rn(v.z, v.w);
}

// ---------------- kernel 2d: transpose gru_kernel [E][N3] -> fp16 g_gkT [N3][E] ----------------
__global__ void convGkT_kernel(const float* __restrict__ G){
    __shared__ float tile[32][33];
    int n0 = blockIdx.x*32, k0 = blockIdx.y*32;
    int tx = threadIdx.x, ty = threadIdx.y;
    #pragma unroll
    for (int i=ty; i<32; i+=8)
        tile[i][tx] = G[(size_t)(k0+i)*N3 + n0+tx];
    __syncthreads();
    #pragma unroll
    for (int i=ty; i<32; i+=8){
        int n = n0 + i, k = k0 + tx;
        g_gkT[(size_t)n*EE + k] = __float2half(tile[tx][i]);
    }
}

// ---------------- kernel 2e: transpose gru_rkernel [U][N3] -> fp16 g_rkTh [N3][U] ----------------
__global__ void convRkT_kernel(const float* __restrict__ G){
    __shared__ float tile[32][33];
    int n0 = blockIdx.x*32, k0 = blockIdx.y*32;
    int tx = threadIdx.x, ty = threadIdx.y;
    #pragma unroll
    for (int i=ty; i<32; i+=8)
        tile[i][tx] = G[(size_t)(k0+i)*N3 + n0+tx];
    __syncthreads();
    #pragma unroll
    for (int i=ty; i<32; i+=8){
        int n = n0 + i, k = k0 + tx;
        g_rkTh[(size_t)n*UU + k] = __float2half(tile[tx][i]);
    }
}

// ---------------- shared HMMA tile constants ----------------
#define HG_STRIDE 72
#define HG_BUFB   (128*HG_STRIDE*2)
#define HG_SMEM   (6*HG_BUFB)

// ---------------- kernel 3: fp16 HMMA xproj GEMM (gathered A) ----------------
__global__ __launch_bounds__(256,2) void xp_hmma(const float* __restrict__ bias0,
                                                 float* __restrict__ C){
    extern __shared__ __align__(128) char sm[];
    const uint32_t sb = smem_to_u32(sm);
    const int tid = threadIdx.x, lane = tid & 31, wid = tid >> 5;
    const int m0 = blockIdx.x * 128;
    const int n0 = blockIdx.y * 128;
    const int wm = wid >> 2, wn = wid & 3;

    const __half* aptr[4];
    int asegs[4];
    #pragma unroll
    for (int i=0;i<4;i++){
        int idx = tid + i*256;
        int row = idx >> 3; asegs[i] = idx & 7;
        int grow = m0 + row;
        int tokv = (grow < MROWS) ? g_arow[grow] : 0;
        aptr[i] = g_embh + (size_t)tokv*EE;
    }
    auto loadA = [&](int kc, int st){
        uint32_t base = sb + st*HG_BUFB;
        #pragma unroll
        for (int i=0;i<4;i++){
            int idx = tid + i*256;
            int row = idx >> 3;
            cp16(base + (uint32_t)(row*HG_STRIDE + asegs[i]*8)*2,
                 aptr[i] + kc*64 + asegs[i]*8);
        }
    };
    auto loadB = [&](int kc, int st){
        const __half* gB = g_gkT + (size_t)n0*EE + kc*64;
        uint32_t base = sb + (3+st)*HG_BUFB;
        #pragma unroll
        for (int i=0;i<4;i++){
            int idx = tid + i*256;
            int row = idx >> 3, seg = idx & 7;
            cp16(base + (uint32_t)(row*HG_STRIDE + seg*8)*2,
                 gB + (size_t)row*EE + seg*8);
        }
    };

    float acc[4][4][4];
    #pragma unroll
    for (int i=0;i<4;i++)
        #pragma unroll
        for (int j=0;j<4;j++)
            #pragma unroll
            for (int p=0;p<4;p++) acc[i][j][p] = 0.f;

    const int lane15 = lane & 15, laneHi = lane >> 4;
    const uint32_t aOff = (uint32_t)((wm*64 + lane15)*HG_STRIDE + laneHi*8)*2;
    const int nr  = (lane & 7) + ((lane >> 4) << 3);
    const int kc8 = ((lane >> 3) & 1) * 8;
    const uint32_t bOff = (uint32_t)((wn*32 + nr)*HG_STRIDE + kc8)*2;

    loadA(0,0); loadB(0,0); cp_commit();
    loadA(1,1); loadB(1,1); cp_commit();

    for (int kc=0; kc<4; kc++){
        int st = kc % 3;
        if (kc < 3) cp_wait<1>(); else cp_wait<0>();
        __syncthreads();
        if (kc + 2 < 4){
            loadA(kc+2, (kc+2)%3);
            loadB(kc+2, (kc+2)%3);
            cp_commit();
        }
        const uint32_t aBase = sb + st*HG_BUFB + aOff;
        const uint32_t bBase = sb + (3+st)*HG_BUFB + bOff;
        #pragma unroll
        for (int k16=0; k16<4; k16++){
            uint32_t af[4][4], bf[2][4];
            #pragma unroll
            for (int mi=0; mi<4; mi++)
                ldsm4(af[mi], aBase + (uint32_t)(mi*16*HG_STRIDE + k16*16)*2);
            #pragma unroll
            for (int ni=0; ni<2; ni++)
                ldsm4(bf[ni], bBase + (uint32_t)(ni*16*HG_STRIDE + k16*16)*2);
            #pragma unroll
            for (int mi=0; mi<4; mi++)
                #pragma unroll
                for (int nt=0; nt<4; nt++)
                    mma16816(acc[mi][nt], af[mi], &bf[nt>>1][(nt&1)*2]);
        }
        if (kc < 3) __syncthreads();
    }

    const int g = lane >> 2, q = lane & 3;
    float2 bias2[4];
    #pragma unroll
    for (int nt=0; nt<4; nt++){
        int col = n0 + wn*32 + nt*8 + q*2;
        bias2[nt] = *(const float2*)(bias0 + col);
    }
    #pragma unroll
    for (int mi=0; mi<4; mi++){
        int r0 = m0 + wm*64 + mi*16 + g;
        int r1 = r0 + 8;
        #pragma unroll
        for (int nt=0; nt<4; nt++){
            int col = n0 + wn*32 + nt*8 + q*2;
            if (r0 < MROWS){
                float2 v = make_float2(acc[mi][nt][0] + bias2[nt].x,
                                       acc[mi][nt][1] + bias2[nt].y);
                *(float2*)(C + (size_t)r0*N3 + col) = v;
            }
            if (r1 < MROWS){
                float2 v = make_float2(acc[mi][nt][2] + bias2[nt].x,
                                       acc[mi][nt][3] + bias2[nt].y);
                *(float2*)(C + (size_t)r1*N3 + col) = v;
            }
        }
    }
}

// ---------------- kernel 4: persistent GRU, tensor-core recurrence ----------------
// rp = h @ rk for this CTA's 24 columns via mma.m16n8k16.
// h enters exactly as hi/lo fp16 split (2 passes, same fp32 acc); rk fp16 in registers.
// Warp w owns k-slice [w*128, w*128+128): B-frags = 48 regs, persistent across steps.
__global__ __launch_bounds__(256,1) void gru_kernel(
    const float* __restrict__ gbias,
    const int* __restrict__ tok)
{
    extern __shared__ char smg[];
    __half* Ahi = (__half*)smg;                       // [16][AST]
    __half* Alo = (__half*)(smg + 16*AST*2);          // [16][AST]
    float*  sc  = (float*)(smg + 2*16*AST*2);         // [8][16][28]
    const int tid = threadIdx.x, lane = tid & 31, wrp = tid >> 5, bl = blockIdx.x;
    const int g = lane >> 2, tig = lane & 3;

    // one-time B fragments from g_rkTh (fp16 rk^T [3072][1024])
    uint32_t bw[8][3][2];
    #pragma unroll
    for (int j=0;j<8;j++)
        #pragma unroll
        for (int nt=0;nt<3;nt++){
            const __half* base = g_rkTh + (size_t)(nt*UU + bl*8 + g)*UU + wrp*128 + j*16 + 2*tig;
            bw[j][nt][0] = *(const uint32_t*)base;
            bw[j][nt][1] = *(const uint32_t*)(base + 8);
        }

    int eb=0, eu=0, ecol=0;
    float bz=0.f, br=0.f, bh=0.f;
    if (tid < 128){
        eb = tid >> 3; eu = tid & 7; ecol = bl*8 + eu;
        bz = gbias[N3 + ecol];
        br = gbias[N3 + UU + ecol];
        bh = gbias[N3 + 2*UU + ecol];
    }

    for (int t=0; t<TT; t++){
        const int rbuf = t & 1, wbuf = rbuf ^ 1;

        // prefetch epilogue inputs
        float xz=0.f, xr=0.f, xh=0.f, hold=0.f; bool msk=false, fl=false;
        if (tid < 128){
            int r = eb*TT + t;
            const float* xp = g_xproj + (size_t)r*N3;
            xz = xp[ecol]; xr = xp[UU+ecol]; xh = xp[2*UU+ecol];
            hold = g_hB[rbuf][eb*UU + ecol];
            msk = (tok[eb*256 + t] != 0);
            fl  = (g_flag[r] != 0);
        }

        // broadcast h -> SMEM as exact hi/lo fp16 split (iter it = batch)
        #pragma unroll 4
        for (int it=0; it<16; it++){
            float4 v = *(const float4*)&g_hB[rbuf][it*UU + tid*4];
            __half h0=__float2half(v.x), h1=__float2half(v.y),
                   h2=__float2half(v.z), h3=__float2half(v.w);
            __half l0=__float2half(v.x-__half2float(h0)),
                   l1=__float2half(v.y-__half2float(h1)),
                   l2=__float2half(v.z-__half2float(h2)),
                   l3=__float2half(v.w-__half2float(h3));
            __half2* dh = (__half2*)&Ahi[it*AST + tid*4];
            dh[0] = __halves2half2(h0,h1); dh[1] = __halves2half2(h2,h3);
            __half2* dl = (__half2*)&Alo[it*AST + tid*4];
            dl[0] = __halves2half2(l0,l1); dl[1] = __halves2half2(l2,l3);
        }
        __syncthreads();

        // tensor-core partial rp for this warp's k-slice
        float acc[3][4];
        #pragma unroll
        for (int nt=0;nt<3;nt++)
            #pragma unroll
            for (int p=0;p<4;p++) acc[nt][p] = 0.f;

        #pragma unroll
        for (int ps=0; ps<2; ps++){
            const char* Ab = ps ? (const char*)Alo : (const char*)Ahi;
            #pragma unroll
            for (int j=0;j<8;j++){
                int koff = wrp*128 + j*16;
                uint32_t a[4];
                a[0] = *(const uint32_t*)(Ab + (size_t)(g*AST     + koff + 2*tig    )*2);
                a[1] = *(const uint32_t*)(Ab + (size_t)((g+8)*AST + koff + 2*tig    )*2);
                a[2] = *(const uint32_t*)(Ab + (size_t)(g*AST     + koff + 2*tig + 8)*2);
                a[3] = *(const uint32_t*)(Ab + (size_t)((g+8)*AST + koff + 2*tig + 8)*2);
                #pragma unroll
                for (int nt=0;nt<3;nt++)
                    mma16816(acc[nt], a, bw[j][nt]);
            }
        }

        // store partials: sc[w][batch][col]
        #pragma unroll
        for (int nt=0;nt<3;nt++){
            int c = nt*8 + 2*tig;
            sc[(wrp*16 + g  )*28 + c    ] = acc[nt][0];
            sc[(wrp*16 + g  )*28 + c + 1] = acc[nt][1];
            sc[(wrp*16 + g+8)*28 + c    ] = acc[nt][2];
            sc[(wrp*16 + g+8)*28 + c + 1] = acc[nt][3];
        }
        __syncthreads();

        // gate math + state update
        if (tid < 128){
            float rz = bz, rr = br, rh = bh;
            #pragma unroll
            for (int w=0;w<8;w++){
                const float* p = &sc[(w*16 + eb)*28];
                rz += p[eu]; rr += p[8+eu]; rh += p[16+eu];
            }
            float z  = 1.f/(1.f + __expf(-(xz+rz)));
            float rg = 1.f/(1.f + __expf(-(xr+rr)));
            float hh = tanhf(xh + rg*rh);
            float hn = z*hold + (1.f - z)*hh;
            float hnew = msk ? hn : hold;
            g_hB[wbuf][eb*UU + ecol] = hnew;
            float yv = fl ? hnew : 0.f;
            g_Ah[(size_t)(eb*TT + t)*UU + ecol] = __float2half(yv);
        }
        grid_barrier();
    }
}

// ---------------- kernel 5: fp16 HMMA output GEMM ----------------
__global__ __launch_bounds__(256,2) void out_hmma(const float* __restrict__ ob,
                                                  float* __restrict__ C){
    extern __shared__ __align__(128) char sm[];
    const uint32_t sb = smem_to_u32(sm);
    const int tid = threadIdx.x, lane = tid & 31, wid = tid >> 5;
    const int m0 = blockIdx.x * 128;
    const int n0 = blockIdx.y * 128;
    const int wm = wid >> 2, wn = wid & 3;

    auto loadA = [&](int kc, int st){
        const __half* gA = g_Ah + (size_t)m0*UU + kc*64;
        uint32_t base = sb + st*HG_BUFB;
        #pragma unroll
        for (int i=0;i<4;i++){
            int idx = tid + i*256;
            int row = idx >> 3, seg = idx & 7;
            cp16(base + (uint32_t)(row*HG_STRIDE + seg*8)*2,
                 gA + (size_t)row*UU + seg*8);
        }
    };
    auto loadB = [&](int kc, int st){
        const __half* gB = g_Wh + (size_t)n0*UU + kc*64;
        uint32_t base = sb + (3+st)*HG_BUFB;
        #pragma unroll
        for (int i=0;i<4;i++){
            int idx = tid + i*256;
            int row = idx >> 3, seg = idx & 7;
            cp16(base + (uint32_t)(row*HG_STRIDE + seg*8)*2,
                 gB + (size_t)row*UU + seg*8);
        }
    };

    float acc[4][4][4];
    #pragma unroll
    for (int i=0;i<4;i++)
        #pragma unroll
        for (int j=0;j<4;j++)
            #pragma unroll
            for (int p=0;p<4;p++) acc[i][j][p] = 0.f;

    const int lane15 = lane & 15, laneHi = lane >> 4;
    const uint32_t aOff = (uint32_t)((wm*64 + lane15)*HG_STRIDE + laneHi*8)*2;
    const int nr  = (lane & 7) + ((lane >> 4) << 3);
    const int kc8 = ((lane >> 3) & 1) * 8;
    const uint32_t bOff = (uint32_t)((wn*32 + nr)*HG_STRIDE + kc8)*2;

    loadA(0,0); loadB(0,0); cp_commit();
    loadA(1,1); loadB(1,1); cp_commit();

    for (int kc=0; kc<16; kc++){
        int st = kc % 3;
        if (kc < 15) cp_wait<1>(); else cp_wait<0>();
        __syncthreads();
        if (kc + 2 < 16){
            loadA(kc+2, (kc+2)%3);
            loadB(kc+2, (kc+2)%3);
            cp_commit();
        }

        const uint32_t aBase = sb + st*HG_BUFB + aOff;
        const uint32_t bBase = sb + (3+st)*HG_BUFB + bOff;
        #pragma unroll
        for (int k16=0; k16<4; k16++){
            uint32_t af[4][4], bf[2][4];
            #pragma unroll
            for (int mi=0; mi<4; mi++)
                ldsm4(af[mi], aBase + (uint32_t)(mi*16*HG_STRIDE + k16*16)*2);
            #pragma unroll
            for (int ni=0; ni<2; ni++)
                ldsm4(bf[ni], bBase + (uint32_t)(ni*16*HG_STRIDE + k16*16)*2);
            #pragma unroll
            for (int mi=0; mi<4; mi++)
                #pragma unroll
                for (int nt=0; nt<4; nt++)
                    mma16816(acc[mi][nt], af[mi], &bf[nt>>1][(nt&1)*2]);
        }
    }

    const int g = lane >> 2, q = lane & 3;
    float2 bias2[4];
    #pragma unroll
    for (int nt=0; nt<4; nt++){
        int col = n0 + wn*32 + nt*8 + q*2;
        bias2[nt] = *(const float2*)(ob + col);
    }
    #pragma unroll
    for (int mi=0; mi<4; mi++){
        int r0 = m0 + wm*64 + mi*16 + g;
        int r1 = r0 + 8;
        #pragma unroll
        for (int nt=0; nt<4; nt++){
            int col = n0 + wn*32 + nt*8 + q*2;
            if (r0 < MROWS){
                float2 v = make_float2(acc[mi][nt][0] + bias2[nt].x,
                                       acc[mi][nt][1] + bias2[nt].y);
                *(float2*)(C + (size_t)r0*VV + col) = v;
            }
            if (r1 < MROWS){
                float2 v = make_float2(acc[mi][nt][2] + bias2[nt].x,
                                       acc[mi][nt][3] + bias2[nt].y);
                *(float2*)(C + (size_t)r1*VV + col) = v;
            }
        }
    }
}

// ---------------- launch ----------------
extern "C" void kernel_launch(void* const* d_in, const int* in_sizes, int n_in,
                              void* d_out, int out_size)
{
    const float* latent = (const float*)d_in[0];
    const int*   tok    = (const int*)d_in[1];
    const float* emb    = (const float*)d_in[2];
    const float* dW     = (const float*)d_in[3];
    const float* db     = (const float*)d_in[4];
    const float* gk     = (const float*)d_in[5];
    const float* grk    = (const float*)d_in[6];
    const float* gb     = (const float*)d_in[7];
    const float* oW     = (const float*)d_in[8];
    const float* ob     = (const float*)d_in[9];
    float* out = (float*)d_out;

    (void)in_sizes; (void)n_in; (void)out_size;

    cudaFuncSetAttribute(gru_kernel, cudaFuncAttributeMaxDynamicSharedMemorySize, GRU_SMEM);
    cudaFuncSetAttribute(out_hmma, cudaFuncAttributeMaxDynamicSharedMemorySize, HG_SMEM);
    cudaFuncSetAttribute(xp_hmma, cudaFuncAttributeMaxDynamicSharedMemorySize, HG_SMEM);

    void *xproj_p = nullptr;
    cudaGetSymbolAddress(&xproj_p, g_xproj);

    h0_kernel<<<(NB*UU + 255)/256, 256>>>(latent, dW, db);
    prep_kernel<<<1, 256>>>(tok);
    convEmb_kernel<<<(VV*EE/4 + 255)/256, 256>>>(emb);
    convGkT_kernel<<<dim3(N3/32, EE/32), dim3(32,8)>>>(gk);
    convRkT_kernel<<<dim3(N3/32, UU/32), dim3(32,8)>>>(grk);
    convW_kernel<<<dim3(VV/32, UU/32), dim3(32,8)>>>(oW);

    // xproj = emb[tok] @ gru_kernel + gru_bias[0]   (HMMA)
    xp_hmma<<<dim3(MPAD/128, N3/128), 256, HG_SMEM>>>(gb, (float*)xproj_p);

    gru_kernel<<<GRU_BLOCKS, 256, GRU_SMEM>>>(gb, tok);

    // m tiles fastest (blockIdx.x) so co-resident CTAs share the same B panel in L2
    out_hmma<<<dim3(MPAD/128, VV/128), 256, HG_SMEM>>>(ob, out);
}

// round 9
// speedup vs baseline: 1.9413x; 1.0421x over previous
#include <cuda_runtime.h>
#include <cuda_fp16.h>
#include <cstdint>

// Problem constants
#define NB   16          // batch
#define TT   255         // teacher length (T-1)
#define UU   1024        // GRU units
#define VV   32000       // vocab
#define EE   256         // emb dim
#define LATD 512         // latent dim
#define MROWS (NB*TT)    // 4080
#define MPAD 4096
#define N3   (3*UU)      // 3072

#define GRU_BLOCKS 128
#define AST 1032                             // padded k-stride of A tiles (halves)
#define GRU_SMEM (2*16*AST*2 + 8*16*28*4)    // Ahi+Alo (66048) + scratch (14336) = 80384

// ---------------- device scratch (no allocs allowed) ----------------
__device__ __align__(128) __half g_hfp[2][2][NB*UU];  // [buf][hi|lo][batch*unit] exact fp16 split of h
__device__ float g_xproj[(size_t)MROWS*N3];           // x @ gru_kernel + b0
__device__ __align__(128) __half g_Ah[(size_t)MPAD*UU];   // fp16 GRU outputs (rows>=4080 stay 0)
__device__ __align__(128) __half g_Wh[(size_t)VV*UU];     // fp16 out_W^T  [V][U]
__device__ __align__(128) __half g_embh[(size_t)VV*EE];   // fp16 emb
__device__ __align__(128) __half g_gkT[(size_t)N3*EE];    // fp16 gru_kernel^T [3072][256]
__device__ __align__(128) __half g_rkTh[(size_t)N3*UU];   // fp16 gru_rkernel^T [3072][1024]
__device__ int   g_arow[MROWS];
__device__ unsigned char g_flag[MROWS];
__device__ unsigned int g_bar_cnt = 0;
__device__ unsigned int g_bar_gen = 0;

// ---------------- PTX helpers ----------------
__device__ __forceinline__ uint32_t smem_to_u32(const void* p){
    uint32_t a;
    asm("{ .reg .u64 t; cvta.to.shared.u64 t, %1; cvt.u32.u64 %0, t; }" : "=r"(a) : "l"(p));
    return a;
}
__device__ __forceinline__ void cp16(uint32_t s, const void* g){
    asm volatile("cp.async.cg.shared.global [%0], [%1], 16;" :: "r"(s), "l"(g));
}
__device__ __forceinline__ void cp_commit(){ asm volatile("cp.async.commit_group;" ::: "memory"); }
template<int N> __device__ __forceinline__ void cp_wait(){
    asm volatile("cp.async.wait_group %0;" :: "n"(N) : "memory");
}
__device__ __forceinline__ void ldsm4(uint32_t* r, uint32_t addr){
    asm volatile("ldmatrix.sync.aligned.m8n8.x4.shared.b16 {%0,%1,%2,%3}, [%4];"
        : "=r"(r[0]),"=r"(r[1]),"=r"(r[2]),"=r"(r[3]) : "r"(addr));
}
__device__ __forceinline__ void mma16816(float* c, const uint32_t* a, const uint32_t* b){
    asm volatile("mma.sync.aligned.m16n8k16.row.col.f32.f16.f16.f32 "
        "{%0,%1,%2,%3}, {%4,%5,%6,%7}, {%8,%9}, {%0,%1,%2,%3};"
        : "+f"(c[0]), "+f"(c[1]), "+f"(c[2]), "+f"(c[3])
        : "r"(a[0]), "r"(a[1]), "r"(a[2]), "r"(a[3]), "r"(b[0]), "r"(b[1]));
}

// R5-proven grid barrier: acq_rel atomics on (cnt, gen), thread-0 spin
__device__ __forceinline__ void grid_barrier(){
    __syncthreads();
    if (threadIdx.x == 0){
        unsigned gen, old;
        asm volatile("ld.acquire.gpu.u32 %0, [%1];" : "=r"(gen) : "l"(&g_bar_gen));
        asm volatile("atom.acq_rel.gpu.add.u32 %0, [%1], 1;" : "=r"(old) : "l"(&g_bar_cnt));
        if (old == gridDim.x - 1){
            *(volatile unsigned*)&g_bar_cnt = 0;
            asm volatile("red.release.gpu.add.u32 [%0], 1;" :: "l"(&g_bar_gen));
        } else {
            unsigned g2;
            do {
                asm volatile("ld.acquire.gpu.u32 %0, [%1];" : "=r"(g2) : "l"(&g_bar_gen));
            } while (g2 == gen);
        }
    }
    __syncthreads();
}

// ---------------- fused prep kernel ----------------
// blocks: [0]=prep, [1,8001)=convEmb, [8001,8769)=convGkT, [8769,8833)=h0,
//         [8833,11905)=convRkT, [11905,43905)=convW
#define PB_PREP 1
#define PB_EMB  8000
#define PB_GKT  768
#define PB_H0   64
#define PB_RKT  3072
#define PB_W    32000
#define PB_TOTAL (PB_PREP+PB_EMB+PB_GKT+PB_H0+PB_RKT+PB_W)

__global__ void prep_all(const float* __restrict__ lat, const float* __restrict__ dW,
                         const float* __restrict__ db,  const int* __restrict__ tok,
                         const float* __restrict__ emb, const float* __restrict__ gk,
                         const float* __restrict__ grk, const float* __restrict__ oW){
    __shared__ float tile[32][33];
    int bid = blockIdx.x;
    const int tid = threadIdx.x;
    const int tx = tid & 31, ty = tid >> 5;

    if (bid < PB_PREP){
        if (tid < NB){
            unsigned char f = 0;
            for (int t=0;t<TT;t++){
                f |= (tok[tid*256 + t] != 0) ? 1 : 0;
                g_flag[tid*TT + t] = f;
            }
        }
        for (int m=tid; m<MROWS; m+=256){
            int v = tok[(m/TT)*256 + (m%TT)];
            if (v < 0) v = 0;
            if (v >= VV) v = VV-1;
            g_arow[m] = v;
        }
        return;
    }
    bid -= PB_PREP;

    if (bid < PB_EMB){
        int i = bid*256 + tid;
        float4 v = ((const float4*)emb)[i];
        __half2* dst = (__half2*)g_embh;
        dst[i*2+0] = __floats2half2_rn(v.x, v.y);
        dst[i*2+1] = __floats2half2_rn(v.z, v.w);
        return;
    }
    bid -= PB_EMB;

    if (bid < PB_GKT){
        int n0 = (bid % 96)*32, k0 = (bid / 96)*32;
        #pragma unroll
        for (int i=ty; i<32; i+=8)
            tile[i][tx] = gk[(size_t)(k0+i)*N3 + n0+tx];
        __syncthreads();
        #pragma unroll
        for (int i=ty; i<32; i+=8)
            g_gkT[(size_t)(n0+i)*EE + k0+tx] = __float2half(tile[tx][i]);
        return;
    }
    bid -= PB_GKT;

    if (bid < PB_H0){
        int o = bid*256 + tid;
        int b = o >> 10, u = o & (UU-1);
        float acc = db[u];
        const float* lrow = lat + b*LATD;
        #pragma unroll 8
        for (int k=0;k<LATD;k++) acc = fmaf(lrow[k], dW[(size_t)k*UU + u], acc);
        __half hi = __float2half(acc);
        __half lo = __float2half(acc - __half2float(hi));
        g_hfp[0][0][b*UU + u] = hi;
        g_hfp[0][1][b*UU + u] = lo;
        return;
    }
    bid -= PB_H0;

    if (bid < PB_RKT){
        int n0 = (bid % 96)*32, k0 = (bid / 96)*32;
        #pragma unroll
        for (int i=ty; i<32; i+=8)
            tile[i][tx] = grk[(size_t)(k0+i)*N3 + n0+tx];
        __syncthreads();
        #pragma unroll
        for (int i=ty; i<32; i+=8)
            g_rkTh[(size_t)(n0+i)*UU + k0+tx] = __float2half(tile[tx][i]);
        return;
    }
    bid -= PB_RKT;

    {   // convW: transpose out_W [U][V] -> fp16 g_Wh [V][U]
        int n0 = (bid % 1000)*32, k0 = (bid / 1000)*32;
        #pragma unroll
        for (int i=ty; i<32; i+=8)
            tile[i][tx] = oW[(size_t)(k0+i)*VV + n0+tx];
        __syncthreads();
        #pragma unroll
        for (int i=ty; i<32; i+=8)
            g_Wh[(size_t)(n0+i)*UU + k0+tx] = __float2half(tile[tx][i]);
        return;
    }
}

// ---------------- shared HMMA tile constants ----------------
#define HG_STRIDE 72
#define HG_BUFB   (128*HG_STRIDE*2)
#define HG_SMEM   (6*HG_BUFB)

// ---------------- kernel 3: fp16 HMMA xproj GEMM (gathered A) ----------------
__global__ __launch_bounds__(256,2) void xp_hmma(const float* __restrict__ bias0,
                                                 float* __restrict__ C){
    extern __shared__ __align__(128) char sm[];
    const uint32_t sb = smem_to_u32(sm);
    const int tid = threadIdx.x, lane = tid & 31, wid = tid >> 5;
    const int m0 = blockIdx.x * 128;
    const int n0 = blockIdx.y * 128;
    const int wm = wid >> 2, wn = wid & 3;

    const __half* aptr[4];
    int asegs[4];
    #pragma unroll
    for (int i=0;i<4;i++){
        int idx = tid + i*256;
        int row = idx >> 3; asegs[i] = idx & 7;
        int grow = m0 + row;
        int tokv = (grow < MROWS) ? g_arow[grow] : 0;
        aptr[i] = g_embh + (size_t)tokv*EE;
    }
    auto loadA = [&](int kc, int st){
        uint32_t base = sb + st*HG_BUFB;
        #pragma unroll
        for (int i=0;i<4;i++){
            int idx = tid + i*256;
            int row = idx >> 3;
            cp16(base + (uint32_t)(row*HG_STRIDE + asegs[i]*8)*2,
                 aptr[i] + kc*64 + asegs[i]*8);
        }
    };
    auto loadB = [&](int kc, int st){
        const __half* gB = g_gkT + (size_t)n0*EE + kc*64;
        uint32_t base = sb + (3+st)*HG_BUFB;
        #pragma unroll
        for (int i=0;i<4;i++){
            int idx = tid + i*256;
            int row = idx >> 3, seg = idx & 7;
            cp16(base + (uint32_t)(row*HG_STRIDE + seg*8)*2,
                 gB + (size_t)row*EE + seg*8);
        }
    };

    float acc[4][4][4];
    #pragma unroll
    for (int i=0;i<4;i++)
        #pragma unroll
        for (int j=0;j<4;j++)
            #pragma unroll
            for (int p=0;p<4;p++) acc[i][j][p] = 0.f;

    const int lane15 = lane & 15, laneHi = lane >> 4;
    const uint32_t aOff = (uint32_t)((wm*64 + lane15)*HG_STRIDE + laneHi*8)*2;
    const int nr  = (lane & 7) + ((lane >> 4) << 3);
    const int kc8 = ((lane >> 3) & 1) * 8;
    const uint32_t bOff = (uint32_t)((wn*32 + nr)*HG_STRIDE + kc8)*2;

    loadA(0,0); loadB(0,0); cp_commit();
    loadA(1,1); loadB(1,1); cp_commit();

    for (int kc=0; kc<4; kc++){
        int st = kc % 3;
        if (kc < 3) cp_wait<1>(); else cp_wait<0>();
        __syncthreads();
        if (kc + 2 < 4){
            loadA(kc+2, (kc+2)%3);
            loadB(kc+2, (kc+2)%3);
            cp_commit();
        }
        const uint32_t aBase = sb + st*HG_BUFB + aOff;
        const uint32_t bBase = sb + (3+st)*HG_BUFB + bOff;
        #pragma unroll
        for (int k16=0; k16<4; k16++){
            uint32_t af[4][4], bf[2][4];
            #pragma unroll
            for (int mi=0; mi<4; mi++)
                ldsm4(af[mi], aBase + (uint32_t)(mi*16*HG_STRIDE + k16*16)*2);
            #pragma unroll
            for (int ni=0; ni<2; ni++)
                ldsm4(bf[ni], bBase + (uint32_t)(ni*16*HG_STRIDE + k16*16)*2);
            #pragma unroll
            for (int mi=0; mi<4; mi++)
                #pragma unroll
                for (int nt=0; nt<4; nt++)
                    mma16816(acc[mi][nt], af[mi], &bf[nt>>1][(nt&1)*2]);
        }
        if (kc < 3) __syncthreads();
    }

    const int g = lane >> 2, q = lane & 3;
    float2 bias2[4];
    #pragma unroll
    for (int nt=0; nt<4; nt++){
        int col = n0 + wn*32 + nt*8 + q*2;
        bias2[nt] = *(const float2*)(bias0 + col);
    }
    #pragma unroll
    for (int mi=0; mi<4; mi++){
        int r0 = m0 + wm*64 + mi*16 + g;
        int r1 = r0 + 8;
        #pragma unroll
        for (int nt=0; nt<4; nt++){
            int col = n0 + wn*32 + nt*8 + q*2;
            if (r0 < MROWS){
                float2 v = make_float2(acc[mi][nt][0] + bias2[nt].x,
                                       acc[mi][nt][1] + bias2[nt].y);
                *(float2*)(C + (size_t)r0*N3 + col) = v;
            }
            if (r1 < MROWS){
                float2 v = make_float2(acc[mi][nt][2] + bias2[nt].x,
                                       acc[mi][nt][3] + bias2[nt].y);
                *(float2*)(C + (size_t)r1*N3 + col) = v;
            }
        }
    }
}

// ---------------- kernel 4: persistent GRU, tensor-core recurrence ----------------
// h lives in global as exact hi/lo fp16 pair; broadcast via pure cp.async.
__global__ __launch_bounds__(256,1) void gru_kernel(
    const float* __restrict__ gbias,
    const int* __restrict__ tok)
{
    extern __shared__ char smg[];
    __half* Ahi = (__half*)smg;                       // [16][AST]
    __half* Alo = (__half*)(smg + 16*AST*2);          // [16][AST]
    float*  sc  = (float*)(smg + 2*16*AST*2);         // [8][16][28]
    const uint32_t sb0 = smem_to_u32(smg);
    const int tid = threadIdx.x, lane = tid & 31, wrp = tid >> 5, bl = blockIdx.x;
    const int g = lane >> 2, tig = lane & 3;

    // one-time B fragments from g_rkTh (fp16 rk^T [3072][1024])
    uint32_t bw[8][3][2];
    #pragma unroll
    for (int j=0;j<8;j++)
        #pragma unroll
        for (int nt=0;nt<3;nt++){
            const __half* base = g_rkTh + (size_t)(nt*UU + bl*8 + g)*UU + wrp*128 + j*16 + 2*tig;
            bw[j][nt][0] = *(const uint32_t*)base;
            bw[j][nt][1] = *(const uint32_t*)(base + 8);
        }

    int eb=0, eu=0, ecol=0;
    float bz=0.f, br=0.f, bh=0.f;
    if (tid < 128){
        eb = tid >> 3; eu = tid & 7; ecol = bl*8 + eu;
        bz = gbias[N3 + ecol];
        br = gbias[N3 + UU + ecol];
        bh = gbias[N3 + 2*UU + ecol];
    }

    for (int t=0; t<TT; t++){
        const int rbuf = t & 1, wbuf = rbuf ^ 1;

        // prefetch epilogue inputs (hide L2 latency)
        float xz=0.f, xr=0.f, xh=0.f; bool msk=false, fl=false;
        if (tid < 128){
            int r = eb*TT + t;
            const float* xp = g_xproj + (size_t)r*N3;
            xz = xp[ecol]; xr = xp[UU+ecol]; xh = xp[2*UU+ecol];
            msk = (tok[eb*256 + t] != 0);
            fl  = (g_flag[r] != 0);
        }

        // broadcast hi/lo h -> SMEM via cp.async (no register round-trip)
        {
            const char* srcH = (const char*)&g_hfp[rbuf][0][0];
            const char* srcL = (const char*)&g_hfp[rbuf][1][0];
            #pragma unroll
            for (int i=0;i<8;i++){
                int idx = tid + i*256;            // 0..2047: b = idx>>7, 16B chunk c = idx&127
                int b = idx >> 7, c = idx & 127;
                cp16(sb0 + (uint32_t)(b*(AST*2) + c*16), srcH + b*2048 + c*16);
                cp16(sb0 + (uint32_t)(16*AST*2 + b*(AST*2) + c*16), srcL + b*2048 + c*16);
            }
            cp_commit(); cp_wait<0>();
        }
        __syncthreads();

        // tensor-core partial rp for this warp's k-slice
        float acc[3][4];
        #pragma unroll
        for (int nt=0;nt<3;nt++)
            #pragma unroll
            for (int p=0;p<4;p++) acc[nt][p] = 0.f;

        #pragma unroll
        for (int ps=0; ps<2; ps++){
            const char* Ab = ps ? (const char*)Alo : (const char*)Ahi;
            #pragma unroll
            for (int j=0;j<8;j++){
                int koff = wrp*128 + j*16;
                uint32_t a[4];
                a[0] = *(const uint32_t*)(Ab + (size_t)(g*AST     + koff + 2*tig    )*2);
                a[1] = *(const uint32_t*)(Ab + (size_t)((g+8)*AST + koff + 2*tig    )*2);
                a[2] = *(const uint32_t*)(Ab + (size_t)(g*AST     + koff + 2*tig + 8)*2);
                a[3] = *(const uint32_t*)(Ab + (size_t)((g+8)*AST + koff + 2*tig + 8)*2);
                #pragma unroll
                for (int nt=0;nt<3;nt++)
                    mma16816(acc[nt], a, bw[j][nt]);
            }
        }

        // store partials: sc[w][batch][col]
        #pragma unroll
        for (int nt=0;nt<3;nt++){
            int c = nt*8 + 2*tig;
            sc[(wrp*16 + g  )*28 + c    ] = acc[nt][0];
            sc[(wrp*16 + g  )*28 + c + 1] = acc[nt][1];
            sc[(wrp*16 + g+8)*28 + c    ] = acc[nt][2];
            sc[(wrp*16 + g+8)*28 + c + 1] = acc[nt][3];
        }
        __syncthreads();

        // gate math + state update
        if (tid < 128){
            float rz = bz, rr = br, rh = bh;
            #pragma unroll
            for (int w=0;w<8;w++){
                const float* p = &sc[(w*16 + eb)*28];
                rz += p[eu]; rr += p[8+eu]; rh += p[16+eu];
            }
            float hold = __half2float(Ahi[eb*AST + ecol]) + __half2float(Alo[eb*AST + ecol]);
            float z  = 1.f/(1.f + __expf(-(xz+rz)));
            float rg = 1.f/(1.f + __expf(-(xr+rr)));
            float hh = tanhf(xh + rg*rh);
            float hn = z*hold + (1.f - z)*hh;
            float hnew = msk ? hn : hold;
            __half nh = __float2half(hnew);
            __half nl = __float2half(hnew - __half2float(nh));
            g_hfp[wbuf][0][eb*UU + ecol] = nh;
            g_hfp[wbuf][1][eb*UU + ecol] = nl;
            g_Ah[(size_t)(eb*TT + t)*UU + ecol] = fl ? nh : __half(0.f);
        }
        grid_barrier();
    }
}

// ---------------- kernel 5: fp16 HMMA output GEMM ----------------
__global__ __launch_bounds__(256,2) void out_hmma(const float* __restrict__ ob,
                                                  float* __restrict__ C){
    extern __shared__ __align__(128) char sm[];
    const uint32_t sb = smem_to_u32(sm);
    const int tid = threadIdx.x, lane = tid & 31, wid = tid >> 5;
    const int m0 = blockIdx.x * 128;
    const int n0 = blockIdx.y * 128;
    const int wm = wid >> 2, wn = wid & 3;

    auto loadA = [&](int kc, int st){
        const __half* gA = g_Ah + (size_t)m0*UU + kc*64;
        uint32_t base = sb + st*HG_BUFB;
        #pragma unroll
        for (int i=0;i<4;i++){
            int idx = tid + i*256;
            int row = idx >> 3, seg = idx & 7;
            cp16(base + (uint32_t)(row*HG_STRIDE + seg*8)*2,
                 gA + (size_t)row*UU + seg*8);
        }
    };
    auto loadB = [&](int kc, int st){
        const __half* gB = g_Wh + (size_t)n0*UU + kc*64;
        uint32_t base = sb + (3+st)*HG_BUFB;
        #pragma unroll
        for (int i=0;i<4;i++){
            int idx = tid + i*256;
            int row = idx >> 3, seg = idx & 7;
            cp16(base + (uint32_t)(row*HG_STRIDE + seg*8)*2,
                 gB + (size_t)row*UU + seg*8);
        }
    };

    float acc[4][4][4];
    #pragma unroll
    for (int i=0;i<4;i++)
        #pragma unroll
        for (int j=0;j<4;j++)
            #pragma unroll
            for (int p=0;p<4;p++) acc[i][j][p] = 0.f;

    const int lane15 = lane & 15, laneHi = lane >> 4;
    const uint32_t aOff = (uint32_t)((wm*64 + lane15)*HG_STRIDE + laneHi*8)*2;
    const int nr  = (lane & 7) + ((lane >> 4) << 3);
    const int kc8 = ((lane >> 3) & 1) * 8;
    const uint32_t bOff = (uint32_t)((wn*32 + nr)*HG_STRIDE + kc8)*2;

    loadA(0,0); loadB(0,0); cp_commit();
    loadA(1,1); loadB(1,1); cp_commit();

    for (int kc=0; kc<16; kc++){
        int st = kc % 3;
        if (kc < 15) cp_wait<1>(); else cp_wait<0>();
        __syncthreads();
        if (kc + 2 < 16){
            loadA(kc+2, (kc+2)%3);
            loadB(kc+2, (kc+2)%3);
            cp_commit();
        }

        const uint32_t aBase = sb + st*HG_BUFB + aOff;
        const uint32_t bBase = sb + (3+st)*HG_BUFB + bOff;
        #pragma unroll
        for (int k16=0; k16<4; k16++){
            uint32_t af[4][4], bf[2][4];
            #pragma unroll
            for (int mi=0; mi<4; mi++)
                ldsm4(af[mi], aBase + (uint32_t)(mi*16*HG_STRIDE + k16*16)*2);
            #pragma unroll
            for (int ni=0; ni<2; ni++)
                ldsm4(bf[ni], bBase + (uint32_t)(ni*16*HG_STRIDE + k16*16)*2);
            #pragma unroll
            for (int mi=0; mi<4; mi++)
                #pragma unroll
                for (int nt=0; nt<4; nt++)
                    mma16816(acc[mi][nt], af[mi], &bf[nt>>1][(nt&1)*2]);
        }
    }

    const int g = lane >> 2, q = lane & 3;
    float2 bias2[4];
    #pragma unroll
    for (int nt=0; nt<4; nt++){
        int col = n0 + wn*32 + nt*8 + q*2;
        bias2[nt] = *(const float2*)(ob + col);
    }
    #pragma unroll
    for (int mi=0; mi<4; mi++){
        int r0 = m0 + wm*64 + mi*16 + g;
        int r1 = r0 + 8;
        #pragma unroll
        for (int nt=0; nt<4; nt++){
            int col = n0 + wn*32 + nt*8 + q*2;
            if (r0 < MROWS){
                float2 v = make_float2(acc[mi][nt][0] + bias2[nt].x,
                                       acc[mi][nt][1] + bias2[nt].y);
                *(float2*)(C + (size_t)r0*VV + col) = v;
            }
            if (r1 < MROWS){
                float2 v = make_float2(acc[mi][nt][2] + bias2[nt].x,
                                       acc[mi][nt][3] + bias2[nt].y);
                *(float2*)(C + (size_t)r1*VV + col) = v;
            }
        }
    }
}

// ---------------- launch ----------------
extern "C" void kernel_launch(void* const* d_in, const int* in_sizes, int n_in,
                              void* d_out, int out_size)
{
    const float* latent = (const float*)d_in[0];
    const int*   tok    = (const int*)d_in[1];
    const float* emb    = (const float*)d_in[2];
    const float* dW     = (const float*)d_in[3];
    const float* db     = (const float*)d_in[4];
    const float* gk     = (const float*)d_in[5];
    const float* grk    = (const float*)d_in[6];
    const float* gb     = (const float*)d_in[7];
    const float* oW     = (const float*)d_in[8];
    const float* ob     = (const float*)d_in[9];
    float* out = (float*)d_out;

    (void)in_sizes; (void)n_in; (void)out_size;

    cudaFuncSetAttribute(gru_kernel, cudaFuncAttributeMaxDynamicSharedMemorySize, GRU_SMEM);
    cudaFuncSetAttribute(out_hmma, cudaFuncAttributeMaxDynamicSharedMemorySize, HG_SMEM);
    cudaFuncSetAttribute(xp_hmma, cudaFuncAttributeMaxDynamicSharedMemorySize, HG_SMEM);

    void *xproj_p = nullptr;
    cudaGetSymbolAddress(&xproj_p, g_xproj);

    // fused prep: tokens/flags, fp16 conversions+transposes, h0
    prep_all<<<PB_TOTAL, 256>>>(latent, dW, db, tok, emb, gk, grk, oW);

    // xproj = emb[tok] @ gru_kernel + gru_bias[0]   (HMMA)
    xp_hmma<<<dim3(MPAD/128, N3/128), 256, HG_SMEM>>>(gb, (float*)xproj_p);

    gru_kernel<<<GRU_BLOCKS, 256, GRU_SMEM>>>(gb, tok);

    // m tiles fastest (blockIdx.x) so co-resident CTAs share the same B panel in L2
    out_hmma<<<dim3(MPAD/128, VV/128), 256, HG_SMEM>>>(ob, out);
}

// round 10
// speedup vs baseline: 2.1413x; 1.1031x over previous
#include <cuda_runtime.h>
#include <cuda_fp16.h>
#include <cstdint>

// Problem constants
#define NB   16          // batch
#define TT   255         // teacher length (T-1)
#define UU   1024        // GRU units
#define VV   32000       // vocab
#define EE   256         // emb dim
#define LATD 512         // latent dim
#define MROWS (NB*TT)    // 4080
#define MPAD 4096
#define N3   (3*UU)      // 3072

#define GRU_BLOCKS 128
#define ASTRIDE 136                          // padded halves per (warp,batch) row
#define AWARP   (16*ASTRIDE)                 // halves per warp slice
#define GRU_SMEM (8*AWARP*2 + 8*16*28*4)     // 34816 + 14336 = 49152

// ---------------- device scratch (no allocs allowed) ----------------
__device__ __align__(128) __half g_hfp[2][NB*UU];     // fp16 hidden state, ping-pong
__device__ float g_xproj[(size_t)MROWS*N3];           // x @ gru_kernel + b0
__device__ __align__(128) __half g_Ah[(size_t)MPAD*UU];   // fp16 GRU outputs (rows>=4080 stay 0)
__device__ __align__(128) __half g_Wh[(size_t)VV*UU];     // fp16 out_W^T  [V][U]
__device__ __align__(128) __half g_embh[(size_t)VV*EE];   // fp16 emb
__device__ __align__(128) __half g_gkT[(size_t)N3*EE];    // fp16 gru_kernel^T [3072][256]
__device__ __align__(128) __half g_rkTh[(size_t)N3*UU];   // fp16 gru_rkernel^T [3072][1024]
__device__ int   g_arow[MROWS];
__device__ unsigned char g_flag[MROWS];
__device__ unsigned int g_bar_cnt = 0;
__device__ unsigned int g_bar_gen = 0;

// ---------------- PTX helpers ----------------
__device__ __forceinline__ uint32_t smem_to_u32(const void* p){
    uint32_t a;
    asm("{ .reg .u64 t; cvta.to.shared.u64 t, %1; cvt.u32.u64 %0, t; }" : "=r"(a) : "l"(p));
    return a;
}
__device__ __forceinline__ void cp16(uint32_t s, const void* g){
    asm volatile("cp.async.cg.shared.global [%0], [%1], 16;" :: "r"(s), "l"(g));
}
__device__ __forceinline__ void cp_commit(){ asm volatile("cp.async.commit_group;" ::: "memory"); }
template<int N> __device__ __forceinline__ void cp_wait(){
    asm volatile("cp.async.wait_group %0;" :: "n"(N) : "memory");
}
__device__ __forceinline__ void ldsm4(uint32_t* r, uint32_t addr){
    asm volatile("ldmatrix.sync.aligned.m8n8.x4.shared.b16 {%0,%1,%2,%3}, [%4];"
        : "=r"(r[0]),"=r"(r[1]),"=r"(r[2]),"=r"(r[3]) : "r"(addr));
}
__device__ __forceinline__ void mma16816(float* c, const uint32_t* a, const uint32_t* b){
    asm volatile("mma.sync.aligned.m16n8k16.row.col.f32.f16.f16.f32 "
        "{%0,%1,%2,%3}, {%4,%5,%6,%7}, {%8,%9}, {%0,%1,%2,%3};"
        : "+f"(c[0]), "+f"(c[1]), "+f"(c[2]), "+f"(c[3])
        : "r"(a[0]), "r"(a[1]), "r"(a[2]), "r"(a[3]), "r"(b[0]), "r"(b[1]));
}

// R5-proven grid barrier: acq_rel atomics on (cnt, gen), thread-0 spin
__device__ __forceinline__ void grid_barrier(){
    __syncthreads();
    if (threadIdx.x == 0){
        unsigned gen, old;
        asm volatile("ld.acquire.gpu.u32 %0, [%1];" : "=r"(gen) : "l"(&g_bar_gen));
        asm volatile("atom.acq_rel.gpu.add.u32 %0, [%1], 1;" : "=r"(old) : "l"(&g_bar_cnt));
        if (old == gridDim.x - 1){
            *(volatile unsigned*)&g_bar_cnt = 0;
            asm volatile("red.release.gpu.add.u32 [%0], 1;" :: "l"(&g_bar_gen));
        } else {
            unsigned g2;
            do {
                asm volatile("ld.acquire.gpu.u32 %0, [%1];" : "=r"(g2) : "l"(&g_bar_gen));
            } while (g2 == gen);
        }
    }
    __syncthreads();
}

// ---------------- fused prep kernel ----------------
#define PB_PREP 1
#define PB_EMB  8000
#define PB_GKT  768
#define PB_H0   64
#define PB_RKT  3072
#define PB_W    32000
#define PB_TOTAL (PB_PREP+PB_EMB+PB_GKT+PB_H0+PB_RKT+PB_W)

__global__ void prep_all(const float* __restrict__ lat, const float* __restrict__ dW,
                         const float* __restrict__ db,  const int* __restrict__ tok,
                         const float* __restrict__ emb, const float* __restrict__ gk,
                         const float* __restrict__ grk, const float* __restrict__ oW){
    __shared__ float tile[32][33];
    int bid = blockIdx.x;
    const int tid = threadIdx.x;
    const int tx = tid & 31, ty = tid >> 5;

    if (bid < PB_PREP){
        if (tid < NB){
            unsigned char f = 0;
            for (int t=0;t<TT;t++){
                f |= (tok[tid*256 + t] != 0) ? 1 : 0;
                g_flag[tid*TT + t] = f;
            }
        }
        for (int m=tid; m<MROWS; m+=256){
            int v = tok[(m/TT)*256 + (m%TT)];
            if (v < 0) v = 0;
            if (v >= VV) v = VV-1;
            g_arow[m] = v;
        }
        return;
    }
    bid -= PB_PREP;

    if (bid < PB_EMB){
        int i = bid*256 + tid;
        float4 v = ((const float4*)emb)[i];
        __half2* dst = (__half2*)g_embh;
        dst[i*2+0] = __floats2half2_rn(v.x, v.y);
        dst[i*2+1] = __floats2half2_rn(v.z, v.w);
        return;
    }
    bid -= PB_EMB;

    if (bid < PB_GKT){
        int n0 = (bid % 96)*32, k0 = (bid / 96)*32;
        #pragma unroll
        for (int i=ty; i<32; i+=8)
            tile[i][tx] = gk[(size_t)(k0+i)*N3 + n0+tx];
        __syncthreads();
        #pragma unroll
        for (int i=ty; i<32; i+=8)
            g_gkT[(size_t)(n0+i)*EE + k0+tx] = __float2half(tile[tx][i]);
        return;
    }
    bid -= PB_GKT;

    if (bid < PB_H0){
        int o = bid*256 + tid;
        int b = o >> 10, u = o & (UU-1);
        float acc = db[u];
        const float* lrow = lat + b*LATD;
        #pragma unroll 8
        for (int k=0;k<LATD;k++) acc = fmaf(lrow[k], dW[(size_t)k*UU + u], acc);
        g_hfp[0][b*UU + u] = __float2half(acc);
        return;
    }
    bid -= PB_H0;

    if (bid < PB_RKT){
        int n0 = (bid % 96)*32, k0 = (bid / 96)*32;
        #pragma unroll
        for (int i=ty; i<32; i+=8)
            tile[i][tx] = grk[(size_t)(k0+i)*N3 + n0+tx];
        __syncthreads();
        #pragma unroll
        for (int i=ty; i<32; i+=8)
            g_rkTh[(size_t)(n0+i)*UU + k0+tx] = __float2half(tile[tx][i]);
        return;
    }
    bid -= PB_RKT;

    {   // convW: transpose out_W [U][V] -> fp16 g_Wh [V][U]
        int n0 = (bid % 1000)*32, k0 = (bid / 1000)*32;
        #pragma unroll
        for (int i=ty; i<32; i+=8)
            tile[i][tx] = oW[(size_t)(k0+i)*VV + n0+tx];
        __syncthreads();
        #pragma unroll
        for (int i=ty; i<32; i+=8)
            g_Wh[(size_t)(n0+i)*UU + k0+tx] = __float2half(tile[tx][i]);
        return;
    }
}

// ---------------- shared HMMA tile constants ----------------
#define HG_STRIDE 72
#define HG_BUFB   (128*HG_STRIDE*2)
#define HG_SMEM   (6*HG_BUFB)

// ---------------- kernel 3: fp16 HMMA xproj GEMM (gathered A) ----------------
__global__ __launch_bounds__(256,2) void xp_hmma(const float* __restrict__ bias0,
                                                 float* __restrict__ C){
    extern __shared__ __align__(128) char sm[];
    const uint32_t sb = smem_to_u32(sm);
    const int tid = threadIdx.x, lane = tid & 31, wid = tid >> 5;
    const int m0 = blockIdx.x * 128;
    const int n0 = blockIdx.y * 128;
    const int wm = wid >> 2, wn = wid & 3;

    const __half* aptr[4];
    int asegs[4];
    #pragma unroll
    for (int i=0;i<4;i++){
        int idx = tid + i*256;
        int row = idx >> 3; asegs[i] = idx & 7;
        int grow = m0 + row;
        int tokv = (grow < MROWS) ? g_arow[grow] : 0;
        aptr[i] = g_embh + (size_t)tokv*EE;
    }
    auto loadA = [&](int kc, int st){
        uint32_t base = sb + st*HG_BUFB;
        #pragma unroll
        for (int i=0;i<4;i++){
            int idx = tid + i*256;
            int row = idx >> 3;
            cp16(base + (uint32_t)(row*HG_STRIDE + asegs[i]*8)*2,
                 aptr[i] + kc*64 + asegs[i]*8);
        }
    };
    auto loadB = [&](int kc, int st){
        const __half* gB = g_gkT + (size_t)n0*EE + kc*64;
        uint32_t base = sb + (3+st)*HG_BUFB;
        #pragma unroll
        for (int i=0;i<4;i++){
            int idx = tid + i*256;
            int row = idx >> 3, seg = idx & 7;
            cp16(base + (uint32_t)(row*HG_STRIDE + seg*8)*2,
                 gB + (size_t)row*EE + seg*8);
        }
    };

    float acc[4][4][4];
    #pragma unroll
    for (int i=0;i<4;i++)
        #pragma unroll
        for (int j=0;j<4;j++)
            #pragma unroll
            for (int p=0;p<4;p++) acc[i][j][p] = 0.f;

    const int lane15 = lane & 15, laneHi = lane >> 4;
    const uint32_t aOff = (uint32_t)((wm*64 + lane15)*HG_STRIDE + laneHi*8)*2;
    const int nr  = (lane & 7) + ((lane >> 4) << 3);
    const int kc8 = ((lane >> 3) & 1) * 8;
    const uint32_t bOff = (uint32_t)((wn*32 + nr)*HG_STRIDE + kc8)*2;

    loadA(0,0); loadB(0,0); cp_commit();
    loadA(1,1); loadB(1,1); cp_commit();

    for (int kc=0; kc<4; kc++){
        int st = kc % 3;
        if (kc < 3) cp_wait<1>(); else cp_wait<0>();
        __syncthreads();
        if (kc + 2 < 4){
            loadA(kc+2, (kc+2)%3);
            loadB(kc+2, (kc+2)%3);
            cp_commit();
        }
        const uint32_t aBase = sb + st*HG_BUFB + aOff;
        const uint32_t bBase = sb + (3+st)*HG_BUFB + bOff;
        #pragma unroll
        for (int k16=0; k16<4; k16++){
            uint32_t af[4][4], bf[2][4];
            #pragma unroll
            for (int mi=0; mi<4; mi++)
                ldsm4(af[mi], aBase + (uint32_t)(mi*16*HG_STRIDE + k16*16)*2);
            #pragma unroll
            for (int ni=0; ni<2; ni++)
                ldsm4(bf[ni], bBase + (uint32_t)(ni*16*HG_STRIDE + k16*16)*2);
            #pragma unroll
            for (int mi=0; mi<4; mi++)
                #pragma unroll
                for (int nt=0; nt<4; nt++)
                    mma16816(acc[mi][nt], af[mi], &bf[nt>>1][(nt&1)*2]);
        }
        if (kc < 3) __syncthreads();
    }

    const int g = lane >> 2, q = lane & 3;
    float2 bias2[4];
    #pragma unroll
    for (int nt=0; nt<4; nt++){
        int col = n0 + wn*32 + nt*8 + q*2;
        bias2[nt] = *(const float2*)(bias0 + col);
    }
    #pragma unroll
    for (int mi=0; mi<4; mi++){
        int r0 = m0 + wm*64 + mi*16 + g;
        int r1 = r0 + 8;
        #pragma unroll
        for (int nt=0; nt<4; nt++){
            int col = n0 + wn*32 + nt*8 + q*2;
            if (r0 < MROWS){
                float2 v = make_float2(acc[mi][nt][0] + bias2[nt].x,
                                       acc[mi][nt][1] + bias2[nt].y);
                *(float2*)(C + (size_t)r0*N3 + col) = v;
            }
            if (r1 < MROWS){
                float2 v = make_float2(acc[mi][nt][2] + bias2[nt].x,
                                       acc[mi][nt][3] + bias2[nt].y);
                *(float2*)(C + (size_t)r1*N3 + col) = v;
            }
        }
    }
}

// ---------------- kernel 4: persistent GRU, tensor-core recurrence (fp16 h, per-warp slices) ----------------
__global__ __launch_bounds__(256,1) void gru_kernel(
    const float* __restrict__ gbias,
    const int* __restrict__ tok)
{
    extern __shared__ char smg[];
    __half* Ah = (__half*)smg;                        // [8 warps][16 batches][ASTRIDE]
    float*  sc = (float*)(smg + 8*AWARP*2);           // [8][16][28]
    const uint32_t sb0 = smem_to_u32(smg);
    const int tid = threadIdx.x, lane = tid & 31, wrp = tid >> 5, bl = blockIdx.x;
    const int g = lane >> 2, tig = lane & 3;

    // one-time B fragments from g_rkTh (fp16 rk^T [3072][1024])
    uint32_t bw[8][3][2];
    #pragma unroll
    for (int j=0;j<8;j++)
        #pragma unroll
        for (int nt=0;nt<3;nt++){
            const __half* base = g_rkTh + (size_t)(nt*UU + bl*8 + g)*UU + wrp*128 + j*16 + 2*tig;
            bw[j][nt][0] = *(const uint32_t*)base;
            bw[j][nt][1] = *(const uint32_t*)(base + 8);
        }

    int eb=0, eu=0, ecol=0;
    float bz=0.f, br=0.f, bh=0.f;
    uint32_t holdOff = 0;
    if (tid < 128){
        eb = tid >> 3; eu = tid & 7; ecol = bl*8 + eu;
        bz = gbias[N3 + ecol];
        br = gbias[N3 + UU + ecol];
        bh = gbias[N3 + 2*UU + ecol];
        holdOff = (uint32_t)(((ecol >> 7)*16 + eb)*ASTRIDE + (ecol & 127));
    }

    const uint32_t wbase = sb0 + wrp*AWARP*2;

    for (int t=0; t<TT; t++){
        const int rbuf = t & 1, wbuf = rbuf ^ 1;

        // prefetch epilogue inputs (hide L2 latency)
        float xz=0.f, xr=0.f, xh=0.f; bool msk=false, fl=false;
        if (tid < 128){
            int r = eb*TT + t;
            const float* xp = g_xproj + (size_t)r*N3;
            xz = xp[ecol]; xr = xp[UU+ecol]; xh = xp[2*UU+ecol];
            msk = (tok[eb*256 + t] != 0);
            fl  = (g_flag[r] != 0);
        }

        // per-warp slice broadcast: warp wrp loads k in [wrp*128, wrp*128+128) for all 16 batches
        {
            const char* srcH = (const char*)&g_hfp[rbuf][0] + wrp*256;
            #pragma unroll
            for (int i=0;i<8;i++){
                int idx = lane + 32*i;             // 0..255: b = idx>>4, 16B chunk c = idx&15
                int b = idx >> 4, c = idx & 15;
                cp16(wbase + (uint32_t)(b*ASTRIDE*2 + c*16), srcH + b*2048 + c*16);
            }
            cp_commit(); cp_wait<0>();
            __syncwarp();
        }

        // tensor-core partial rp for this warp's k-slice
        float acc[3][4];
        #pragma unroll
        for (int nt=0;nt<3;nt++)
            #pragma unroll
            for (int p=0;p<4;p++) acc[nt][p] = 0.f;

        const char* Ab = (const char*)smg + wrp*AWARP*2;
        #pragma unroll
        for (int j=0;j<8;j++){
            int koff = j*16 + 2*tig;
            uint32_t a[4];
            a[0] = *(const uint32_t*)(Ab + (size_t)(g*ASTRIDE     + koff    )*2);
            a[1] = *(const uint32_t*)(Ab + (size_t)((g+8)*ASTRIDE + koff    )*2);
            a[2] = *(const uint32_t*)(Ab + (size_t)(g*ASTRIDE     + koff + 8)*2);
            a[3] = *(const uint32_t*)(Ab + (size_t)((g+8)*ASTRIDE + koff + 8)*2);
            #pragma unroll
            for (int nt=0;nt<3;nt++)
                mma16816(acc[nt], a, bw[j][nt]);
        }

        // store partials: sc[w][batch][col]
        #pragma unroll
        for (int nt=0;nt<3;nt++){
            int c = nt*8 + 2*tig;
            sc[(wrp*16 + g  )*28 + c    ] = acc[nt][0];
            sc[(wrp*16 + g  )*28 + c + 1] = acc[nt][1];
            sc[(wrp*16 + g+8)*28 + c    ] = acc[nt][2];
            sc[(wrp*16 + g+8)*28 + c + 1] = acc[nt][3];
        }
        __syncthreads();

        // gate math + state update
        if (tid < 128){
            float rz = bz, rr = br, rh = bh;
            #pragma unroll
            for (int w=0;w<8;w++){
                const float* p = &sc[(w*16 + eb)*28];
                rz += p[eu]; rr += p[8+eu]; rh += p[16+eu];
            }
            float hold = __half2float(Ah[holdOff]);
            float z  = 1.f/(1.f + __expf(-(xz+rz)));
            float rg = 1.f/(1.f + __expf(-(xr+rr)));
            float hh = tanhf(xh + rg*rh);
            float hn = z*hold + (1.f - z)*hh;
            float hnew = msk ? hn : hold;
            __half nh = __float2half(hnew);
            g_hfp[wbuf][eb*UU + ecol] = nh;
            g_Ah[(size_t)(eb*TT + t)*UU + ecol] = fl ? nh : __half(0.f);
        }
        grid_barrier();
    }
}

// ---------------- kernel 5: fp16 HMMA output GEMM ----------------
__global__ __launch_bounds__(256,2) void out_hmma(const float* __restrict__ ob,
                                                  float* __restrict__ C){
    extern __shared__ __align__(128) char sm[];
    const uint32_t sb = smem_to_u32(sm);
    const int tid = threadIdx.x, lane = tid & 31, wid = tid >> 5;
    const int m0 = blockIdx.x * 128;
    const int n0 = blockIdx.y * 128;
    const int wm = wid >> 2, wn = wid & 3;

    auto loadA = [&](int kc, int st){
        const __half* gA = g_Ah + (size_t)m0*UU + kc*64;
        uint32_t base = sb + st*HG_BUFB;
        #pragma unroll
        for (int i=0;i<4;i++){
            int idx = tid + i*256;
            int row = idx >> 3, seg = idx & 7;
            cp16(base + (uint32_t)(row*HG_STRIDE + seg*8)*2,
                 gA + (size_t)row*UU + seg*8);
        }
    };
    auto loadB = [&](int kc, int st){
        const __half* gB = g_Wh + (size_t)n0*UU + kc*64;
        uint32_t base = sb + (3+st)*HG_BUFB;
        #pragma unroll
        for (int i=0;i<4;i++){
            int idx = tid + i*256;
            int row = idx >> 3, seg = idx & 7;
            cp16(base + (uint32_t)(row*HG_STRIDE + seg*8)*2,
                 gB + (size_t)row*UU + seg*8);
        }
    };

    float acc[4][4][4];
    #pragma unroll
    for (int i=0;i<4;i++)
        #pragma unroll
        for (int j=0;j<4;j++)
            #pragma unroll
            for (int p=0;p<4;p++) acc[i][j][p] = 0.f;

    const int lane15 = lane & 15, laneHi = lane >> 4;
    const uint32_t aOff = (uint32_t)((wm*64 + lane15)*HG_STRIDE + laneHi*8)*2;
    const int nr  = (lane & 7) + ((lane >> 4) << 3);
    const int kc8 = ((lane >> 3) & 1) * 8;
    const uint32_t bOff = (uint32_t)((wn*32 + nr)*HG_STRIDE + kc8)*2;

    loadA(0,0); loadB(0,0); cp_commit();
    loadA(1,1); loadB(1,1); cp_commit();

    for (int kc=0; kc<16; kc++){
        int st = kc % 3;
        if (kc < 15) cp_wait<1>(); else cp_wait<0>();
        __syncthreads();
        if (kc + 2 < 16){
            loadA(kc+2, (kc+2)%3);
            loadB(kc+2, (kc+2)%3);
            cp_commit();
        }

        const uint32_t aBase = sb + st*HG_BUFB + aOff;
        const uint32_t bBase = sb + (3+st)*HG_BUFB + bOff;
        #pragma unroll
        for (int k16=0; k16<4; k16++){
            uint32_t af[4][4], bf[2][4];
            #pragma unroll
            for (int mi=0; mi<4; mi++)
                ldsm4(af[mi], aBase + (uint32_t)(mi*16*HG_STRIDE + k16*16)*2);
            #pragma unroll
            for (int ni=0; ni<2; ni++)
                ldsm4(bf[ni], bBase + (uint32_t)(ni*16*HG_STRIDE + k16*16)*2);
            #pragma unroll
            for (int mi=0; mi<4; mi++)
                #pragma unroll
                for (int nt=0; nt<4; nt++)
                    mma16816(acc[mi][nt], af[mi], &bf[nt>>1][(nt&1)*2]);
        }
    }

    const int g = lane >> 2, q = lane & 3;
    float2 bias2[4];
    #pragma unroll
    for (int nt=0; nt<4; nt++){
        int col = n0 + wn*32 + nt*8 + q*2;
        bias2[nt] = *(const float2*)(ob + col);
    }
    #pragma unroll
    for (int mi=0; mi<4; mi++){
        int r0 = m0 + wm*64 + mi*16 + g;
        int r1 = r0 + 8;
        #pragma unroll
        for (int nt=0; nt<4; nt++){
            int col = n0 + wn*32 + nt*8 + q*2;
            if (r0 < MROWS){
                float2 v = make_float2(acc[mi][nt][0] + bias2[nt].x,
                                       acc[mi][nt][1] + bias2[nt].y);
                *(float2*)(C + (size_t)r0*VV + col) = v;
            }
            if (r1 < MROWS){
                float2 v = make_float2(acc[mi][nt][2] + bias2[nt].x,
                                       acc[mi][nt][3] + bias2[nt].y);
                *(float2*)(C + (size_t)r1*VV + col) = v;
            }
        }
    }
}

// ---------------- launch ----------------
extern "C" void kernel_launch(void* const* d_in, const int* in_sizes, int n_in,
                              void* d_out, int out_size)
{
    const float* latent = (const float*)d_in[0];
    const int*   tok    = (const int*)d_in[1];
    const float* emb    = (const float*)d_in[2];
    const float* dW     = (const float*)d_in[3];
    const float* db     = (const float*)d_in[4];
    const float* gk     = (const float*)d_in[5];
    const float* grk    = (const float*)d_in[6];
    const float* gb     = (const float*)d_in[7];
    const float* oW     = (const float*)d_in[8];
    const float* ob     = (const float*)d_in[9];
    float* out = (float*)d_out;

    (void)in_sizes; (void)n_in; (void)out_size;

    cudaFuncSetAttribute(gru_kernel, cudaFuncAttributeMaxDynamicSharedMemorySize, GRU_SMEM);
    cudaFuncSetAttribute(out_hmma, cudaFuncAttributeMaxDynamicSharedMemorySize, HG_SMEM);
    cudaFuncSetAttribute(xp_hmma, cudaFuncAttributeMaxDynamicSharedMemorySize, HG_SMEM);

    void *xproj_p = nullptr;
    cudaGetSymbolAddress(&xproj_p, g_xproj);

    // fused prep: tokens/flags, fp16 conversions+transposes, h0
    prep_all<<<PB_TOTAL, 256>>>(latent, dW, db, tok, emb, gk, grk, oW);

    // xproj = emb[tok] @ gru_kernel + gru_bias[0]   (HMMA)
    xp_hmma<<<dim3(MPAD/128, N3/128), 256, HG_SMEM>>>(gb, (float*)xproj_p);

    gru_kernel<<<GRU_BLOCKS, 256, GRU_SMEM>>>(gb, tok);

    // m tiles fastest (blockIdx.x) so co-resident CTAs share the same B panel in L2
    out_hmma<<<dim3(MPAD/128, VV/128), 256, HG_SMEM>>>(ob, out);
}

// round 11
// speedup vs baseline: 2.2252x; 1.0392x over previous
#include <cuda_runtime.h>
#include <cuda_fp16.h>
#include <cstdint>

// Problem constants
#define NB   16          // batch
#define TT   255         // teacher length (T-1)
#define UU   1024        // GRU units
#define VV   32000       // vocab
#define EE   256         // emb dim
#define LATD 512         // latent dim
#define MROWS (NB*TT)    // 4080
#define MPAD 4096
#define N3   (3*UU)      // 3072

#define GRU_BLOCKS 128
#define ASTRIDE 136                          // padded halves per (warp,batch) row
#define AWARP   (16*ASTRIDE)                 // halves per warp slice
#define GRU_SMEM (8*AWARP*2 + 8*16*28*4)     // 34816 + 14336 = 49152

// ---------------- device scratch (no allocs allowed) ----------------
__device__ __align__(128) __half g_hfp[2][NB*UU];     // fp16 hidden state, ping-pong
__device__ float g_xproj[(size_t)MROWS*N3];           // x @ gru_kernel + b0
__device__ __align__(128) __half g_Ah[(size_t)MPAD*UU];   // fp16 GRU outputs (rows>=4080 stay 0)
__device__ __align__(128) __half g_Wh[(size_t)VV*UU];     // fp16 out_W^T  [V][U]
__device__ __align__(128) __half g_embh[(size_t)VV*EE];   // fp16 emb
__device__ __align__(128) __half g_gkT[(size_t)N3*EE];    // fp16 gru_kernel^T [3072][256]
__device__ __align__(128) __half g_rkTh[(size_t)N3*UU];   // fp16 gru_rkernel^T [3072][1024]
__device__ int   g_arow[MROWS];
__device__ unsigned char g_flag[MROWS];
__device__ __align__(256) unsigned g_cnt8[8][64];     // two-level barrier counters (256B apart)

// ---------------- PTX helpers ----------------
__device__ __forceinline__ uint32_t smem_to_u32(const void* p){
    uint32_t a;
    asm("{ .reg .u64 t; cvta.to.shared.u64 t, %1; cvt.u32.u64 %0, t; }" : "=r"(a) : "l"(p));
    return a;
}
__device__ __forceinline__ void cp16(uint32_t s, const void* g){
    asm volatile("cp.async.cg.shared.global [%0], [%1], 16;" :: "r"(s), "l"(g));
}
__device__ __forceinline__ void cp_commit(){ asm volatile("cp.async.commit_group;" ::: "memory"); }
template<int N> __device__ __forceinline__ void cp_wait(){
    asm volatile("cp.async.wait_group %0;" :: "n"(N) : "memory");
}
__device__ __forceinline__ void ldsm4(uint32_t* r, uint32_t addr){
    asm volatile("ldmatrix.sync.aligned.m8n8.x4.shared.b16 {%0,%1,%2,%3}, [%4];"
        : "=r"(r[0]),"=r"(r[1]),"=r"(r[2]),"=r"(r[3]) : "r"(addr));
}
__device__ __forceinline__ void mma16816(float* c, const uint32_t* a, const uint32_t* b){
    asm volatile("mma.sync.aligned.m16n8k16.row.col.f32.f16.f16.f32 "
        "{%0,%1,%2,%3}, {%4,%5,%6,%7}, {%8,%9}, {%0,%1,%2,%3};"
        : "+f"(c[0]), "+f"(c[1]), "+f"(c[2]), "+f"(c[3])
        : "r"(a[0]), "r"(a[1]), "r"(a[2]), "r"(a[3]), "r"(b[0]), "r"(b[1]));
}

// two-level grid barrier: 8 counters (16 CTAs each), threads 0-7 spin one counter each.
__device__ __forceinline__ void gru_barrier2(int bl, int t){
    __syncthreads();
    if (threadIdx.x == 0){
        asm volatile("red.release.gpu.add.u32 [%0], 1;" :: "l"(&g_cnt8[bl & 7][0]) : "memory");
    }
    if (threadIdx.x < 8){
        unsigned target = 16u*(unsigned)(t+1);
        const unsigned* p = &g_cnt8[threadIdx.x][0];
        unsigned v;
        do {
            asm volatile("ld.acquire.gpu.u32 %0, [%1];" : "=r"(v) : "l"(p) : "memory");
        } while (v < target);
    }
    __syncthreads();
}

__global__ void bar_reset(){
    if (threadIdx.x < 8) g_cnt8[threadIdx.x][0] = 0;
}

// ---------------- fused prep kernel ----------------
#define PB_PREP 1
#define PB_EMB  8000
#define PB_GKT  768
#define PB_H0   64
#define PB_RKT  3072
#define PB_W    32000
#define PB_TOTAL (PB_PREP+PB_EMB+PB_GKT+PB_H0+PB_RKT+PB_W)

__global__ void prep_all(const float* __restrict__ lat, const float* __restrict__ dW,
                         const float* __restrict__ db,  const int* __restrict__ tok,
                         const float* __restrict__ emb, const float* __restrict__ gk,
                         const float* __restrict__ grk, const float* __restrict__ oW){
    __shared__ float tile[32][33];
    int bid = blockIdx.x;
    const int tid = threadIdx.x;
    const int tx = tid & 31, ty = tid >> 5;

    if (bid < PB_PREP){
        if (tid < NB){
            unsigned char f = 0;
            for (int t=0;t<TT;t++){
                f |= (tok[tid*256 + t] != 0) ? 1 : 0;
                g_flag[tid*TT + t] = f;
            }
        }
        for (int m=tid; m<MROWS; m+=256){
            int v = tok[(m/TT)*256 + (m%TT)];
            if (v < 0) v = 0;
            if (v >= VV) v = VV-1;
            g_arow[m] = v;
        }
        return;
    }
    bid -= PB_PREP;

    if (bid < PB_EMB){
        int i = bid*256 + tid;
        float4 v = ((const float4*)emb)[i];
        __half2* dst = (__half2*)g_embh;
        dst[i*2+0] = __floats2half2_rn(v.x, v.y);
        dst[i*2+1] = __floats2half2_rn(v.z, v.w);
        return;
    }
    bid -= PB_EMB;

    if (bid < PB_GKT){
        int n0 = (bid % 96)*32, k0 = (bid / 96)*32;
        #pragma unroll
        for (int i=ty; i<32; i+=8)
            tile[i][tx] = gk[(size_t)(k0+i)*N3 + n0+tx];
        __syncthreads();
        #pragma unroll
        for (int i=ty; i<32; i+=8)
            g_gkT[(size_t)(n0+i)*EE + k0+tx] = __float2half(tile[tx][i]);
        return;
    }
    bid -= PB_GKT;

    if (bid < PB_H0){
        int o = bid*256 + tid;
        int b = o >> 10, u = o & (UU-1);
        float acc = db[u];
        const float* lrow = lat + b*LATD;
        #pragma unroll 8
        for (int k=0;k<LATD;k++) acc = fmaf(lrow[k], dW[(size_t)k*UU + u], acc);
        g_hfp[0][b*UU + u] = __float2half(acc);
        return;
    }
    bid -= PB_H0;

    if (bid < PB_RKT){
        int n0 = (bid % 96)*32, k0 = (bid / 96)*32;
        #pragma unroll
        for (int i=ty; i<32; i+=8)
            tile[i][tx] = grk[(size_t)(k0+i)*N3 + n0+tx];
        __syncthreads();
        #pragma unroll
        for (int i=ty; i<32; i+=8)
            g_rkTh[(size_t)(n0+i)*UU + k0+tx] = __float2half(tile[tx][i]);
        return;
    }
    bid -= PB_RKT;

    {   // convW: transpose out_W [U][V] -> fp16 g_Wh [V][U]
        int n0 = (bid % 1000)*32, k0 = (bid / 1000)*32;
        #pragma unroll
        for (int i=ty; i<32; i+=8)
            tile[i][tx] = oW[(size_t)(k0+i)*VV + n0+tx];
        __syncthreads();
        #pragma unroll
        for (int i=ty; i<32; i+=8)
            g_Wh[(size_t)(n0+i)*UU + k0+tx] = __float2half(tile[tx][i]);
        return;
    }
}

// ---------------- xp tile constants (128x128) ----------------
#define HG_STRIDE 72
#define HG_BUFB   (128*HG_STRIDE*2)
#define HG_SMEM   (6*HG_BUFB)

// ---------------- kernel 3: fp16 HMMA xproj GEMM (gathered A) ----------------
__global__ __launch_bounds__(256,2) void xp_hmma(const float* __restrict__ bias0,
                                                 float* __restrict__ C){
    extern __shared__ __align__(128) char sm[];
    const uint32_t sb = smem_to_u32(sm);
    const int tid = threadIdx.x, lane = tid & 31, wid = tid >> 5;
    const int m0 = blockIdx.x * 128;
    const int n0 = blockIdx.y * 128;
    const int wm = wid >> 2, wn = wid & 3;

    const __half* aptr[4];
    int asegs[4];
    #pragma unroll
    for (int i=0;i<4;i++){
        int idx = tid + i*256;
        int row = idx >> 3; asegs[i] = idx & 7;
        int grow = m0 + row;
        int tokv = (grow < MROWS) ? g_arow[grow] : 0;
        aptr[i] = g_embh + (size_t)tokv*EE;
    }
    auto loadA = [&](int kc, int st){
        uint32_t base = sb + st*HG_BUFB;
        #pragma unroll
        for (int i=0;i<4;i++){
            int idx = tid + i*256;
            int row = idx >> 3;
            cp16(base + (uint32_t)(row*HG_STRIDE + asegs[i]*8)*2,
                 aptr[i] + kc*64 + asegs[i]*8);
        }
    };
    auto loadB = [&](int kc, int st){
        const __half* gB = g_gkT + (size_t)n0*EE + kc*64;
        uint32_t base = sb + (3+st)*HG_BUFB;
        #pragma unroll
        for (int i=0;i<4;i++){
            int idx = tid + i*256;
            int row = idx >> 3, seg = idx & 7;
            cp16(base + (uint32_t)(row*HG_STRIDE + seg*8)*2,
                 gB + (size_t)row*EE + seg*8);
        }
    };

    float acc[4][4][4];
    #pragma unroll
    for (int i=0;i<4;i++)
        #pragma unroll
        for (int j=0;j<4;j++)
            #pragma unroll
            for (int p=0;p<4;p++) acc[i][j][p] = 0.f;

    const int lane15 = lane & 15, laneHi = lane >> 4;
    const uint32_t aOff = (uint32_t)((wm*64 + lane15)*HG_STRIDE + laneHi*8)*2;
    const int nr  = (lane & 7) + ((lane >> 4) << 3);
    const int kc8 = ((lane >> 3) & 1) * 8;
    const uint32_t bOff = (uint32_t)((wn*32 + nr)*HG_STRIDE + kc8)*2;

    loadA(0,0); loadB(0,0); cp_commit();
    loadA(1,1); loadB(1,1); cp_commit();

    for (int kc=0; kc<4; kc++){
        int st = kc % 3;
        if (kc < 3) cp_wait<1>(); else cp_wait<0>();
        __syncthreads();
        if (kc + 2 < 4){
            loadA(kc+2, (kc+2)%3);
            loadB(kc+2, (kc+2)%3);
            cp_commit();
        }
        const uint32_t aBase = sb + st*HG_BUFB + aOff;
        const uint32_t bBase = sb + (3+st)*HG_BUFB + bOff;
        #pragma unroll
        for (int k16=0; k16<4; k16++){
            uint32_t af[4][4], bf[2][4];
            #pragma unroll
            for (int mi=0; mi<4; mi++)
                ldsm4(af[mi], aBase + (uint32_t)(mi*16*HG_STRIDE + k16*16)*2);
            #pragma unroll
            for (int ni=0; ni<2; ni++)
                ldsm4(bf[ni], bBase + (uint32_t)(ni*16*HG_STRIDE + k16*16)*2);
            #pragma unroll
            for (int mi=0; mi<4; mi++)
                #pragma unroll
                for (int nt=0; nt<4; nt++)
                    mma16816(acc[mi][nt], af[mi], &bf[nt>>1][(nt&1)*2]);
        }
        if (kc < 3) __syncthreads();
    }

    const int g = lane >> 2, q = lane & 3;
    float2 bias2[4];
    #pragma unroll
    for (int nt=0; nt<4; nt++){
        int col = n0 + wn*32 + nt*8 + q*2;
        bias2[nt] = *(const float2*)(bias0 + col);
    }
    #pragma unroll
    for (int mi=0; mi<4; mi++){
        int r0 = m0 + wm*64 + mi*16 + g;
        int r1 = r0 + 8;
        #pragma unroll
        for (int nt=0; nt<4; nt++){
            int col = n0 + wn*32 + nt*8 + q*2;
            if (r0 < MROWS){
                float2 v = make_float2(acc[mi][nt][0] + bias2[nt].x,
                                       acc[mi][nt][1] + bias2[nt].y);
                *(float2*)(C + (size_t)r0*N3 + col) = v;
            }
            if (r1 < MROWS){
                float2 v = make_float2(acc[mi][nt][2] + bias2[nt].x,
                                       acc[mi][nt][3] + bias2[nt].y);
                *(float2*)(C + (size_t)r1*N3 + col) = v;
            }
        }
    }
}

// ---------------- kernel 4: persistent GRU, tensor-core recurrence ----------------
__global__ __launch_bounds__(256,1) void gru_kernel(
    const float* __restrict__ gbias,
    const int* __restrict__ tok)
{
    extern __shared__ char smg[];
    __half* Ah = (__half*)smg;                        // [8 warps][16 batches][ASTRIDE]
    float*  sc = (float*)(smg + 8*AWARP*2);           // [8][16][28]
    const uint32_t sb0 = smem_to_u32(smg);
    const int tid = threadIdx.x, lane = tid & 31, wrp = tid >> 5, bl = blockIdx.x;
    const int g = lane >> 2, tig = lane & 3;

    // one-time B fragments from g_rkTh (fp16 rk^T [3072][1024])
    uint32_t bw[8][3][2];
    #pragma unroll
    for (int j=0;j<8;j++)
        #pragma unroll
        for (int nt=0;nt<3;nt++){
            const __half* base = g_rkTh + (size_t)(nt*UU + bl*8 + g)*UU + wrp*128 + j*16 + 2*tig;
            bw[j][nt][0] = *(const uint32_t*)base;
            bw[j][nt][1] = *(const uint32_t*)(base + 8);
        }

    int eb=0, eu=0, ecol=0;
    float bz=0.f, br=0.f, bh=0.f;
    uint32_t holdOff = 0;
    if (tid < 128){
        eb = tid >> 3; eu = tid & 7; ecol = bl*8 + eu;
        bz = gbias[N3 + ecol];
        br = gbias[N3 + UU + ecol];
        bh = gbias[N3 + 2*UU + ecol];
        holdOff = (uint32_t)(((ecol >> 7)*16 + eb)*ASTRIDE + (ecol & 127));
    }

    const uint32_t wbase = sb0 + wrp*AWARP*2;

    for (int t=0; t<TT; t++){
        const int rbuf = t & 1, wbuf = rbuf ^ 1;

        // prefetch epilogue inputs (hide L2 latency)
        float xz=0.f, xr=0.f, xh=0.f; bool msk=false, fl=false;
        if (tid < 128){
            int r = eb*TT + t;
            const float* xp = g_xproj + (size_t)r*N3;
            xz = xp[ecol]; xr = xp[UU+ecol]; xh = xp[2*UU+ecol];
            msk = (tok[eb*256 + t] != 0);
            fl  = (g_flag[r] != 0);
        }

        // per-warp slice broadcast: warp wrp loads k in [wrp*128, wrp*128+128) for all 16 batches
        {
            const char* srcH = (const char*)&g_hfp[rbuf][0] + wrp*256;
            #pragma unroll
            for (int i=0;i<8;i++){
                int idx = lane + 32*i;             // 0..255: b = idx>>4, 16B chunk c = idx&15
                int b = idx >> 4, c = idx & 15;
                cp16(wbase + (uint32_t)(b*ASTRIDE*2 + c*16), srcH + b*2048 + c*16);
            }
            cp_commit(); cp_wait<0>();
            __syncwarp();
        }

        // tensor-core partial rp for this warp's k-slice
        float acc[3][4];
        #pragma unroll
        for (int nt=0;nt<3;nt++)
            #pragma unroll
            for (int p=0;p<4;p++) acc[nt][p] = 0.f;

        const char* Ab = (const char*)smg + wrp*AWARP*2;
        #pragma unroll
        for (int j=0;j<8;j++){
            int koff = j*16 + 2*tig;
            uint32_t a[4];
            a[0] = *(const uint32_t*)(Ab + (size_t)(g*ASTRIDE     + koff    )*2);
            a[1] = *(const uint32_t*)(Ab + (size_t)((g+8)*ASTRIDE + koff    )*2);
            a[2] = *(const uint32_t*)(Ab + (size_t)(g*ASTRIDE     + koff + 8)*2);
            a[3] = *(const uint32_t*)(Ab + (size_t)((g+8)*ASTRIDE + koff + 8)*2);
            #pragma unroll
            for (int nt=0;nt<3;nt++)
                mma16816(acc[nt], a, bw[j][nt]);
        }

        // store partials: sc[w][batch][col]
        #pragma unroll
        for (int nt=0;nt<3;nt++){
            int c = nt*8 + 2*tig;
            sc[(wrp*16 + g  )*28 + c    ] = acc[nt][0];
            sc[(wrp*16 + g  )*28 + c + 1] = acc[nt][1];
            sc[(wrp*16 + g+8)*28 + c    ] = acc[nt][2];
            sc[(wrp*16 + g+8)*28 + c + 1] = acc[nt][3];
        }
        __syncthreads();

        // gate math + state update
        if (tid < 128){
            float rz = bz, rr = br, rh = bh;
            #pragma unroll
            for (int w=0;w<8;w++){
                const float* p = &sc[(w*16 + eb)*28];
                rz += p[eu]; rr += p[8+eu]; rh += p[16+eu];
            }
            float hold = __half2float(Ah[holdOff]);
            float z  = 1.f/(1.f + __expf(-(xz+rz)));
            float rg = 1.f/(1.f + __expf(-(xr+rr)));
            float hh = tanhf(xh + rg*rh);
            float hn = z*hold + (1.f - z)*hh;
            float hnew = msk ? hn : hold;
            __half nh = __float2half(hnew);
            g_hfp[wbuf][eb*UU + ecol] = nh;
            g_Ah[(size_t)(eb*TT + t)*UU + ecol] = fl ? nh : __half(0.f);
        }
        gru_barrier2(bl, t);
    }
}

// ---------------- kernel 5: fp16 HMMA output GEMM (CTA 128x256, warp 64x64) ----------------
#define OG_ABUF (128*HG_STRIDE*2)         // 18432
#define OG_BBUF (256*HG_STRIDE*2)         // 36864
#define OG_SMEM (3*OG_ABUF + 3*OG_BBUF)   // 165888

__global__ __launch_bounds__(256,1) void out_hmma(const float* __restrict__ ob,
                                                  float* __restrict__ C){
    extern __shared__ __align__(128) char sm[];
    const uint32_t sb = smem_to_u32(sm);
    const int tid = threadIdx.x, lane = tid & 31, wid = tid >> 5;
    const int m0 = blockIdx.x * 128;
    const int n0 = blockIdx.y * 256;
    const int wm = wid >> 2, wn = wid & 3;     // 2m x 4n warps, 64x64 tiles

    auto loadA = [&](int kc, int st){
        const __half* gA = g_Ah + (size_t)m0*UU + kc*64;
        uint32_t base = sb + st*OG_ABUF;
        #pragma unroll
        for (int i=0;i<4;i++){
            int idx = tid + i*256;             // 0..1023: 128 rows x 8 segs
            int row = idx >> 3, seg = idx & 7;
            cp16(base + (uint32_t)(row*HG_STRIDE + seg*8)*2,
                 gA + (size_t)row*UU + seg*8);
        }
    };
    auto loadB = [&](int kc, int st){
        const __half* gB = g_Wh + (size_t)n0*UU + kc*64;
        uint32_t base = sb + 3*OG_ABUF + st*OG_BBUF;
        #pragma unroll
        for (int i=0;i<8;i++){
            int idx = tid + i*256;             // 0..2047: 256 rows x 8 segs
            int row = idx >> 3, seg = idx & 7;
            cp16(base + (uint32_t)(row*HG_STRIDE + seg*8)*2,
                 gB + (size_t)row*UU + seg*8);
        }
    };

    float acc[4][8][4];
    #pragma unroll
    for (int i=0;i<4;i++)
        #pragma unroll
        for (int j=0;j<8;j++)
            #pragma unroll
            for (int p=0;p<4;p++) acc[i][j][p] = 0.f;

    const int lane15 = lane & 15, laneHi = lane >> 4;
    const uint32_t aOff = (uint32_t)((wm*64 + lane15)*HG_STRIDE + laneHi*8)*2;
    const int nr  = (lane & 7) + ((lane >> 4) << 3);
    const int kc8 = ((lane >> 3) & 1) * 8;
    const uint32_t bOff = (uint32_t)((wn*64 + nr)*HG_STRIDE + kc8)*2;

    loadA(0,0); loadB(0,0); cp_commit();
    loadA(1,1); loadB(1,1); cp_commit();

    for (int kc=0; kc<16; kc++){
        int st = kc % 3;
        if (kc < 15) cp_wait<1>(); else cp_wait<0>();
        __syncthreads();
        if (kc + 2 < 16){
            loadA(kc+2, (kc+2)%3);
            loadB(kc+2, (kc+2)%3);
            cp_commit();
        }

        const uint32_t aBase = sb + st*OG_ABUF + aOff;
        const uint32_t bBase = sb + 3*OG_ABUF + st*OG_BBUF + bOff;
        #pragma unroll
        for (int k16=0; k16<4; k16++){
            uint32_t af[4][4], bf[4][4];
            #pragma unroll
            for (int mi=0; mi<4; mi++)
                ldsm4(af[mi], aBase + (uint32_t)(mi*16*HG_STRIDE + k16*16)*2);
            #pragma unroll
            for (int ni=0; ni<4; ni++)
                ldsm4(bf[ni], bBase + (uint32_t)(ni*16*HG_STRIDE + k16*16)*2);
            #pragma unroll
            for (int mi=0; mi<4; mi++)
                #pragma unroll
                for (int nt=0; nt<8; nt++)
                    mma16816(acc[mi][nt], af[mi], &bf[nt>>1][(nt&1)*2]);
        }
    }

    const int g = lane >> 2, q = lane & 3;
    float2 bias2[8];
    #pragma unroll
    for (int nt=0; nt<8; nt++){
        int col = n0 + wn*64 + nt*8 + q*2;
        bias2[nt] = *(const float2*)(ob + col);
    }
    #pragma unroll
    for (int mi=0; mi<4; mi++){
        int r0 = m0 + wm*64 + mi*16 + g;
        int r1 = r0 + 8;
        #pragma unroll
        for (int nt=0; nt<8; nt++){
            int col = n0 + wn*64 + nt*8 + q*2;
            if (r0 < MROWS){
                float2 v = make_float2(acc[mi][nt][0] + bias2[nt].x,
                                       acc[mi][nt][1] + bias2[nt].y);
                *(float2*)(C + (size_t)r0*VV + col) = v;
            }
            if (r1 < MROWS){
                float2 v = make_float2(acc[mi][nt][2] + bias2[nt].x,
                                       acc[mi][nt][3] + bias2[nt].y);
                *(float2*)(C + (size_t)r1*VV + col) = v;
            }
        }
    }
}

// ---------------- launch ----------------
extern "C" void kernel_launch(void* const* d_in, const int* in_sizes, int n_in,
                              void* d_out, int out_size)
{
    const float* latent = (const float*)d_in[0];
    const int*   tok    = (const int*)d_in[1];
    const float* emb    = (const float*)d_in[2];
    const float* dW     = (const float*)d_in[3];
    const float* db     = (const float*)d_in[4];
    const float* gk     = (const float*)d_in[5];
    const float* grk    = (const float*)d_in[6];
    const float* gb     = (const float*)d_in[7];
    const float* oW     = (const float*)d_in[8];
    const float* ob     = (const float*)d_in[9];
    float* out = (float*)d_out;

    (void)in_sizes; (void)n_in; (void)out_size;

    cudaFuncSetAttribute(gru_kernel, cudaFuncAttributeMaxDynamicSharedMemorySize, GRU_SMEM);
    cudaFuncSetAttribute(out_hmma, cudaFuncAttributeMaxDynamicSharedMemorySize, OG_SMEM);
    cudaFuncSetAttribute(xp_hmma, cudaFuncAttributeMaxDynamicSharedMemorySize, HG_SMEM);

    void *xproj_p = nullptr;
    cudaGetSymbolAddress(&xproj_p, g_xproj);

    // fused prep: tokens/flags, fp16 conversions+transposes, h0; + barrier counter reset
    prep_all<<<PB_TOTAL, 256>>>(latent, dW, db, tok, emb, gk, grk, oW);
    bar_reset<<<1, 32>>>();

    // xproj = emb[tok] @ gru_kernel + gru_bias[0]   (HMMA)
    xp_hmma<<<dim3(MPAD/128, N3/128), 256, HG_SMEM>>>(gb, (float*)xproj_p);

    gru_kernel<<<GRU_BLOCKS, 256, GRU_SMEM>>>(gb, tok);

    // m tiles fastest (blockIdx.x) so co-resident CTAs share the same B panel in L2
    out_hmma<<<dim3(MPAD/128, VV/256), 256, OG_SMEM>>>(ob, out);
}

// round 12
// speedup vs baseline: 2.2796x; 1.0244x over previous
#include <cuda_runtime.h>
#include <cuda_fp16.h>
#include <cstdint>

// Problem constants
#define NB   16          // batch
#define TT   255         // teacher length (T-1)
#define UU   1024        // GRU units
#define VV   32000       // vocab
#define EE   256         // emb dim
#define LATD 512         // latent dim
#define MROWS (NB*TT)    // 4080
#define MPAD 4096
#define N3   (3*UU)      // 3072

#define GRU_BLOCKS 64
#define UPC 16                               // units per CTA
#define NLOC 48                              // local N (3 gates x 16 units)
#define SCSTRIDE 52
#define ASTRIDE 136                          // padded halves per (warp,batch) row
#define AWARP   (16*ASTRIDE)                 // halves per warp slice
#define GRU_SMEM (8*AWARP*2 + 8*16*SCSTRIDE*4)   // 34816 + 26624 = 61440

// ---------------- device scratch (no allocs allowed) ----------------
__device__ __align__(128) __half g_hfp[2][NB*UU];     // fp16 hidden state, ping-pong
__device__ float g_xproj[(size_t)MROWS*N3];           // x @ gru_kernel + b0
__device__ __align__(128) __half g_Ah[(size_t)MPAD*UU];   // fp16 GRU outputs (rows>=4080 stay 0)
__device__ __align__(128) __half g_Wh[(size_t)VV*UU];     // fp16 out_W^T  [V][U]
__device__ __align__(128) __half g_embh[(size_t)VV*EE];   // fp16 emb
__device__ __align__(128) __half g_gkT[(size_t)N3*EE];    // fp16 gru_kernel^T [3072][256]
__device__ __align__(128) __half g_rkTh[(size_t)N3*UU];   // fp16 gru_rkernel^T [3072][1024]
__device__ int   g_arow[MROWS];
__device__ unsigned char g_flag[MROWS];
__device__ __align__(256) unsigned g_cnt8[8][64];     // two-level barrier counters (256B apart)

// ---------------- PTX helpers ----------------
__device__ __forceinline__ uint32_t smem_to_u32(const void* p){
    uint32_t a;
    asm("{ .reg .u64 t; cvta.to.shared.u64 t, %1; cvt.u32.u64 %0, t; }" : "=r"(a) : "l"(p));
    return a;
}
__device__ __forceinline__ void cp16(uint32_t s, const void* g){
    asm volatile("cp.async.cg.shared.global [%0], [%1], 16;" :: "r"(s), "l"(g));
}
__device__ __forceinline__ void cp_commit(){ asm volatile("cp.async.commit_group;" ::: "memory"); }
template<int N> __device__ __forceinline__ void cp_wait(){
    asm volatile("cp.async.wait_group %0;" :: "n"(N) : "memory");
}
__device__ __forceinline__ void ldsm4(uint32_t* r, uint32_t addr){
    asm volatile("ldmatrix.sync.aligned.m8n8.x4.shared.b16 {%0,%1,%2,%3}, [%4];"
        : "=r"(r[0]),"=r"(r[1]),"=r"(r[2]),"=r"(r[3]) : "r"(addr));
}
__device__ __forceinline__ void mma16816(float* c, const uint32_t* a, const uint32_t* b){
    asm volatile("mma.sync.aligned.m16n8k16.row.col.f32.f16.f16.f32 "
        "{%0,%1,%2,%3}, {%4,%5,%6,%7}, {%8,%9}, {%0,%1,%2,%3};"
        : "+f"(c[0]), "+f"(c[1]), "+f"(c[2]), "+f"(c[3])
        : "r"(a[0]), "r"(a[1]), "r"(a[2]), "r"(a[3]), "r"(b[0]), "r"(b[1]));
}

// two-level grid barrier: 8 counters (8 CTAs each), threads 0-7 spin one counter each.
__device__ __forceinline__ void gru_barrier2(int bl, int t){
    __syncthreads();
    if (threadIdx.x == 0){
        asm volatile("red.release.gpu.add.u32 [%0], 1;" :: "l"(&g_cnt8[bl & 7][0]) : "memory");
    }
    if (threadIdx.x < 8){
        unsigned target = (unsigned)(GRU_BLOCKS/8)*(unsigned)(t+1);
        const unsigned* p = &g_cnt8[threadIdx.x][0];
        unsigned v;
        do {
            asm volatile("ld.acquire.gpu.u32 %0, [%1];" : "=r"(v) : "l"(p) : "memory");
        } while (v < target);
    }
    __syncthreads();
}

__global__ void bar_reset(){
    if (threadIdx.x < 8) g_cnt8[threadIdx.x][0] = 0;
}

// ---------------- fused prep kernel ----------------
#define PB_PREP 1
#define PB_EMB  8000
#define PB_GKT  768
#define PB_H0   64
#define PB_RKT  3072
#define PB_W    32000
#define PB_TOTAL (PB_PREP+PB_EMB+PB_GKT+PB_H0+PB_RKT+PB_W)

__global__ void prep_all(const float* __restrict__ lat, const float* __restrict__ dW,
                         const float* __restrict__ db,  const int* __restrict__ tok,
                         const float* __restrict__ emb, const float* __restrict__ gk,
                         const float* __restrict__ grk, const float* __restrict__ oW){
    __shared__ float tile[32][33];
    int bid = blockIdx.x;
    const int tid = threadIdx.x;
    const int tx = tid & 31, ty = tid >> 5;

    if (bid < PB_PREP){
        if (tid < NB){
            unsigned char f = 0;
            for (int t=0;t<TT;t++){
                f |= (tok[tid*256 + t] != 0) ? 1 : 0;
                g_flag[tid*TT + t] = f;
            }
        }
        for (int m=tid; m<MROWS; m+=256){
            int v = tok[(m/TT)*256 + (m%TT)];
            if (v < 0) v = 0;
            if (v >= VV) v = VV-1;
            g_arow[m] = v;
        }
        return;
    }
    bid -= PB_PREP;

    if (bid < PB_EMB){
        int i = bid*256 + tid;
        float4 v = ((const float4*)emb)[i];
        __half2* dst = (__half2*)g_embh;
        dst[i*2+0] = __floats2half2_rn(v.x, v.y);
        dst[i*2+1] = __floats2half2_rn(v.z, v.w);
        return;
    }
    bid -= PB_EMB;

    if (bid < PB_GKT){
        int n0 = (bid % 96)*32, k0 = (bid / 96)*32;
        #pragma unroll
        for (int i=ty; i<32; i+=8)
            tile[i][tx] = gk[(size_t)(k0+i)*N3 + n0+tx];
        __syncthreads();
        #pragma unroll
        for (int i=ty; i<32; i+=8)
            g_gkT[(size_t)(n0+i)*EE + k0+tx] = __float2half(tile[tx][i]);
        return;
    }
    bid -= PB_GKT;

    if (bid < PB_H0){
        int o = bid*256 + tid;
        int b = o >> 10, u = o & (UU-1);
        float acc = db[u];
        const float* lrow = lat + b*LATD;
        #pragma unroll 8
        for (int k=0;k<LATD;k++) acc = fmaf(lrow[k], dW[(size_t)k*UU + u], acc);
        g_hfp[0][b*UU + u] = __float2half(acc);
        return;
    }
    bid -= PB_H0;

    if (bid < PB_RKT){
        int n0 = (bid % 96)*32, k0 = (bid / 96)*32;
        #pragma unroll
        for (int i=ty; i<32; i+=8)
            tile[i][tx] = grk[(size_t)(k0+i)*N3 + n0+tx];
        __syncthreads();
        #pragma unroll
        for (int i=ty; i<32; i+=8)
            g_rkTh[(size_t)(n0+i)*UU + k0+tx] = __float2half(tile[tx][i]);
        return;
    }
    bid -= PB_RKT;

    {   // convW: transpose out_W [U][V] -> fp16 g_Wh [V][U]
        int n0 = (bid % 1000)*32, k0 = (bid / 1000)*32;
        #pragma unroll
        for (int i=ty; i<32; i+=8)
            tile[i][tx] = oW[(size_t)(k0+i)*VV + n0+tx];
        __syncthreads();
        #pragma unroll
        for (int i=ty; i<32; i+=8)
            g_Wh[(size_t)(n0+i)*UU + k0+tx] = __float2half(tile[tx][i]);
        return;
    }
}

// ---------------- xp tile constants (128x128) ----------------
#define HG_STRIDE 72
#define HG_BUFB   (128*HG_STRIDE*2)
#define HG_SMEM   (6*HG_BUFB)

// ---------------- kernel 3: fp16 HMMA xproj GEMM (gathered A) ----------------
__global__ __launch_bounds__(256,2) void xp_hmma(const float* __restrict__ bias0,
                                                 float* __restrict__ C){
    extern __shared__ __align__(128) char sm[];
    const uint32_t sb = smem_to_u32(sm);
    const int tid = threadIdx.x, lane = tid & 31, wid = tid >> 5;
    const int m0 = blockIdx.x * 128;
    const int n0 = blockIdx.y * 128;
    const int wm = wid >> 2, wn = wid & 3;

    const __half* aptr[4];
    int asegs[4];
    #pragma unroll
    for (int i=0;i<4;i++){
        int idx = tid + i*256;
        int row = idx >> 3; asegs[i] = idx & 7;
        int grow = m0 + row;
        int tokv = (grow < MROWS) ? g_arow[grow] : 0;
        aptr[i] = g_embh + (size_t)tokv*EE;
    }
    auto loadA = [&](int kc, int st){
        uint32_t base = sb + st*HG_BUFB;
        #pragma unroll
        for (int i=0;i<4;i++){
            int idx = tid + i*256;
            int row = idx >> 3;
            cp16(base + (uint32_t)(row*HG_STRIDE + asegs[i]*8)*2,
                 aptr[i] + kc*64 + asegs[i]*8);
        }
    };
    auto loadB = [&](int kc, int st){
        const __half* gB = g_gkT + (size_t)n0*EE + kc*64;
        uint32_t base = sb + (3+st)*HG_BUFB;
        #pragma unroll
        for (int i=0;i<4;i++){
            int idx = tid + i*256;
            int row = idx >> 3, seg = idx & 7;
            cp16(base + (uint32_t)(row*HG_STRIDE + seg*8)*2,
                 gB + (size_t)row*EE + seg*8);
        }
    };

    float acc[4][4][4];
    #pragma unroll
    for (int i=0;i<4;i++)
        #pragma unroll
        for (int j=0;j<4;j++)
            #pragma unroll
            for (int p=0;p<4;p++) acc[i][j][p] = 0.f;

    const int lane15 = lane & 15, laneHi = lane >> 4;
    const uint32_t aOff = (uint32_t)((wm*64 + lane15)*HG_STRIDE + laneHi*8)*2;
    const int nr  = (lane & 7) + ((lane >> 4) << 3);
    const int kc8 = ((lane >> 3) & 1) * 8;
    const uint32_t bOff = (uint32_t)((wn*32 + nr)*HG_STRIDE + kc8)*2;

    loadA(0,0); loadB(0,0); cp_commit();
    loadA(1,1); loadB(1,1); cp_commit();

    for (int kc=0; kc<4; kc++){
        int st = kc % 3;
        if (kc < 3) cp_wait<1>(); else cp_wait<0>();
        __syncthreads();
        if (kc + 2 < 4){
            loadA(kc+2, (kc+2)%3);
            loadB(kc+2, (kc+2)%3);
            cp_commit();
        }
        const uint32_t aBase = sb + st*HG_BUFB + aOff;
        const uint32_t bBase = sb + (3+st)*HG_BUFB + bOff;
        #pragma unroll
        for (int k16=0; k16<4; k16++){
            uint32_t af[4][4], bf[2][4];
            #pragma unroll
            for (int mi=0; mi<4; mi++)
                ldsm4(af[mi], aBase + (uint32_t)(mi*16*HG_STRIDE + k16*16)*2);
            #pragma unroll
            for (int ni=0; ni<2; ni++)
                ldsm4(bf[ni], bBase + (uint32_t)(ni*16*HG_STRIDE + k16*16)*2);
            #pragma unroll
            for (int mi=0; mi<4; mi++)
                #pragma unroll
                for (int nt=0; nt<4; nt++)
                    mma16816(acc[mi][nt], af[mi], &bf[nt>>1][(nt&1)*2]);
        }
        if (kc < 3) __syncthreads();
    }

    const int g = lane >> 2, q = lane & 3;
    float2 bias2[4];
    #pragma unroll
    for (int nt=0; nt<4; nt++){
        int col = n0 + wn*32 + nt*8 + q*2;
        bias2[nt] = *(const float2*)(bias0 + col);
    }
    #pragma unroll
    for (int mi=0; mi<4; mi++){
        int r0 = m0 + wm*64 + mi*16 + g;
        int r1 = r0 + 8;
        #pragma unroll
        for (int nt=0; nt<4; nt++){
            int col = n0 + wn*32 + nt*8 + q*2;
            if (r0 < MROWS){
                float2 v = make_float2(acc[mi][nt][0] + bias2[nt].x,
                                       acc[mi][nt][1] + bias2[nt].y);
                *(float2*)(C + (size_t)r0*N3 + col) = v;
            }
            if (r1 < MROWS){
                float2 v = make_float2(acc[mi][nt][2] + bias2[nt].x,
                                       acc[mi][nt][3] + bias2[nt].y);
                *(float2*)(C + (size_t)r1*N3 + col) = v;
            }
        }
    }
}

// ---------------- kernel 4: persistent GRU, tensor-core recurrence (64 CTAs x 16 units) ----------------
__global__ __launch_bounds__(256,1) void gru_kernel(
    const float* __restrict__ gbias,
    const int* __restrict__ tok)
{
    extern __shared__ char smg[];
    __half* Ah = (__half*)smg;                        // [8 warps][16 batches][ASTRIDE]
    float*  sc = (float*)(smg + 8*AWARP*2);           // [8][16][SCSTRIDE]
    const uint32_t sb0 = smem_to_u32(smg);
    const int tid = threadIdx.x, lane = tid & 31, wrp = tid >> 5, bl = blockIdx.x;
    const int g = lane >> 2, tig = lane & 3;

    // one-time B fragments from g_rkTh (fp16 rk^T [3072][1024]); 6 n-tiles of 8 cols
    uint32_t bw[8][6][2];
    #pragma unroll
    for (int j=0;j<8;j++)
        #pragma unroll
        for (int nt=0;nt<6;nt++){
            int n_local = nt*8 + g;
            int gate = n_local >> 4, u = n_local & 15;
            const __half* base = g_rkTh + (size_t)(gate*UU + bl*UPC + u)*UU + wrp*128 + j*16 + 2*tig;
            bw[j][nt][0] = *(const uint32_t*)base;
            bw[j][nt][1] = *(const uint32_t*)(base + 8);
        }

    const int eb = tid >> 4, eu = tid & 15;
    const int ecol = bl*UPC + eu;
    const float bz = gbias[N3 + ecol];
    const float br = gbias[N3 + UU + ecol];
    const float bh = gbias[N3 + 2*UU + ecol];
    const uint32_t holdOff = (uint32_t)(((ecol >> 7)*16 + eb)*ASTRIDE + (ecol & 127));

    const uint32_t wbase = sb0 + wrp*AWARP*2;

    for (int t=0; t<TT; t++){
        const int rbuf = t & 1, wbuf = rbuf ^ 1;

        // prefetch epilogue inputs (hide L2 latency)
        int r = eb*TT + t;
        const float* xp = g_xproj + (size_t)r*N3;
        float xz = xp[ecol], xr = xp[UU+ecol], xh = xp[2*UU+ecol];
        bool msk = (tok[eb*256 + t] != 0);
        bool fl  = (g_flag[r] != 0);

        // per-warp slice broadcast: warp wrp loads k in [wrp*128, wrp*128+128) for all 16 batches
        {
            const char* srcH = (const char*)&g_hfp[rbuf][0] + wrp*256;
            #pragma unroll
            for (int i=0;i<8;i++){
                int idx = lane + 32*i;             // 0..255: b = idx>>4, 16B chunk c = idx&15
                int b = idx >> 4, c = idx & 15;
                cp16(wbase + (uint32_t)(b*ASTRIDE*2 + c*16), srcH + b*2048 + c*16);
            }
            cp_commit(); cp_wait<0>();
            __syncwarp();
        }

        // tensor-core partial rp for this warp's k-slice
        float acc[6][4];
        #pragma unroll
        for (int nt=0;nt<6;nt++)
            #pragma unroll
            for (int p=0;p<4;p++) acc[nt][p] = 0.f;

        const char* Ab = (const char*)smg + wrp*AWARP*2;
        #pragma unroll
        for (int j=0;j<8;j++){
            int koff = j*16 + 2*tig;
            uint32_t a[4];
            a[0] = *(const uint32_t*)(Ab + (size_t)(g*ASTRIDE     + koff    )*2);
            a[1] = *(const uint32_t*)(Ab + (size_t)((g+8)*ASTRIDE + koff    )*2);
            a[2] = *(const uint32_t*)(Ab + (size_t)(g*ASTRIDE     + koff + 8)*2);
            a[3] = *(const uint32_t*)(Ab + (size_t)((g+8)*ASTRIDE + koff + 8)*2);
            #pragma unroll
            for (int nt=0;nt<6;nt++)
                mma16816(acc[nt], a, bw[j][nt]);
        }

        // store partials: sc[w][batch][col]
        #pragma unroll
        for (int nt=0;nt<6;nt++){
            int c = nt*8 + 2*tig;
            sc[(wrp*16 + g  )*SCSTRIDE + c    ] = acc[nt][0];
            sc[(wrp*16 + g  )*SCSTRIDE + c + 1] = acc[nt][1];
            sc[(wrp*16 + g+8)*SCSTRIDE + c    ] = acc[nt][2];
            sc[(wrp*16 + g+8)*SCSTRIDE + c + 1] = acc[nt][3];
        }
        __syncthreads();

        // gate math + state update (all 256 threads: 16 batches x 16 units)
        {
            float rz = bz, rr = br, rh = bh;
            #pragma unroll
            for (int w=0;w<8;w++){
                const float* p = &sc[(w*16 + eb)*SCSTRIDE];
                rz += p[eu]; rr += p[16+eu]; rh += p[32+eu];
            }
            float hold = __half2float(Ah[holdOff]);
            float z  = 1.f/(1.f + __expf(-(xz+rz)));
            float rg = 1.f/(1.f + __expf(-(xr+rr)));
            float e2 = __expf(2.f*(xh + rg*rh));
            float hh = __fdividef(e2 - 1.f, e2 + 1.f);
            float hn = z*hold + (1.f - z)*hh;
            float hnew = msk ? hn : hold;
            __half nh = __float2half(hnew);
            g_hfp[wbuf][eb*UU + ecol] = nh;
            g_Ah[(size_t)(eb*TT + t)*UU + ecol] = fl ? nh : __half(0.f);
        }
        gru_barrier2(bl, t);
    }
}

// ---------------- kernel 5: fp16 HMMA output GEMM (CTA 128x256, warp 64x64) ----------------
#define OG_ABUF (128*HG_STRIDE*2)         // 18432
#define OG_BBUF (256*HG_STRIDE*2)         // 36864
#define OG_SMEM (3*OG_ABUF + 3*OG_BBUF)   // 165888

__global__ __launch_bounds__(256,1) void out_hmma(const float* __restrict__ ob,
                                                  float* __restrict__ C){
    extern __shared__ __align__(128) char sm[];
    const uint32_t sb = smem_to_u32(sm);
    const int tid = threadIdx.x, lane = tid & 31, wid = tid >> 5;
    const int m0 = blockIdx.x * 128;
    const int n0 = blockIdx.y * 256;
    const int wm = wid >> 2, wn = wid & 3;     // 2m x 4n warps, 64x64 tiles

    auto loadA = [&](int kc, int st){
        const __half* gA = g_Ah + (size_t)m0*UU + kc*64;
        uint32_t base = sb + st*OG_ABUF;
        #pragma unroll
        for (int i=0;i<4;i++){
            int idx = tid + i*256;             // 0..1023: 128 rows x 8 segs
            int row = idx >> 3, seg = idx & 7;
            cp16(base + (uint32_t)(row*HG_STRIDE + seg*8)*2,
                 gA + (size_t)row*UU + seg*8);
        }
    };
    auto loadB = [&](int kc, int st){
        const __half* gB = g_Wh + (size_t)n0*UU + kc*64;
        uint32_t base = sb + 3*OG_ABUF + st*OG_BBUF;
        #pragma unroll
        for (int i=0;i<8;i++){
            int idx = tid + i*256;             // 0..2047: 256 rows x 8 segs
            int row = idx >> 3, seg = idx & 7;
            cp16(base + (uint32_t)(row*HG_STRIDE + seg*8)*2,
                 gB + (size_t)row*UU + seg*8);
        }
    };

    float acc[4][8][4];
    #pragma unroll
    for (int i=0;i<4;i++)
        #pragma unroll
        for (int j=0;j<8;j++)
            #pragma unroll
            for (int p=0;p<4;p++) acc[i][j][p] = 0.f;

    const int lane15 = lane & 15, laneHi = lane >> 4;
    const uint32_t aOff = (uint32_t)((wm*64 + lane15)*HG_STRIDE + laneHi*8)*2;
    const int nr  = (lane & 7) + ((lane >> 4) << 3);
    const int kc8 = ((lane >> 3) & 1) * 8;
    const uint32_t bOff = (uint32_t)((wn*64 + nr)*HG_STRIDE + kc8)*2;

    loadA(0,0); loadB(0,0); cp_commit();
    loadA(1,1); loadB(1,1); cp_commit();

    for (int kc=0; kc<16; kc++){
        int st = kc % 3;
        if (kc < 15) cp_wait<1>(); else cp_wait<0>();
        __syncthreads();
        if (kc + 2 < 16){
            loadA(kc+2, (kc+2)%3);
            loadB(kc+2, (kc+2)%3);
            cp_commit();
        }

        const uint32_t aBase = sb + st*OG_ABUF + aOff;
        const uint32_t bBase = sb + 3*OG_ABUF + st*OG_BBUF + bOff;
        #pragma unroll
        for (int k16=0; k16<4; k16++){
            uint32_t af[4][4], bf[4][4];
            #pragma unroll
            for (int mi=0; mi<4; mi++)
                ldsm4(af[mi], aBase + (uint32_t)(mi*16*HG_STRIDE + k16*16)*2);
            #pragma unroll
            for (int ni=0; ni<4; ni++)
                ldsm4(bf[ni], bBase + (uint32_t)(ni*16*HG_STRIDE + k16*16)*2);
            #pragma unroll
            for (int mi=0; mi<4; mi++)
                #pragma unroll
                for (int nt=0; nt<8; nt++)
                    mma16816(acc[mi][nt], af[mi], &bf[nt>>1][(nt&1)*2]);
        }
    }

    const int g = lane >> 2, q = lane & 3;
    float2 bias2[8];
    #pragma unroll
    for (int nt=0; nt<8; nt++){
        int col = n0 + wn*64 + nt*8 + q*2;
        bias2[nt] = *(const float2*)(ob + col);
    }
    #pragma unroll
    for (int mi=0; mi<4; mi++){
        int r0 = m0 + wm*64 + mi*16 + g;
        int r1 = r0 + 8;
        #pragma unroll
        for (int nt=0; nt<8; nt++){
            int col = n0 + wn*64 + nt*8 + q*2;
            if (r0 < MROWS){
                float2 v = make_float2(acc[mi][nt][0] + bias2[nt].x,
                                       acc[mi][nt][1] + bias2[nt].y);
                *(float2*)(C + (size_t)r0*VV + col) = v;
            }
            if (r1 < MROWS){
                float2 v = make_float2(acc[mi][nt][2] + bias2[nt].x,
                                       acc[mi][nt][3] + bias2[nt].y);
                *(float2*)(C + (size_t)r1*VV + col) = v;
            }
        }
    }
}

// ---------------- launch ----------------
extern "C" void kernel_launch(void* const* d_in, const int* in_sizes, int n_in,
                              void* d_out, int out_size)
{
    const float* latent = (const float*)d_in[0];
    const int*   tok    = (const int*)d_in[1];
    const float* emb    = (const float*)d_in[2];
    const float* dW     = (const float*)d_in[3];
    const float* db     = (const float*)d_in[4];
    const float* gk     = (const float*)d_in[5];
    const float* grk    = (const float*)d_in[6];
    const float* gb     = (const float*)d_in[7];
    const float* oW     = (const float*)d_in[8];
    const float* ob     = (const float*)d_in[9];
    float* out = (float*)d_out;

    (void)in_sizes; (void)n_in; (void)out_size;

    cudaFuncSetAttribute(gru_kernel, cudaFuncAttributeMaxDynamicSharedMemorySize, GRU_SMEM);
    cudaFuncSetAttribute(out_hmma, cudaFuncAttributeMaxDynamicSharedMemorySize, OG_SMEM);
    cudaFuncSetAttribute(xp_hmma, cudaFuncAttributeMaxDynamicSharedMemorySize, HG_SMEM);

    void *xproj_p = nullptr;
    cudaGetSymbolAddress(&xproj_p, g_xproj);

    // fused prep: tokens/flags, fp16 conversions+transposes, h0; + barrier counter reset
    prep_all<<<PB_TOTAL, 256>>>(latent, dW, db, tok, emb, gk, grk, oW);
    bar_reset<<<1, 32>>>();

    // xproj = emb[tok] @ gru_kernel + gru_bias[0]   (HMMA)
    xp_hmma<<<dim3(MPAD/128, N3/128), 256, HG_SMEM>>>(gb, (float*)xproj_p);

    gru_kernel<<<GRU_BLOCKS, 256, GRU_SMEM>>>(gb, tok);

    // m tiles fastest (blockIdx.x) so co-resident CTAs share the same B panel in L2
    out_hmma<<<dim3(MPAD/128, VV/256), 256, OG_SMEM>>>(ob, out);
}

// round 13
// speedup vs baseline: 2.9466x; 1.2926x over previous
#include <cuda_runtime.h>
#include <cuda_fp16.h>
#include <cstdint>

// Problem constants
#define NB   16          // batch
#define TT   255         // teacher length (T-1)
#define UU   1024        // GRU units
#define VV   32000       // vocab
#define EE   256         // emb dim
#define LATD 512         // latent dim
#define MROWS (NB*TT)    // 4080
#define MPAD 4096
#define N3   (3*UU)      // 3072

#define GRU_BLOCKS 64
#define OUT_BLOCKS 84
#define FUSED_BLOCKS (GRU_BLOCKS+OUT_BLOCKS)
#define NTILES (32*125)                      // 4000 output tiles (m 0..31, nb 0..124)
#define UPC 16                               // units per CTA
#define SCSTRIDE 52
#define ASTRIDE 136                          // padded halves per (warp,batch) row
#define AWARP   (16*ASTRIDE)                 // halves per warp slice

// ---------------- device scratch (no allocs allowed) ----------------
__device__ __align__(128) __half g_hfp[2][NB*UU];     // fp16 hidden state, ping-pong
__device__ float g_xproj[(size_t)MROWS*N3];           // x @ gru_kernel + b0
__device__ __align__(128) __half g_Ah[(size_t)MPAD*UU];   // fp16 GRU outputs, row = t*16+b
__device__ __align__(128) __half g_Wh[(size_t)VV*UU];     // fp16 out_W^T  [V][U]
__device__ __align__(128) __half g_embh[(size_t)VV*EE];   // fp16 emb
__device__ __align__(128) __half g_gkT[(size_t)N3*EE];    // fp16 gru_kernel^T [3072][256]
__device__ __align__(128) __half g_rkTh[(size_t)N3*UU];   // fp16 gru_rkernel^T [3072][1024]
__device__ int   g_arow[MROWS];
__device__ unsigned char g_flag[MROWS];
__device__ __align__(256) unsigned g_cnt8[8][64];     // two-level barrier counters (256B apart)
__device__ unsigned g_tile;                           // output tile work queue

// ---------------- PTX helpers ----------------
__device__ __forceinline__ uint32_t smem_to_u32(const void* p){
    uint32_t a;
    asm("{ .reg .u64 t; cvta.to.shared.u64 t, %1; cvt.u32.u64 %0, t; }" : "=r"(a) : "l"(p));
    return a;
}
__device__ __forceinline__ void cp16(uint32_t s, const void* g){
    asm volatile("cp.async.cg.shared.global [%0], [%1], 16;" :: "r"(s), "l"(g));
}
__device__ __forceinline__ void cp_commit(){ asm volatile("cp.async.commit_group;" ::: "memory"); }
template<int N> __device__ __forceinline__ void cp_wait(){
    asm volatile("cp.async.wait_group %0;" :: "n"(N) : "memory");
}
__device__ __forceinline__ void ldsm4(uint32_t* r, uint32_t addr){
    asm volatile("ldmatrix.sync.aligned.m8n8.x4.shared.b16 {%0,%1,%2,%3}, [%4];"
        : "=r"(r[0]),"=r"(r[1]),"=r"(r[2]),"=r"(r[3]) : "r"(addr));
}
__device__ __forceinline__ void mma16816(float* c, const uint32_t* a, const uint32_t* b){
    asm volatile("mma.sync.aligned.m16n8k16.row.col.f32.f16.f16.f32 "
        "{%0,%1,%2,%3}, {%4,%5,%6,%7}, {%8,%9}, {%0,%1,%2,%3};"
        : "+f"(c[0]), "+f"(c[1]), "+f"(c[2]), "+f"(c[3])
        : "r"(a[0]), "r"(a[1]), "r"(a[2]), "r"(a[3]), "r"(b[0]), "r"(b[1]));
}

// two-level grid barrier: 8 counters (8 CTAs each), threads 0-7 spin one counter each.
__device__ __forceinline__ void gru_barrier2(int bl, int t){
    __syncthreads();
    if (threadIdx.x == 0){
        asm volatile("red.release.gpu.add.u32 [%0], 1;" :: "l"(&g_cnt8[bl & 7][0]) : "memory");
    }
    if (threadIdx.x < 8){
        unsigned target = (unsigned)(GRU_BLOCKS/8)*(unsigned)(t+1);
        const unsigned* p = &g_cnt8[threadIdx.x][0];
        unsigned v;
        do {
            asm volatile("ld.acquire.gpu.u32 %0, [%1];" : "=r"(v) : "l"(p) : "memory");
        } while (v < target);
    }
    __syncthreads();
}

// out-role readiness: all 8 counters >= min(64*(m+1), 8*TT)
__device__ __forceinline__ void wait_tile_ready(int m){
    if (threadIdx.x < 8){
        unsigned target = 64u*(unsigned)(m+1);
        unsigned maxt = 8u*(unsigned)TT;
        if (target > maxt) target = maxt;
        const unsigned* p = &g_cnt8[threadIdx.x][0];
        unsigned v;
        for(;;){
            asm volatile("ld.acquire.gpu.u32 %0, [%1];" : "=r"(v) : "l"(p) : "memory");
            if (v >= target) break;
            __nanosleep(256);
        }
    }
    __syncthreads();
}

__global__ void bar_reset(){
    if (threadIdx.x < 8) g_cnt8[threadIdx.x][0] = 0;
    if (threadIdx.x == 8) g_tile = 0;
}

// ---------------- fused prep kernel ----------------
#define PB_PREP 1
#define PB_EMB  8000
#define PB_GKT  768
#define PB_H0   64
#define PB_RKT  3072
#define PB_W    32000
#define PB_TOTAL (PB_PREP+PB_EMB+PB_GKT+PB_H0+PB_RKT+PB_W)

__global__ void prep_all(const float* __restrict__ lat, const float* __restrict__ dW,
                         const float* __restrict__ db,  const int* __restrict__ tok,
                         const float* __restrict__ emb, const float* __restrict__ gk,
                         const float* __restrict__ grk, const float* __restrict__ oW){
    __shared__ float tile[32][33];
    int bid = blockIdx.x;
    const int tid = threadIdx.x;
    const int tx = tid & 31, ty = tid >> 5;

    if (bid < PB_PREP){
        if (tid < NB){
            unsigned char f = 0;
            for (int t=0;t<TT;t++){
                f |= (tok[tid*256 + t] != 0) ? 1 : 0;
                g_flag[tid*TT + t] = f;
            }
        }
        for (int m=tid; m<MROWS; m+=256){
            int v = tok[(m/TT)*256 + (m%TT)];
            if (v < 0) v = 0;
            if (v >= VV) v = VV-1;
            g_arow[m] = v;
        }
        return;
    }
    bid -= PB_PREP;

    if (bid < PB_EMB){
        int i = bid*256 + tid;
        float4 v = ((const float4*)emb)[i];
        __half2* dst = (__half2*)g_embh;
        dst[i*2+0] = __floats2half2_rn(v.x, v.y);
        dst[i*2+1] = __floats2half2_rn(v.z, v.w);
        return;
    }
    bid -= PB_EMB;

    if (bid < PB_GKT){
        int n0 = (bid % 96)*32, k0 = (bid / 96)*32;
        #pragma unroll
        for (int i=ty; i<32; i+=8)
            tile[i][tx] = gk[(size_t)(k0+i)*N3 + n0+tx];
        __syncthreads();
        #pragma unroll
        for (int i=ty; i<32; i+=8)
            g_gkT[(size_t)(n0+i)*EE + k0+tx] = __float2half(tile[tx][i]);
        return;
    }
    bid -= PB_GKT;

    if (bid < PB_H0){
        int o = bid*256 + tid;
        int b = o >> 10, u = o & (UU-1);
        float acc = db[u];
        const float* lrow = lat + b*LATD;
        #pragma unroll 8
        for (int k=0;k<LATD;k++) acc = fmaf(lrow[k], dW[(size_t)k*UU + u], acc);
        g_hfp[0][b*UU + u] = __float2half(acc);
        return;
    }
    bid -= PB_H0;

    if (bid < PB_RKT){
        int n0 = (bid % 96)*32, k0 = (bid / 96)*32;
        #pragma unroll
        for (int i=ty; i<32; i+=8)
            tile[i][tx] = grk[(size_t)(k0+i)*N3 + n0+tx];
        __syncthreads();
        #pragma unroll
        for (int i=ty; i<32; i+=8)
            g_rkTh[(size_t)(n0+i)*UU + k0+tx] = __float2half(tile[tx][i]);
        return;
    }
    bid -= PB_RKT;

    {   // convW: transpose out_W [U][V] -> fp16 g_Wh [V][U]
        int n0 = (bid % 1000)*32, k0 = (bid / 1000)*32;
        #pragma unroll
        for (int i=ty; i<32; i+=8)
            tile[i][tx] = oW[(size_t)(k0+i)*VV + n0+tx];
        __syncthreads();
        #pragma unroll
        for (int i=ty; i<32; i+=8)
            g_Wh[(size_t)(n0+i)*UU + k0+tx] = __float2half(tile[tx][i]);
        return;
    }
}

// ---------------- xp tile constants (128x128) ----------------
#define HG_STRIDE 72
#define HG_BUFB   (128*HG_STRIDE*2)
#define HG_SMEM   (6*HG_BUFB)

// ---------------- kernel 3: fp16 HMMA xproj GEMM (gathered A) ----------------
__global__ __launch_bounds__(256,2) void xp_hmma(const float* __restrict__ bias0,
                                                 float* __restrict__ C){
    extern __shared__ __align__(128) char sm[];
    const uint32_t sb = smem_to_u32(sm);
    const int tid = threadIdx.x, lane = tid & 31, wid = tid >> 5;
    const int m0 = blockIdx.x * 128;
    const int n0 = blockIdx.y * 128;
    const int wm = wid >> 2, wn = wid & 3;

    const __half* aptr[4];
    int asegs[4];
    #pragma unroll
    for (int i=0;i<4;i++){
        int idx = tid + i*256;
        int row = idx >> 3; asegs[i] = idx & 7;
        int grow = m0 + row;
        int tokv = (grow < MROWS) ? g_arow[grow] : 0;
        aptr[i] = g_embh + (size_t)tokv*EE;
    }
    auto loadA = [&](int kc, int st){
        uint32_t base = sb + st*HG_BUFB;
        #pragma unroll
        for (int i=0;i<4;i++){
            int idx = tid + i*256;
            int row = idx >> 3;
            cp16(base + (uint32_t)(row*HG_STRIDE + asegs[i]*8)*2,
                 aptr[i] + kc*64 + asegs[i]*8);
        }
    };
    auto loadB = [&](int kc, int st){
        const __half* gB = g_gkT + (size_t)n0*EE + kc*64;
        uint32_t base = sb + (3+st)*HG_BUFB;
        #pragma unroll
        for (int i=0;i<4;i++){
            int idx = tid + i*256;
            int row = idx >> 3, seg = idx & 7;
            cp16(base + (uint32_t)(row*HG_STRIDE + seg*8)*2,
                 gB + (size_t)row*EE + seg*8);
        }
    };

    float acc[4][4][4];
    #pragma unroll
    for (int i=0;i<4;i++)
        #pragma unroll
        for (int j=0;j<4;j++)
            #pragma unroll
            for (int p=0;p<4;p++) acc[i][j][p] = 0.f;

    const int lane15 = lane & 15, laneHi = lane >> 4;
    const uint32_t aOff = (uint32_t)((wm*64 + lane15)*HG_STRIDE + laneHi*8)*2;
    const int nr  = (lane & 7) + ((lane >> 4) << 3);
    const int kc8 = ((lane >> 3) & 1) * 8;
    const uint32_t bOff = (uint32_t)((wn*32 + nr)*HG_STRIDE + kc8)*2;

    loadA(0,0); loadB(0,0); cp_commit();
    loadA(1,1); loadB(1,1); cp_commit();

    for (int kc=0; kc<4; kc++){
        int st = kc % 3;
        if (kc < 3) cp_wait<1>(); else cp_wait<0>();
        __syncthreads();
        if (kc + 2 < 4){
            loadA(kc+2, (kc+2)%3);
            loadB(kc+2, (kc+2)%3);
            cp_commit();
        }
        const uint32_t aBase = sb + st*HG_BUFB + aOff;
        const uint32_t bBase = sb + (3+st)*HG_BUFB + bOff;
        #pragma unroll
        for (int k16=0; k16<4; k16++){
            uint32_t af[4][4], bf[2][4];
            #pragma unroll
            for (int mi=0; mi<4; mi++)
                ldsm4(af[mi], aBase + (uint32_t)(mi*16*HG_STRIDE + k16*16)*2);
            #pragma unroll
            for (int ni=0; ni<2; ni++)
                ldsm4(bf[ni], bBase + (uint32_t)(ni*16*HG_STRIDE + k16*16)*2);
            #pragma unroll
            for (int mi=0; mi<4; mi++)
                #pragma unroll
                for (int nt=0; nt<4; nt++)
                    mma16816(acc[mi][nt], af[mi], &bf[nt>>1][(nt&1)*2]);
        }
        if (kc < 3) __syncthreads();
    }

    const int g = lane >> 2, q = lane & 3;
    float2 bias2[4];
    #pragma unroll
    for (int nt=0; nt<4; nt++){
        int col = n0 + wn*32 + nt*8 + q*2;
        bias2[nt] = *(const float2*)(bias0 + col);
    }
    #pragma unroll
    for (int mi=0; mi<4; mi++){
        int r0 = m0 + wm*64 + mi*16 + g;
        int r1 = r0 + 8;
        #pragma unroll
        for (int nt=0; nt<4; nt++){
            int col = n0 + wn*32 + nt*8 + q*2;
            if (r0 < MROWS){
                float2 v = make_float2(acc[mi][nt][0] + bias2[nt].x,
                                       acc[mi][nt][1] + bias2[nt].y);
                *(float2*)(C + (size_t)r0*N3 + col) = v;
            }
            if (r1 < MROWS){
                float2 v = make_float2(acc[mi][nt][2] + bias2[nt].x,
                                       acc[mi][nt][3] + bias2[nt].y);
                *(float2*)(C + (size_t)r1*N3 + col) = v;
            }
        }
    }
}

// ---------------- output GEMM tile (CTA 128x256, warp 64x64) ----------------
#define OG_ABUF (128*HG_STRIDE*2)         // 18432
#define OG_BBUF (256*HG_STRIDE*2)         // 36864
#define OG_SMEM (3*OG_ABUF + 3*OG_BBUF)   // 165888

__device__ __forceinline__ void out_tile(char* sm, uint32_t sb,
                                         int tid, int lane, int wid,
                                         int m0, int n0,
                                         const float* __restrict__ ob,
                                         float* __restrict__ C){
    const int wm = wid >> 2, wn = wid & 3;     // 2m x 4n warps, 64x64 tiles

    auto loadA = [&](int kc, int st){
        const __half* gA = g_Ah + (size_t)m0*UU + kc*64;
        uint32_t base = sb + st*OG_ABUF;
        #pragma unroll
        for (int i=0;i<4;i++){
            int idx = tid + i*256;             // 0..1023: 128 rows x 8 segs
            int row = idx >> 3, seg = idx & 7;
            cp16(base + (uint32_t)(row*HG_STRIDE + seg*8)*2,
                 gA + (size_t)row*UU + seg*8);
        }
    };
    auto loadB = [&](int kc, int st){
        const __half* gB = g_Wh + (size_t)n0*UU + kc*64;
        uint32_t base = sb + 3*OG_ABUF + st*OG_BBUF;
        #pragma unroll
        for (int i=0;i<8;i++){
            int idx = tid + i*256;             // 0..2047: 256 rows x 8 segs
            int row = idx >> 3, seg = idx & 7;
            cp16(base + (uint32_t)(row*HG_STRIDE + seg*8)*2,
                 gB + (size_t)row*UU + seg*8);
        }
    };

    float acc[4][8][4];
    #pragma unroll
    for (int i=0;i<4;i++)
        #pragma unroll
        for (int j=0;j<8;j++)
            #pragma unroll
            for (int p=0;p<4;p++) acc[i][j][p] = 0.f;

    const int lane15 = lane & 15, laneHi = lane >> 4;
    const uint32_t aOff = (uint32_t)((wm*64 + lane15)*HG_STRIDE + laneHi*8)*2;
    const int nr  = (lane & 7) + ((lane >> 4) << 3);
    const int kc8 = ((lane >> 3) & 1) * 8;
    const uint32_t bOff = (uint32_t)((wn*64 + nr)*HG_STRIDE + kc8)*2;

    loadA(0,0); loadB(0,0); cp_commit();
    loadA(1,1); loadB(1,1); cp_commit();

    for (int kc=0; kc<16; kc++){
        int st = kc % 3;
        if (kc < 15) cp_wait<1>(); else cp_wait<0>();
        __syncthreads();
        if (kc + 2 < 16){
            loadA(kc+2, (kc+2)%3);
            loadB(kc+2, (kc+2)%3);
            cp_commit();
        }

        const uint32_t aBase = sb + st*OG_ABUF + aOff;
        const uint32_t bBase = sb + 3*OG_ABUF + st*OG_BBUF + bOff;
        #pragma unroll
        for (int k16=0; k16<4; k16++){
            uint32_t af[4][4], bf[4][4];
            #pragma unroll
            for (int mi=0; mi<4; mi++)
                ldsm4(af[mi], aBase + (uint32_t)(mi*16*HG_STRIDE + k16*16)*2);
            #pragma unroll
            for (int ni=0; ni<4; ni++)
                ldsm4(bf[ni], bBase + (uint32_t)(ni*16*HG_STRIDE + k16*16)*2);
            #pragma unroll
            for (int mi=0; mi<4; mi++)
                #pragma unroll
                for (int nt=0; nt<8; nt++)
                    mma16816(acc[mi][nt], af[mi], &bf[nt>>1][(nt&1)*2]);
        }
    }

    // epilogue: bias + store. A-row r = t*16+b -> C-row = b*TT + t, valid iff t < TT
    const int g = lane >> 2, q = lane & 3;
    float2 bias2[8];
    #pragma unroll
    for (int nt=0; nt<8; nt++){
        int col = n0 + wn*64 + nt*8 + q*2;
        bias2[nt] = *(const float2*)(ob + col);
    }
    #pragma unroll
    for (int mi=0; mi<4; mi++){
        int r0 = m0 + wm*64 + mi*16 + g;
        int r1 = r0 + 8;
        int t0 = r0 >> 4, b0 = r0 & 15;
        int t1 = r1 >> 4, b1 = r1 & 15;
        #pragma unroll
        for (int nt=0; nt<8; nt++){
            int col = n0 + wn*64 + nt*8 + q*2;
            if (t0 < TT){
                float2 v = make_float2(acc[mi][nt][0] + bias2[nt].x,
                                       acc[mi][nt][1] + bias2[nt].y);
                *(float2*)(C + (size_t)(b0*TT + t0)*VV + col) = v;
            }
            if (t1 < TT){
                float2 v = make_float2(acc[mi][nt][2] + bias2[nt].x,
                                       acc[mi][nt][3] + bias2[nt].y);
                *(float2*)(C + (size_t)(b1*TT + t1)*VV + col) = v;
            }
        }
    }
}

// ---------------- fused persistent kernel: GRU (CTAs 0..63) + output GEMM (64..147, then all) ----------------
__global__ __launch_bounds__(256,1) void gru_out_fused(
    const float* __restrict__ gbias,
    const int* __restrict__ tok,
    const float* __restrict__ ob,
    float* __restrict__ C)
{
    extern __shared__ __align__(128) char smg[];
    __shared__ unsigned s_ti;
    const uint32_t sb0 = smem_to_u32(smg);
    const int tid = threadIdx.x, lane = tid & 31, wrp = tid >> 5, bl = blockIdx.x;

    if (bl < GRU_BLOCKS){
        // ---------------- GRU role ----------------
        __half* Ah = (__half*)smg;                        // [8 warps][16 batches][ASTRIDE]
        float*  sc = (float*)(smg + 8*AWARP*2);           // [8][16][SCSTRIDE]
        const int g = lane >> 2, tig = lane & 3;

        // one-time B fragments from g_rkTh (fp16 rk^T [3072][1024]); 6 n-tiles of 8 cols
        uint32_t bw[8][6][2];
        #pragma unroll
        for (int j=0;j<8;j++)
            #pragma unroll
            for (int nt=0;nt<6;nt++){
                int n_local = nt*8 + g;
                int gate = n_local >> 4, u = n_local & 15;
                const __half* base = g_rkTh + (size_t)(gate*UU + bl*UPC + u)*UU + wrp*128 + j*16 + 2*tig;
                bw[j][nt][0] = *(const uint32_t*)base;
                bw[j][nt][1] = *(const uint32_t*)(base + 8);
            }

        const int eb = tid >> 4, eu = tid & 15;
        const int ecol = bl*UPC + eu;
        const float bz = gbias[N3 + ecol];
        const float br = gbias[N3 + UU + ecol];
        const float bh = gbias[N3 + 2*UU + ecol];
        const uint32_t holdOff = (uint32_t)(((ecol >> 7)*16 + eb)*ASTRIDE + (ecol & 127));

        const uint32_t wbase = sb0 + wrp*AWARP*2;

        for (int t=0; t<TT; t++){
            const int rbuf = t & 1, wbuf = rbuf ^ 1;

            int r = eb*TT + t;
            const float* xp = g_xproj + (size_t)r*N3;
            float xz = xp[ecol], xr = xp[UU+ecol], xh = xp[2*UU+ecol];
            bool msk = (tok[eb*256 + t] != 0);
            bool fl  = (g_flag[r] != 0);

            {
                const char* srcH = (const char*)&g_hfp[rbuf][0] + wrp*256;
                #pragma unroll
                for (int i=0;i<8;i++){
                    int idx = lane + 32*i;
                    int b = idx >> 4, c = idx & 15;
                    cp16(wbase + (uint32_t)(b*ASTRIDE*2 + c*16), srcH + b*2048 + c*16);
                }
                cp_commit(); cp_wait<0>();
                __syncwarp();
            }

            float acc[6][4];
            #pragma unroll
            for (int nt=0;nt<6;nt++)
                #pragma unroll
                for (int p=0;p<4;p++) acc[nt][p] = 0.f;

            const char* Ab = (const char*)smg + wrp*AWARP*2;
            #pragma unroll
            for (int j=0;j<8;j++){
                int koff = j*16 + 2*tig;
                uint32_t a[4];
                a[0] = *(const uint32_t*)(Ab + (size_t)(g*ASTRIDE     + koff    )*2);
                a[1] = *(const uint32_t*)(Ab + (size_t)((g+8)*ASTRIDE + koff    )*2);
                a[2] = *(const uint32_t*)(Ab + (size_t)(g*ASTRIDE     + koff + 8)*2);
                a[3] = *(const uint32_t*)(Ab + (size_t)((g+8)*ASTRIDE + koff + 8)*2);
                #pragma unroll
                for (int nt=0;nt<6;nt++)
                    mma16816(acc[nt], a, bw[j][nt]);
            }

            #pragma unroll
            for (int nt=0;nt<6;nt++){
                int c = nt*8 + 2*tig;
                sc[(wrp*16 + g  )*SCSTRIDE + c    ] = acc[nt][0];
                sc[(wrp*16 + g  )*SCSTRIDE + c + 1] = acc[nt][1];
                sc[(wrp*16 + g+8)*SCSTRIDE + c    ] = acc[nt][2];
                sc[(wrp*16 + g+8)*SCSTRIDE + c + 1] = acc[nt][3];
            }
            __syncthreads();

            {
                float rz = bz, rr = br, rh = bh;
                #pragma unroll
                for (int w=0;w<8;w++){
                    const float* p = &sc[(w*16 + eb)*SCSTRIDE];
                    rz += p[eu]; rr += p[16+eu]; rh += p[32+eu];
                }
                float hold = __half2float(Ah[holdOff]);
                float z  = 1.f/(1.f + __expf(-(xz+rz)));
                float rg = 1.f/(1.f + __expf(-(xr+rr)));
                float e2 = __expf(2.f*(xh + rg*rh));
                float hh = __fdividef(e2 - 1.f, e2 + 1.f);
                float hn = z*hold + (1.f - z)*hh;
                float hnew = msk ? hn : hold;
                __half nh = __float2half(hnew);
                g_hfp[wbuf][eb*UU + ecol] = nh;
                // g_Ah row = t*16 + b (contiguous per step -> tile readiness in 8-step blocks)
                g_Ah[(size_t)(t*16 + eb)*UU + ecol] = fl ? nh : __half(0.f);
            }
            gru_barrier2(bl, t);
        }
        // fall through: join the output tile queue
    }

    // ---------------- output GEMM role (persistent tile queue) ----------------
    for(;;){
        if (tid == 0) s_ti = atomicAdd(&g_tile, 1u);
        __syncthreads();
        unsigned ti = s_ti;
        if (ti >= NTILES) break;
        int m = (int)(ti / 125), nb = (int)(ti % 125);
        wait_tile_ready(m);
        out_tile(smg, sb0, tid, lane, tid >> 5, m*128, nb*256, ob, C);
        __syncthreads();
    }
}

// ---------------- launch ----------------
extern "C" void kernel_launch(void* const* d_in, const int* in_sizes, int n_in,
                              void* d_out, int out_size)
{
    const float* latent = (const float*)d_in[0];
    const int*   tok    = (const int*)d_in[1];
    const float* emb    = (const float*)d_in[2];
    const float* dW     = (const float*)d_in[3];
    const float* db     = (const float*)d_in[4];
    const float* gk     = (const float*)d_in[5];
    const float* grk    = (const float*)d_in[6];
    const float* gb     = (const float*)d_in[7];
    const float* oW     = (const float*)d_in[8];
    const float* ob     = (const float*)d_in[9];
    float* out = (float*)d_out;

    (void)in_sizes; (void)n_in; (void)out_size;

    cudaFuncSetAttribute(gru_out_fused, cudaFuncAttributeMaxDynamicSharedMemorySize, OG_SMEM);
    cudaFuncSetAttribute(xp_hmma, cudaFuncAttributeMaxDynamicSharedMemorySize, HG_SMEM);

    void *xproj_p = nullptr;
    cudaGetSymbolAddress(&xproj_p, g_xproj);

    // fused prep: tokens/flags, fp16 conversions+transposes, h0; + barrier/queue reset
    prep_all<<<PB_TOTAL, 256>>>(latent, dW, db, tok, emb, gk, grk, oW);
    bar_reset<<<1, 32>>>();

    // xproj = emb[tok] @ gru_kernel + gru_bias[0]   (HMMA)
    xp_hmma<<<dim3(MPAD/128, N3/128), 256, HG_SMEM>>>(gb, (float*)xproj_p);

    // fused persistent GRU + output GEMM with overlap
    gru_out_fused<<<FUSED_BLOCKS, 256, OG_SMEM>>>(gb, tok, ob, out);
}